// round 10
// baseline (speedup 1.0000x reference)
#include <cuda_runtime.h>
#include <cuda_bf16.h>
#include <math.h>
#include <stdint.h>
#include <stddef.h>

// ---------------------------------------------------------------------------
// MultiHeadPooledAttention — bf16 HMMA GEMMs, operands pre-split into planar
// bf16 hi/lo buffers; cp.async double-buffered mainloop (no in-loop convert).
// 3-pass hi/lo split == single GEMM over virtual 3K with plane offsets.
// ---------------------------------------------------------------------------

namespace {
constexpr int B_  = 2;
constexpr int L_  = 6273;   // 1 + 8*28*28
constexpr int NH_ = 8;
constexpr int LP_ = 1569;   // 1 + 8*14*14
constexpr int LPP_ = 1600;  // LP padded to 32
constexpr int NB_ = 1568;
constexpr int LGLD_ = 1600;
constexpr float SCALE_ = 0.04419417382415922f;  // 512^-0.5

// fp32 scratch
constexpr size_t SZ_PQ  = (size_t)16 * LP_ * 512;
constexpr size_t SZ_PK  = (size_t)16 * LP_ * 512;
constexpr size_t SZ_PX  = (size_t)B_ * LP_ * 512;
constexpr size_t SZ_EMB = (size_t)NB_ * 512;
constexpr size_t SZ_BP  = (size_t)3 * 4096;
constexpr size_t SZ_LG  = (size_t)16 * LP_ * LGLD_;

constexpr size_t OF_PQ  = 0;
constexpr size_t OF_PK  = OF_PQ + SZ_PQ;
constexpr size_t OF_PX  = OF_PK + SZ_PK;
constexpr size_t OF_EMB = OF_PX + SZ_PX;
constexpr size_t OF_BP  = OF_EMB + SZ_EMB;
constexpr size_t OF_LG  = OF_BP + SZ_BP;
constexpr size_t SZ_F32 = OF_LG + SZ_LG;

// bf16 hi/lo buffers (planar: hi at [0,Kh), lo at [Kh,2Kh), row stride 2Kh)
constexpr size_t SZB_WPT2  = (size_t)12 * 512 * 1024;
constexpr size_t SZB_WT2   = (size_t)24 * 512 * 1024;
constexpr size_t SZB_WXE2  = (size_t)512 * 4096;
constexpr size_t SZB_WD2   = (size_t)512 * 8192;
constexpr size_t SZB_WEFF2 = (size_t)3 * 4096 * 4096;
constexpr size_t SZB_XG2   = (size_t)3136 * 4096;
constexpr size_t SZB_PQ2   = (size_t)16 * LP_ * 1024;
constexpr size_t SZB_K22   = (size_t)16 * LP_ * 1024;
constexpr size_t SZB_PVT2  = (size_t)16 * 512 * 3200;
constexpr size_t SZB_AT2   = (size_t)16 * LP_ * 3200;
constexpr size_t SZB_ST2   = (size_t)B_ * LP_ * 8192;

constexpr size_t OB_WPT2  = 0;
constexpr size_t OB_WT2   = OB_WPT2 + SZB_WPT2;
constexpr size_t OB_WXE2  = OB_WT2 + SZB_WT2;
constexpr size_t OB_WD2   = OB_WXE2 + SZB_WXE2;
constexpr size_t OB_WEFF2 = OB_WD2 + SZB_WD2;
constexpr size_t OB_XG2   = OB_WEFF2 + SZB_WEFF2;
constexpr size_t OB_PQ2   = OB_XG2 + SZB_XG2;
constexpr size_t OB_K22   = OB_PQ2 + SZB_PQ2;
constexpr size_t OB_PVT2  = OB_K22 + SZB_K22;
constexpr size_t OB_AT2   = OB_PVT2 + SZB_PVT2;
constexpr size_t OB_ST2   = OB_AT2 + SZB_AT2;
constexpr size_t SZ_BF    = OB_ST2 + SZB_ST2;
}  // namespace

__device__ float g_scratch[SZ_F32];
__device__ __align__(16) __nv_bfloat16 g_bf[SZ_BF];

// ------------------------------- PTX helpers -------------------------------

__device__ __forceinline__ uint32_t smem_u32(const void* p) {
  uint32_t a;
  asm("{ .reg .u64 t; cvta.to.shared.u64 t, %1; cvt.u32.u64 %0, t; }"
      : "=r"(a) : "l"(p));
  return a;
}

__device__ __forceinline__ void ldm4(uint32_t* d, uint32_t addr) {
  asm volatile("ldmatrix.sync.aligned.m8n8.x4.shared.b16 {%0,%1,%2,%3}, [%4];"
               : "=r"(d[0]), "=r"(d[1]), "=r"(d[2]), "=r"(d[3]) : "r"(addr));
}

__device__ __forceinline__ void mma16816(float* c, const uint32_t* a,
                                         const uint32_t* b) {
  asm volatile(
      "mma.sync.aligned.m16n8k16.row.col.f32.bf16.bf16.f32 "
      "{%0,%1,%2,%3}, {%4,%5,%6,%7}, {%8,%9}, {%0,%1,%2,%3};"
      : "+f"(c[0]), "+f"(c[1]), "+f"(c[2]), "+f"(c[3])
      : "r"(a[0]), "r"(a[1]), "r"(a[2]), "r"(a[3]), "r"(b[0]), "r"(b[1]));
}

__device__ __forceinline__ void cpa16(uint32_t dst, const void* src, bool ok) {
  int sz = ok ? 16 : 0;
  asm volatile("cp.async.cg.shared.global [%0], [%1], 16, %2;"
               :: "r"(dst), "l"(src), "r"(sz) : "memory");
}
__device__ __forceinline__ void cpa_commit() {
  asm volatile("cp.async.commit_group;" ::: "memory");
}
template <int N>
__device__ __forceinline__ void cpa_wait() {
  asm volatile("cp.async.wait_group %0;" :: "n"(N) : "memory");
}

// write hi/lo split at planar offset
__device__ __forceinline__ void st2(__nv_bfloat16* p, size_t i, size_t kh,
                                    float v) {
  __nv_bfloat16 h = __float2bfloat16(v);
  p[i] = h;
  p[i + kh] = __float2bfloat16(v - __bfloat162float(h));
}

// --------------------------- cp.async GEMM kernel ----------------------------
// C[M,N] = A[M,K']·B[N,K']^T over virtual K' (pass planes); operands bf16.
// Tile 128x128 x chunk 32; 256 threads; 2-stage cp.async pipeline.

constexpr int ROWB = 80;
constexpr int TILEB = 128 * ROWB;  // 10240

__device__ __forceinline__ void issue_tile(const __nv_bfloat16* S, int stride,
                                           int rmax, int r0, int kofs,
                                           uint32_t dstB, int tid) {
#pragma unroll
  for (int i = 0; i < 2; i++) {
    int idx = tid + 256 * i;       // 512 x 16B units
    int row = idx >> 2, q = idx & 3;
    int gr = r0 + row;
    bool ok = gr < rmax;
    const __nv_bfloat16* src =
        S + (size_t)(ok ? gr : 0) * stride + kofs + q * 8;
    cpa16(dstB + (uint32_t)(row * ROWB + q * 16), src, ok);
  }
}

template <typename P, bool SPLIT>
__global__ __launch_bounds__(256) void gemm_ca(P p) {
  __shared__ __align__(16) char sm[4 * TILEB];  // 2 stages x (A,B)
  uint32_t base = smem_u32(sm);

  const int tid = threadIdx.x;
  const int wid = tid >> 5, lane = tid & 31;
  const int wm = wid >> 1, wn = wid & 1;   // warp tile 32(M) x 64(N)
  const int lj = lane >> 3, lr = lane & 7;

  const int z = blockIdx.z;
  const __nv_bfloat16* A = p.Aptr(z);
  const __nv_bfloat16* Bm = p.Bptr(z);
  const int M = p.M, N = p.N;
  const int m0 = blockIdx.y * 128, n0 = blockIdx.x * 128;
  const int nch = p.nch, Kh = p.Kh, sA = p.sA, sB = p.sB;
  const int npass = SPLIT ? 3 : 1;
  const int total = npass * nch;

  float acc[2][8][4];
#pragma unroll
  for (int a = 0; a < 2; a++)
#pragma unroll
    for (int b = 0; b < 8; b++)
#pragma unroll
      for (int c = 0; c < 4; c++) acc[a][b][c] = 0.f;

  const uint32_t aRow = (uint32_t)(wm * 32 + (lj & 1) * 8 + lr);
  const uint32_t aCol = (uint32_t)((lj >> 1) * 16);
  const uint32_t bRow = (uint32_t)(wn * 64 + (lj >> 1) * 8 + lr);
  const uint32_t bCol = (uint32_t)((lj & 1) * 16);

  // prologue
  {
    uint32_t st = base;
    issue_tile(A, sA, M, m0, 0, st, tid);
    issue_tile(Bm, sB, N, n0, 0, st + TILEB, tid);
    cpa_commit();
  }

  for (int it = 0; it < total; ++it) {
    int s = it & 1;
    if (it + 1 < total) {
      int nit = it + 1;
      int pass = nit / nch, kc = nit - pass * nch;
      int offA = (pass == 1) ? Kh : 0;
      int offB = (pass == 2) ? Kh : 0;
      int k0 = kc * 32;
      uint32_t st = base + (uint32_t)((1 - s) * 2 * TILEB);
      issue_tile(A, sA, M, m0, offA + k0, st, tid);
      issue_tile(Bm, sB, N, n0, offB + k0, st + TILEB, tid);
      cpa_commit();
      cpa_wait<1>();
    } else {
      cpa_wait<0>();
    }
    __syncthreads();

    uint32_t aT = base + (uint32_t)(s * 2 * TILEB);
    uint32_t bT = aT + TILEB;
#pragma unroll
    for (int ks = 0; ks < 2; ks++) {
      uint32_t afr[2][4];
#pragma unroll
      for (int mi = 0; mi < 2; mi++)
        ldm4(afr[mi], aT + (aRow + mi * 16) * ROWB + ks * 32 + aCol);
      uint32_t bfr[8][2];
#pragma unroll
      for (int nb = 0; nb < 4; nb++) {
        uint32_t t[4];
        ldm4(t, bT + (bRow + nb * 16) * ROWB + ks * 32 + bCol);
        bfr[2 * nb][0] = t[0];
        bfr[2 * nb][1] = t[1];
        bfr[2 * nb + 1][0] = t[2];
        bfr[2 * nb + 1][1] = t[3];
      }
#pragma unroll
      for (int mi = 0; mi < 2; mi++)
#pragma unroll
        for (int ni = 0; ni < 8; ni++)
          mma16816(acc[mi][ni], afr[mi], bfr[ni]);
    }
    __syncthreads();  // stage s safe to overwrite next iteration
  }

  const int rr = lane >> 2, cc = (lane & 3) * 2;
#pragma unroll
  for (int mi = 0; mi < 2; mi++) {
#pragma unroll
    for (int ni = 0; ni < 8; ni++) {
      int rb = m0 + wm * 32 + mi * 16 + rr;
      int cb = n0 + wn * 64 + ni * 8 + cc;
      if (rb < M) {
        if (cb < N)     p.store(z, rb, cb,     acc[mi][ni][0]);
        if (cb + 1 < N) p.store(z, rb, cb + 1, acc[mi][ni][1]);
      }
      if (rb + 8 < M) {
        if (cb < N)     p.store(z, rb + 8, cb,     acc[mi][ni][2]);
        if (cb + 1 < N) p.store(z, rb + 8, cb + 1, acc[mi][ni][3]);
      }
    }
  }
}

// ----------------------------- GEMM problem defs ----------------------------

struct WeffP {
  int M, N, nch, Kh, sA, sB;
  const __nv_bfloat16 *wpT2, *Wt2;
  __nv_bfloat16* Weff2;
  __device__ const __nv_bfloat16* Aptr(int z) const {
    int ti = z >> 5, t = z & 3;
    return wpT2 + (size_t)(ti * 4 + t) * 512 * 1024;
  }
  __device__ const __nv_bfloat16* Bptr(int z) const {
    int ti = z >> 5, n = (z & 31) >> 2;
    return Wt2 + (size_t)(ti * 8 + n) * 512 * 1024;
  }
  __device__ void store(int z, int r, int c, float v) const {
    int ti = z >> 5, n = (z & 31) >> 2, t = z & 3;
    size_t row = (size_t)ti * 4096 + n * 512 + r;
    st2(Weff2, row * 4096 + t * 512 + c, 2048, v);
  }
};

struct PoolQP {
  int M, N, nch, Kh, sA, sB;
  const __nv_bfloat16 *Xg2, *W2;
  const float* bias;
  float* PQ;
  __nv_bfloat16* PQ2;
  __device__ const __nv_bfloat16* Aptr(int) const { return Xg2; }
  __device__ const __nv_bfloat16* Bptr(int) const { return W2; }
  __device__ void store(int, int r, int c, float v) const {
    int b = r / NB_, o = r % NB_;
    v += bias[c];
    int n = c >> 9, d = c & 511;
    PQ[((size_t)(b * 8 + n) * LP_ + 1 + o) * 512 + d] = v;
    st2(PQ2, ((size_t)(b * 8 + n) * LP_ + 1 + o) * 1024 + d, 512, v);
  }
};

struct PoolKP {
  int M, N, nch, Kh, sA, sB;
  const __nv_bfloat16 *Xg2, *W2;
  const float* bias;
  float* PK;
  __device__ const __nv_bfloat16* Aptr(int) const { return Xg2; }
  __device__ const __nv_bfloat16* Bptr(int) const { return W2; }
  __device__ void store(int, int r, int c, float v) const {
    int b = r / NB_, o = r % NB_;
    v += bias[c];
    int n = c >> 9, d = c & 511;
    PK[((size_t)(b * 8 + n) * LP_ + 1 + o) * 512 + d] = v;
  }
};

struct PoolVP {
  int M, N, nch, Kh, sA, sB;
  const __nv_bfloat16 *Xg2, *W2;
  const float* bias;
  __nv_bfloat16* PVt2;
  __device__ const __nv_bfloat16* Aptr(int) const { return Xg2; }
  __device__ const __nv_bfloat16* Bptr(int) const { return W2; }
  __device__ void store(int, int r, int c, float v) const {
    int b = r / NB_, o = r % NB_;
    v += bias[c];
    int n = c >> 9, d = c & 511;
    st2(PVt2, ((size_t)(b * 8 + n) * 512 + d) * 3200 + 1 + o, 1600, v);
  }
};

struct PoolXP {
  int M, N, nch, Kh, sA, sB;
  const __nv_bfloat16 *Xg2, *W2;
  float* PX;
  __device__ const __nv_bfloat16* Aptr(int) const { return Xg2; }
  __device__ const __nv_bfloat16* Bptr(int) const { return W2; }
  __device__ void store(int, int r, int c, float v) const {
    int b = r / NB_, o = r % NB_;
    PX[((size_t)b * LP_ + 1 + o) * 512 + c] = v;
  }
};

struct LogitsP {
  int M, N, nch, Kh, sA, sB;
  const __nv_bfloat16 *PQ2, *K22;
  float* lg;
  __device__ const __nv_bfloat16* Aptr(int z) const {
    return PQ2 + (size_t)z * LP_ * 1024;
  }
  __device__ const __nv_bfloat16* Bptr(int z) const {
    return K22 + (size_t)z * LP_ * 1024;
  }
  __device__ void store(int z, int r, int c, float v) const {
    lg[(size_t)z * LP_ * LGLD_ + (size_t)r * LGLD_ + c] = v;
  }
};

struct AVP {
  int M, N, nch, Kh, sA, sB;
  const __nv_bfloat16 *at2, *PVt2;
  const float* PQ;
  __nv_bfloat16* st2b;
  __device__ const __nv_bfloat16* Aptr(int z) const {
    return at2 + (size_t)z * LP_ * 3200;
  }
  __device__ const __nv_bfloat16* Bptr(int z) const {
    return PVt2 + (size_t)z * 512 * 3200;
  }
  __device__ void store(int z, int r, int c, float v) const {
    float pq = PQ[(size_t)z * LP_ * 512 + (size_t)r * 512 + c];
    v += (r > 0 ? 2.f : 1.f) * pq;
    int b = z >> 3, n = z & 7;
    st2(st2b, ((size_t)b * LP_ + r) * 8192 + n * 512 + c, 4096, v);
  }
};

struct FinalP {
  int M, N, nch, Kh, sA, sB;
  const __nv_bfloat16 *st2b, *Wd2;
  const float* bd;
  const float* PX;
  float* y;
  __device__ const __nv_bfloat16* Aptr(int) const { return st2b; }
  __device__ const __nv_bfloat16* Bptr(int) const { return Wd2; }
  __device__ void store(int, int r, int c, float v) const {
    y[(size_t)r * 512 + c] = v + bd[c] + PX[(size_t)r * 512 + c];
  }
};

// ------------------------------ helper kernels ------------------------------

__global__ void k_wpT2(const float* wpq, const float* wpk, const float* wpv,
                       __nv_bfloat16* wpT2) {
  size_t idx = (size_t)blockIdx.x * blockDim.x + threadIdx.x;
  if (idx >= (size_t)3 * 512 * 512 * 4) return;
  int ti = (int)(idx / (512 * 512 * 4));
  int r = (int)(idx % (512 * 512 * 4));
  int c = r / 2048;
  int d = (r % 2048) >> 2;
  int t = r & 3;
  const float* wp = (ti == 0) ? wpq : ((ti == 1) ? wpk : wpv);
  st2(wpT2, ((size_t)(ti * 4 + t) * 512 + c) * 1024 + d, 512, wp[r]);
}

__global__ void k_wt2(const float* Wq, const float* Wk, const float* Wv,
                      __nv_bfloat16* Wt2) {
  size_t idx = (size_t)blockIdx.x * blockDim.x + threadIdx.x;
  if (idx >= (size_t)3 * 8 * 512 * 512) return;
  int d = (int)(idx & 511);
  int m = (int)((idx >> 9) & 511);
  int n = (int)((idx >> 18) & 7);
  int ti = (int)(idx >> 21);
  const float* W = (ti == 0) ? Wq : ((ti == 1) ? Wk : Wv);
  float v = W[(size_t)(n * 512 + d) * 512 + m];
  st2(Wt2, ((size_t)(ti * 8 + n) * 512 + m) * 1024 + d, 512, v);
}

__global__ void k_wxe2(const float* wpx, __nv_bfloat16* WXe2) {
  size_t idx = (size_t)blockIdx.x * blockDim.x + threadIdx.x;
  if (idx >= (size_t)512 * 2048) return;
  int c = (int)(idx >> 11);
  int col = (int)(idx & 2047);
  int t = col >> 9, m = col & 511;
  float v = wpx[(size_t)c * 2048 + m * 4 + t];
  st2(WXe2, (size_t)c * 4096 + col, 2048, v);
}

__global__ void k_wd2(const float* Wd, __nv_bfloat16* Wd2) {
  size_t idx = (size_t)blockIdx.x * blockDim.x + threadIdx.x;
  if (idx >= (size_t)512 * 4096) return;
  int c = (int)(idx >> 12), k = (int)(idx & 4095);
  st2(Wd2, (size_t)c * 8192 + k, 4096, Wd[idx]);
}

__global__ void k_bpool(const float* wpq, const float* wpk, const float* wpv,
                        const float* bq, const float* bk, const float* bv,
                        float* bpool) {
  int j = blockIdx.x * blockDim.x + threadIdx.x;
  if (j >= 3 * 4096) return;
  int ti = j / 4096, h = j % 4096, n = h >> 9, c = h & 511;
  const float* wp = (ti == 0) ? wpq : ((ti == 1) ? wpk : wpv);
  const float* b = (ti == 0) ? bq : ((ti == 1) ? bk : bv);
  float s = 0.f;
  for (int d = 0; d < 512; d++) {
    float bb = b[n * 512 + d];
    const float* w = wp + (size_t)c * 2048 + d * 4;
    s += (w[0] + w[1] + w[2] + w[3]) * bb;
  }
  bpool[j] = s;
}

__global__ void k_gather2(const float* x, __nv_bfloat16* Xg2) {
  size_t idx = (size_t)blockIdx.x * blockDim.x + threadIdx.x;
  if (idx >= (size_t)3136 * 2048) return;
  int r = (int)(idx >> 11);
  int col = (int)(idx & 2047);
  int t = col >> 9, m = col & 511;
  int b = r / NB_, o = r % NB_;
  int t2 = o / 196, hh = (o / 14) % 14, ww = o % 14;
  int kh = t >> 1, kw = t & 1;
  int row = 1 + (t2 * 28 + 2 * hh + kh) * 28 + 2 * ww + kw;
  float v = x[((size_t)b * L_ + row) * 512 + m];
  st2(Xg2, (size_t)r * 4096 + col, 2048, v);
}

__global__ void k_padpv(__nv_bfloat16* PVt2) {
  int idx = blockIdx.x * blockDim.x + threadIdx.x;
  if (idx >= 16 * 512 * 31) return;
  int j = idx % 31;
  int rc = idx / 31;  // z*512 + c
  int k = LP_ + j;    // 1569..1599
  size_t b = (size_t)rc * 3200;
  PVt2[b + k] = __float2bfloat16(0.f);
  PVt2[b + 1600 + k] = __float2bfloat16(0.f);
}

__global__ void k_cls(const float* x, const float* Wq, const float* bq,
                      const float* Wk, const float* bk, const float* Wv,
                      const float* bv, float* PQ, float* PK, float* PX,
                      __nv_bfloat16* PQ2, __nv_bfloat16* PVt2) {
  int idx = blockIdx.x * blockDim.x + threadIdx.x;
  if (idx < 2 * 12288) {
    int b = idx / 12288, j = idx % 12288, ti = j / 4096, jj = j & 4095;
    const float* W = (ti == 0) ? Wq : ((ti == 1) ? Wk : Wv);
    const float* bias = (ti == 0) ? bq : ((ti == 1) ? bk : bv);
    const float* xr = x + (size_t)b * L_ * 512;
    const float* wr = W + (size_t)jj * 512;
    float s = bias[jj];
    for (int m = 0; m < 512; m++) s += xr[m] * wr[m];
    int n = jj >> 9, c = jj & 511;
    int zz = b * 8 + n;
    if (ti == 0) {
      PQ[(size_t)zz * LP_ * 512 + c] = s;
      st2(PQ2, (size_t)zz * LP_ * 1024 + c, 512, s);
    } else if (ti == 1) {
      PK[(size_t)zz * LP_ * 512 + c] = s;
    } else {
      st2(PVt2, ((size_t)zz * 512 + c) * 3200 + 0, 1600, s);
    }
  } else if (idx < 2 * 12288 + 2 * 512) {
    int k = idx - 2 * 12288;
    int b = k >> 9, c = k & 511;
    PX[(size_t)b * LP_ * 512 + c] = x[(size_t)b * L_ * 512 + c];
  }
}

__device__ __forceinline__ float sincos_val(int pos, int c, int dim) {
  int half = dim / 2;
  bool is_cos = c >= half;
  int i = is_cos ? c - half : c;
  float omega = powf(10000.f, -((float)i) / (float)half);
  float ang = (float)pos * omega;
  return is_cos ? cosf(ang) : sinf(ang);
}

__global__ void k_emb(float* emb) {
  size_t idx = (size_t)blockIdx.x * blockDim.x + threadIdx.x;
  if (idx >= SZ_EMB) return;
  int k = (int)(idx >> 9);
  int c = (int)(idx & 511);
  int t2 = k / 196, h2 = (k / 14) % 14, w2 = k % 14;
  float v;
  if (c < 170) v = sincos_val(t2, c, 170);
  else if (c < 340) v = sincos_val(h2, c - 170, 170);
  else v = sincos_val(w2, c - 340, 172);
  emb[idx] = v;
}

__global__ void k_k2(const float* PK, const float* emb, __nv_bfloat16* K22) {
  size_t idx = (size_t)blockIdx.x * blockDim.x + threadIdx.x;
  if (idx >= (size_t)16 * LP_ * 512) return;
  size_t rem = idx % ((size_t)LP_ * 512);
  int k = (int)(rem >> 9);
  int c = (int)(rem & 511);
  size_t z = idx / ((size_t)LP_ * 512);
  float v = SCALE_ * PK[idx];
  if (k > 0) v += emb[(size_t)(k - 1) * 512 + c];
  st2(K22, (z * LP_ + k) * 1024 + c, 512, v);
}

__global__ void k_row0(const float* PQ, const float* PK, float* lg) {
  int z = blockIdx.y;
  int kq = blockIdx.x * 8 + (threadIdx.x >> 5);
  int lane = threadIdx.x & 31;
  if (kq >= LP_) return;
  const float* q = PQ + (size_t)z * LP_ * 512;
  const float* kr = PK + (size_t)z * LP_ * 512 + (size_t)kq * 512;
  float s = 0.f;
  for (int i = lane; i < 512; i += 32) s += q[i] * kr[i];
#pragma unroll
  for (int o = 16; o; o >>= 1) s += __shfl_xor_sync(0xFFFFFFFFu, s, o);
  if (lane == 0) lg[(size_t)z * LP_ * LGLD_ + kq] = s * SCALE_;
}

__global__ void k_softmax(float* lg, __nv_bfloat16* at2) {
  int z = blockIdx.y, q = blockIdx.x;
  float* row = lg + ((size_t)z * LP_ + q) * LGLD_;
  __nv_bfloat16* arow = at2 + ((size_t)z * LP_ + q) * 3200;
  int tid = threadIdx.x;
  __shared__ float red[256];
  float mx = -1e30f;
  for (int i = tid; i < LP_; i += 256) mx = fmaxf(mx, row[i]);
  red[tid] = mx;
  __syncthreads();
  for (int s = 128; s > 0; s >>= 1) {
    if (tid < s) red[tid] = fmaxf(red[tid], red[tid + s]);
    __syncthreads();
  }
  mx = red[0];
  __syncthreads();
  float sum = 0.f;
  for (int i = tid; i < LP_; i += 256) {
    float e = expf(row[i] - mx);
    row[i] = e;
    sum += e;
  }
  red[tid] = sum;
  __syncthreads();
  for (int s = 128; s > 0; s >>= 1) {
    if (tid < s) red[tid] += red[tid + s];
    __syncthreads();
  }
  float inv = 1.f / red[0];
  for (int i = tid; i < LPP_; i += 256) {
    float v = (i < LP_) ? row[i] * inv : 0.f;
    __nv_bfloat16 h = __float2bfloat16(v);
    arow[i] = h;
    arow[1600 + i] = __float2bfloat16(v - __bfloat162float(h));
  }
}

__global__ void k_ln(float* y, const float* gamma, const float* beta) {
  int row = blockIdx.x;
  float* yr = y + (size_t)row * 512;
  int tid = threadIdx.x;
  float v0 = yr[tid], v1 = yr[tid + 256];
  __shared__ float red[256];
  red[tid] = v0 + v1;
  __syncthreads();
  for (int s = 128; s > 0; s >>= 1) {
    if (tid < s) red[tid] += red[tid + s];
    __syncthreads();
  }
  float mu = red[0] * (1.f / 512.f);
  __syncthreads();
  float d0 = v0 - mu, d1 = v1 - mu;
  red[tid] = d0 * d0 + d1 * d1;
  __syncthreads();
  for (int s = 128; s > 0; s >>= 1) {
    if (tid < s) red[tid] += red[tid + s];
    __syncthreads();
  }
  float inv = rsqrtf(red[0] * (1.f / 512.f) + 1e-5f);
  yr[tid] = d0 * inv * gamma[tid] + beta[tid];
  yr[tid + 256] = d1 * inv * gamma[tid + 256] + beta[tid + 256];
}

// --------------------------------- launcher ---------------------------------

extern "C" void kernel_launch(void* const* d_in, const int* in_sizes, int n_in,
                              void* d_out, int out_size) {
  (void)in_sizes; (void)n_in; (void)out_size;
  const float* x   = (const float*)d_in[0];
  const float* Wq  = (const float*)d_in[1];
  const float* bq  = (const float*)d_in[2];
  const float* Wk  = (const float*)d_in[3];
  const float* bk  = (const float*)d_in[4];
  const float* Wv  = (const float*)d_in[5];
  const float* bv  = (const float*)d_in[6];
  const float* wpq = (const float*)d_in[7];
  const float* wpk = (const float*)d_in[8];
  const float* wpv = (const float*)d_in[9];
  const float* wpx = (const float*)d_in[10];
  const float* Wd  = (const float*)d_in[11];
  const float* bd  = (const float*)d_in[12];
  const float* gamma = (const float*)d_in[13];
  const float* beta  = (const float*)d_in[14];
  float* y = (float*)d_out;

  float* S = nullptr;
  cudaGetSymbolAddress((void**)&S, g_scratch);
  __nv_bfloat16* Bf = nullptr;
  cudaGetSymbolAddress((void**)&Bf, g_bf);

  float* PQ   = S + OF_PQ;
  float* PK   = S + OF_PK;
  float* PX   = S + OF_PX;
  float* emb  = S + OF_EMB;
  float* bpool = S + OF_BP;
  float* lg   = S + OF_LG;

  __nv_bfloat16* wpT2  = Bf + OB_WPT2;
  __nv_bfloat16* Wt2   = Bf + OB_WT2;
  __nv_bfloat16* WXe2  = Bf + OB_WXE2;
  __nv_bfloat16* Wd2   = Bf + OB_WD2;
  __nv_bfloat16* Weff2 = Bf + OB_WEFF2;
  __nv_bfloat16* Xg2   = Bf + OB_XG2;
  __nv_bfloat16* PQ2   = Bf + OB_PQ2;
  __nv_bfloat16* K22   = Bf + OB_K22;
  __nv_bfloat16* PVt2  = Bf + OB_PVT2;
  __nv_bfloat16* at2   = Bf + OB_AT2;
  __nv_bfloat16* st2b  = Bf + OB_ST2;

  // converters
  k_wpT2<<<(int)((3u * 512 * 512 * 4 + 255) / 256), 256>>>(wpq, wpk, wpv, wpT2);
  k_wt2<<<(int)((3u * 8 * 512 * 512 + 255) / 256), 256>>>(Wq, Wk, Wv, Wt2);
  k_wxe2<<<(512 * 2048 + 255) / 256, 256>>>(wpx, WXe2);
  k_wd2<<<(512 * 4096 + 255) / 256, 256>>>(Wd, Wd2);
  k_bpool<<<(3 * 4096 + 255) / 256, 256>>>(wpq, wpk, wpv, bq, bk, bv, bpool);
  k_gather2<<<(int)((3136u * 2048 + 255) / 256), 256>>>(x, Xg2);
  k_padpv<<<(16 * 512 * 31 + 255) / 256, 256>>>(PVt2);

  {
    WeffP p;
    p.M = 512; p.N = 512; p.nch = 16; p.Kh = 512; p.sA = 1024; p.sB = 1024;
    p.wpT2 = wpT2; p.Wt2 = Wt2; p.Weff2 = Weff2;
    gemm_ca<WeffP, true><<<dim3(4, 4, 96), 256>>>(p);
  }

  {
    PoolQP p;
    p.M = 3136; p.N = 4096; p.nch = 64; p.Kh = 2048; p.sA = 4096; p.sB = 4096;
    p.Xg2 = Xg2; p.W2 = Weff2; p.bias = bpool; p.PQ = PQ; p.PQ2 = PQ2;
    gemm_ca<PoolQP, true><<<dim3(32, 25, 1), 256>>>(p);
  }
  {
    PoolKP p;
    p.M = 3136; p.N = 4096; p.nch = 64; p.Kh = 2048; p.sA = 4096; p.sB = 4096;
    p.Xg2 = Xg2; p.W2 = Weff2 + (size_t)4096 * 4096; p.bias = bpool + 4096;
    p.PK = PK;
    gemm_ca<PoolKP, false><<<dim3(32, 25, 1), 256>>>(p);
  }
  {
    PoolVP p;
    p.M = 3136; p.N = 4096; p.nch = 64; p.Kh = 2048; p.sA = 4096; p.sB = 4096;
    p.Xg2 = Xg2; p.W2 = Weff2 + (size_t)2 * 4096 * 4096; p.bias = bpool + 8192;
    p.PVt2 = PVt2;
    gemm_ca<PoolVP, true><<<dim3(32, 25, 1), 256>>>(p);
  }
  {
    PoolXP p;
    p.M = 3136; p.N = 512; p.nch = 64; p.Kh = 2048; p.sA = 4096; p.sB = 4096;
    p.Xg2 = Xg2; p.W2 = WXe2; p.PX = PX;
    gemm_ca<PoolXP, true><<<dim3(4, 25, 1), 256>>>(p);
  }

  k_cls<<<(2 * 12288 + 2 * 512 + 255) / 256, 256>>>(x, Wq, bq, Wk, bk, Wv, bv,
                                                    PQ, PK, PX, PQ2, PVt2);
  k_emb<<<(int)((SZ_EMB + 255) / 256), 256>>>(emb);
  k_k2<<<(int)(((size_t)16 * LP_ * 512 + 255) / 256), 256>>>(PK, emb, K22);

  {
    LogitsP p;
    p.M = LP_; p.N = LP_; p.nch = 16; p.Kh = 512; p.sA = 1024; p.sB = 1024;
    p.PQ2 = PQ2; p.K22 = K22; p.lg = lg;
    gemm_ca<LogitsP, true><<<dim3(13, 13, 16), 256>>>(p);
  }

  k_row0<<<dim3((LP_ + 7) / 8, 16), 256>>>(PQ, PK, lg);
  k_softmax<<<dim3(LP_, 16), 256>>>(lg, at2);

  {
    AVP p;
    p.M = LP_; p.N = 512; p.nch = 50; p.Kh = 1600; p.sA = 3200; p.sB = 3200;
    p.at2 = at2; p.PVt2 = PVt2; p.PQ = PQ; p.st2b = st2b;
    gemm_ca<AVP, true><<<dim3(4, 13, 16), 256>>>(p);
  }

  {
    FinalP p;
    p.M = B_ * LP_; p.N = 512; p.nch = 128; p.Kh = 4096; p.sA = 8192;
    p.sB = 8192;
    p.st2b = st2b; p.Wd2 = Wd2; p.bd = bd; p.PX = PX; p.y = y;
    gemm_ca<FinalP, true><<<dim3(4, 25, 1), 256>>>(p);
  }

  k_ln<<<B_ * LP_, 256>>>(y, gamma, beta);
}

// round 11
// speedup vs baseline: 1.1461x; 1.1461x over previous
#include <cuda_runtime.h>
#include <cuda_bf16.h>
#include <math.h>
#include <stdint.h>
#include <stddef.h>

// ---------------------------------------------------------------------------
// MultiHeadPooledAttention — bf16 HMMA GEMMs, operands pre-split into planar
// bf16 hi/lo; cp.async 2-stage pipeline loading all 4 planes per chunk, all
// 3 split passes run from resident SMEM. 64x64 warp tiles (4 warps/CTA).
// ---------------------------------------------------------------------------

namespace {
constexpr int B_  = 2;
constexpr int L_  = 6273;   // 1 + 8*28*28
constexpr int NH_ = 8;
constexpr int LP_ = 1569;   // 1 + 8*14*14
constexpr int LPP_ = 1600;
constexpr int NB_ = 1568;
constexpr int LGLD_ = 1600;
constexpr float SCALE_ = 0.04419417382415922f;  // 512^-0.5

// fp32 scratch
constexpr size_t SZ_PQ  = (size_t)16 * LP_ * 512;
constexpr size_t SZ_PK  = (size_t)16 * LP_ * 512;
constexpr size_t SZ_PX  = (size_t)B_ * LP_ * 512;
constexpr size_t SZ_EMB = (size_t)NB_ * 512;
constexpr size_t SZ_BP  = (size_t)3 * 4096;
constexpr size_t SZ_LG  = (size_t)16 * LP_ * LGLD_;

constexpr size_t OF_PQ  = 0;
constexpr size_t OF_PK  = OF_PQ + SZ_PQ;
constexpr size_t OF_PX  = OF_PK + SZ_PK;
constexpr size_t OF_EMB = OF_PX + SZ_PX;
constexpr size_t OF_BP  = OF_EMB + SZ_EMB;
constexpr size_t OF_LG  = OF_BP + SZ_BP;
constexpr size_t SZ_F32 = OF_LG + SZ_LG;

// bf16 hi/lo buffers (planar: hi at [0,Kh), lo at [Kh,2Kh), row stride 2Kh)
constexpr size_t SZB_WPT2  = (size_t)12 * 512 * 1024;
constexpr size_t SZB_WT2   = (size_t)24 * 512 * 1024;
constexpr size_t SZB_WXE2  = (size_t)512 * 4096;
constexpr size_t SZB_WD2   = (size_t)512 * 8192;
constexpr size_t SZB_WEFF2 = (size_t)3 * 4096 * 4096;
constexpr size_t SZB_XG2   = (size_t)3136 * 4096;
constexpr size_t SZB_PQ2   = (size_t)16 * LP_ * 1024;
constexpr size_t SZB_K22   = (size_t)16 * LP_ * 1024;
constexpr size_t SZB_PVT2  = (size_t)16 * 512 * 3200;
constexpr size_t SZB_AT2   = (size_t)16 * LP_ * 3200;
constexpr size_t SZB_ST2   = (size_t)B_ * LP_ * 8192;

constexpr size_t OB_WPT2  = 0;
constexpr size_t OB_WT2   = OB_WPT2 + SZB_WPT2;
constexpr size_t OB_WXE2  = OB_WT2 + SZB_WT2;
constexpr size_t OB_WD2   = OB_WXE2 + SZB_WXE2;
constexpr size_t OB_WEFF2 = OB_WD2 + SZB_WD2;
constexpr size_t OB_XG2   = OB_WEFF2 + SZB_WEFF2;
constexpr size_t OB_PQ2   = OB_XG2 + SZB_XG2;
constexpr size_t OB_K22   = OB_PQ2 + SZB_PQ2;
constexpr size_t OB_PVT2  = OB_K22 + SZB_K22;
constexpr size_t OB_AT2   = OB_PVT2 + SZB_PVT2;
constexpr size_t OB_ST2   = OB_AT2 + SZB_AT2;
constexpr size_t SZ_BF    = OB_ST2 + SZB_ST2;
}  // namespace

__device__ float g_scratch[SZ_F32];
__device__ __align__(16) __nv_bfloat16 g_bf[SZ_BF];

// ------------------------------- PTX helpers -------------------------------

__device__ __forceinline__ uint32_t smem_u32(const void* p) {
  uint32_t a;
  asm("{ .reg .u64 t; cvta.to.shared.u64 t, %1; cvt.u32.u64 %0, t; }"
      : "=r"(a) : "l"(p));
  return a;
}

__device__ __forceinline__ void ldm4(uint32_t* d, uint32_t addr) {
  asm volatile("ldmatrix.sync.aligned.m8n8.x4.shared.b16 {%0,%1,%2,%3}, [%4];"
               : "=r"(d[0]), "=r"(d[1]), "=r"(d[2]), "=r"(d[3]) : "r"(addr));
}

__device__ __forceinline__ void mma16816(float* c, const uint32_t* a,
                                         const uint32_t* b) {
  asm volatile(
      "mma.sync.aligned.m16n8k16.row.col.f32.bf16.bf16.f32 "
      "{%0,%1,%2,%3}, {%4,%5,%6,%7}, {%8,%9}, {%0,%1,%2,%3};"
      : "+f"(c[0]), "+f"(c[1]), "+f"(c[2]), "+f"(c[3])
      : "r"(a[0]), "r"(a[1]), "r"(a[2]), "r"(a[3]), "r"(b[0]), "r"(b[1]));
}

__device__ __forceinline__ void cpa16(uint32_t dst, const void* src, bool ok) {
  int sz = ok ? 16 : 0;
  asm volatile("cp.async.cg.shared.global [%0], [%1], 16, %2;"
               :: "r"(dst), "l"(src), "r"(sz) : "memory");
}
__device__ __forceinline__ void cpa_commit() {
  asm volatile("cp.async.commit_group;" ::: "memory");
}
template <int N>
__device__ __forceinline__ void cpa_wait() {
  asm volatile("cp.async.wait_group %0;" :: "n"(N) : "memory");
}

// write hi/lo split at planar offset
__device__ __forceinline__ void st2(__nv_bfloat16* p, size_t i, size_t kh,
                                    float v) {
  __nv_bfloat16 h = __float2bfloat16(v);
  p[i] = h;
  p[i + kh] = __float2bfloat16(v - __bfloat162float(h));
}

// --------------------------- cp.async GEMM kernel ----------------------------
// C[M,N] = A[M,K]·B[N,K]^T, bf16 hi/lo planar operands. Tile 128x128 x 32;
// 128 threads (4 warps, 64x64 each); 2 stages x 4 planes of SMEM.

constexpr int ROWB = 80;
constexpr int TILEB = 128 * ROWB;        // 10240
constexpr int STAGEB = 4 * TILEB;        // 40960
constexpr int SMEMB = 2 * STAGEB;        // 81920

__device__ __forceinline__ void issue4(const __nv_bfloat16* S, int stride,
                                       int rmax, int r0, int kofs,
                                       uint32_t dstB, int tid) {
#pragma unroll
  for (int i = 0; i < 4; i++) {
    int idx = tid + 128 * i;       // 512 x 16B units
    int row = idx >> 2, q = idx & 3;
    int gr = r0 + row;
    bool ok = gr < rmax;
    const __nv_bfloat16* src =
        S + (size_t)(ok ? gr : 0) * stride + kofs + q * 8;
    cpa16(dstB + (uint32_t)(row * ROWB + q * 16), src, ok);
  }
}

template <typename P, bool SPLIT>
__global__ __launch_bounds__(128) void gemm_ca(P p) {
  extern __shared__ __align__(16) char sm[];
  uint32_t base = smem_u32(sm);

  const int tid = threadIdx.x;
  const int wid = tid >> 5, lane = tid & 31;
  const int wm = wid >> 1, wn = wid & 1;   // 2x2 warps, 64x64 each
  const int lj = lane >> 3, lr = lane & 7;

  const int z = blockIdx.z;
  const __nv_bfloat16* A = p.Aptr(z);
  const __nv_bfloat16* Bm = p.Bptr(z);
  const int M = p.M, N = p.N;
  const int m0 = blockIdx.y * 128, n0 = blockIdx.x * 128;
  const int nch = p.nch, Kh = p.Kh, sA = p.sA, sB = p.sB;

  float acc[4][8][4];
#pragma unroll
  for (int a = 0; a < 4; a++)
#pragma unroll
    for (int b = 0; b < 8; b++)
#pragma unroll
      for (int c = 0; c < 4; c++) acc[a][b][c] = 0.f;

  const uint32_t aRow = (uint32_t)(wm * 64 + (lj & 1) * 8 + lr);
  const uint32_t aCol = (uint32_t)((lj >> 1) * 16);
  const uint32_t bRow = (uint32_t)(wn * 64 + (lj >> 1) * 8 + lr);
  const uint32_t bCol = (uint32_t)((lj & 1) * 16);

  // prologue: chunk 0 into stage 0
  {
    uint32_t st = base;
    issue4(A, sA, M, m0, 0, st, tid);
    if (SPLIT) issue4(A, sA, M, m0, Kh, st + TILEB, tid);
    issue4(Bm, sB, N, n0, 0, st + 2 * TILEB, tid);
    if (SPLIT) issue4(Bm, sB, N, n0, Kh, st + 3 * TILEB, tid);
    cpa_commit();
  }

  for (int ch = 0; ch < nch; ++ch) {
    int s = ch & 1;
    if (ch + 1 < nch) {
      int k0 = (ch + 1) * 32;
      uint32_t st = base + (uint32_t)((1 - s) * STAGEB);
      issue4(A, sA, M, m0, k0, st, tid);
      if (SPLIT) issue4(A, sA, M, m0, Kh + k0, st + TILEB, tid);
      issue4(Bm, sB, N, n0, k0, st + 2 * TILEB, tid);
      if (SPLIT) issue4(Bm, sB, N, n0, Kh + k0, st + 3 * TILEB, tid);
      cpa_commit();
      cpa_wait<1>();
    } else {
      cpa_wait<0>();
    }
    __syncthreads();

    uint32_t stg = base + (uint32_t)(s * STAGEB);
    const int npass = SPLIT ? 3 : 1;
#pragma unroll 1
    for (int ps = 0; ps < npass; ps++) {
      uint32_t aT = stg + ((ps == 1) ? TILEB : 0);
      uint32_t bT = stg + 2 * TILEB + ((ps == 2) ? TILEB : 0);
#pragma unroll
      for (int ks = 0; ks < 2; ks++) {
        uint32_t afr[4][4];
#pragma unroll
        for (int mi = 0; mi < 4; mi++)
          ldm4(afr[mi], aT + (aRow + mi * 16) * ROWB + ks * 32 + aCol);
        uint32_t bfr[8][2];
#pragma unroll
        for (int nb = 0; nb < 4; nb++) {
          uint32_t t[4];
          ldm4(t, bT + (bRow + nb * 16) * ROWB + ks * 32 + bCol);
          bfr[2 * nb][0] = t[0];
          bfr[2 * nb][1] = t[1];
          bfr[2 * nb + 1][0] = t[2];
          bfr[2 * nb + 1][1] = t[3];
        }
#pragma unroll
        for (int mi = 0; mi < 4; mi++)
#pragma unroll
          for (int ni = 0; ni < 8; ni++)
            mma16816(acc[mi][ni], afr[mi], bfr[ni]);
      }
    }
    __syncthreads();
  }

  const int rr = lane >> 2, cc = (lane & 3) * 2;
#pragma unroll
  for (int mi = 0; mi < 4; mi++) {
#pragma unroll
    for (int ni = 0; ni < 8; ni++) {
      int rb = m0 + wm * 64 + mi * 16 + rr;
      int cb = n0 + wn * 64 + ni * 8 + cc;
      if (rb < M) {
        if (cb < N)     p.store(z, rb, cb,     acc[mi][ni][0]);
        if (cb + 1 < N) p.store(z, rb, cb + 1, acc[mi][ni][1]);
      }
      if (rb + 8 < M) {
        if (cb < N)     p.store(z, rb + 8, cb,     acc[mi][ni][2]);
        if (cb + 1 < N) p.store(z, rb + 8, cb + 1, acc[mi][ni][3]);
      }
    }
  }
}

// ----------------------------- GEMM problem defs ----------------------------

struct WeffP {
  int M, N, nch, Kh, sA, sB;
  const __nv_bfloat16 *wpT2, *Wt2;
  __nv_bfloat16* Weff2;
  __device__ const __nv_bfloat16* Aptr(int z) const {
    int ti = z >> 5, t = z & 3;
    return wpT2 + (size_t)(ti * 4 + t) * 512 * 1024;
  }
  __device__ const __nv_bfloat16* Bptr(int z) const {
    int ti = z >> 5, n = (z & 31) >> 2;
    return Wt2 + (size_t)(ti * 8 + n) * 512 * 1024;
  }
  __device__ void store(int z, int r, int c, float v) const {
    int ti = z >> 5, n = (z & 31) >> 2, t = z & 3;
    size_t row = (size_t)ti * 4096 + n * 512 + r;
    st2(Weff2, row * 4096 + t * 512 + c, 2048, v);
  }
};

struct PoolQP {
  int M, N, nch, Kh, sA, sB;
  const __nv_bfloat16 *Xg2, *W2;
  const float* bias;
  float* PQ;
  __nv_bfloat16* PQ2;
  __device__ const __nv_bfloat16* Aptr(int) const { return Xg2; }
  __device__ const __nv_bfloat16* Bptr(int) const { return W2; }
  __device__ void store(int, int r, int c, float v) const {
    int b = r / NB_, o = r % NB_;
    v += bias[c];
    int n = c >> 9, d = c & 511;
    PQ[((size_t)(b * 8 + n) * LP_ + 1 + o) * 512 + d] = v;
    st2(PQ2, ((size_t)(b * 8 + n) * LP_ + 1 + o) * 1024 + d, 512, v);
  }
};

struct PoolKP {
  int M, N, nch, Kh, sA, sB;
  const __nv_bfloat16 *Xg2, *W2;
  const float* bias;
  float* PK;
  __device__ const __nv_bfloat16* Aptr(int) const { return Xg2; }
  __device__ const __nv_bfloat16* Bptr(int) const { return W2; }
  __device__ void store(int, int r, int c, float v) const {
    int b = r / NB_, o = r % NB_;
    v += bias[c];
    int n = c >> 9, d = c & 511;
    PK[((size_t)(b * 8 + n) * LP_ + 1 + o) * 512 + d] = v;
  }
};

struct PoolVP {
  int M, N, nch, Kh, sA, sB;
  const __nv_bfloat16 *Xg2, *W2;
  const float* bias;
  __nv_bfloat16* PVt2;
  __device__ const __nv_bfloat16* Aptr(int) const { return Xg2; }
  __device__ const __nv_bfloat16* Bptr(int) const { return W2; }
  __device__ void store(int, int r, int c, float v) const {
    int b = r / NB_, o = r % NB_;
    v += bias[c];
    int n = c >> 9, d = c & 511;
    st2(PVt2, ((size_t)(b * 8 + n) * 512 + d) * 3200 + 1 + o, 1600, v);
  }
};

struct PoolXP {
  int M, N, nch, Kh, sA, sB;
  const __nv_bfloat16 *Xg2, *W2;
  float* PX;
  __device__ const __nv_bfloat16* Aptr(int) const { return Xg2; }
  __device__ const __nv_bfloat16* Bptr(int) const { return W2; }
  __device__ void store(int, int r, int c, float v) const {
    int b = r / NB_, o = r % NB_;
    PX[((size_t)b * LP_ + 1 + o) * 512 + c] = v;
  }
};

struct LogitsP {
  int M, N, nch, Kh, sA, sB;
  const __nv_bfloat16 *PQ2, *K22;
  float* lg;
  __device__ const __nv_bfloat16* Aptr(int z) const {
    return PQ2 + (size_t)z * LP_ * 1024;
  }
  __device__ const __nv_bfloat16* Bptr(int z) const {
    return K22 + (size_t)z * LP_ * 1024;
  }
  __device__ void store(int z, int r, int c, float v) const {
    lg[(size_t)z * LP_ * LGLD_ + (size_t)r * LGLD_ + c] = v;
  }
};

struct AVP {
  int M, N, nch, Kh, sA, sB;
  const __nv_bfloat16 *at2, *PVt2;
  const float* PQ;
  __nv_bfloat16* st2b;
  __device__ const __nv_bfloat16* Aptr(int z) const {
    return at2 + (size_t)z * LP_ * 3200;
  }
  __device__ const __nv_bfloat16* Bptr(int z) const {
    return PVt2 + (size_t)z * 512 * 3200;
  }
  __device__ void store(int z, int r, int c, float v) const {
    float pq = PQ[(size_t)z * LP_ * 512 + (size_t)r * 512 + c];
    v += (r > 0 ? 2.f : 1.f) * pq;
    int b = z >> 3, n = z & 7;
    st2(st2b, ((size_t)b * LP_ + r) * 8192 + n * 512 + c, 4096, v);
  }
};

struct FinalP {
  int M, N, nch, Kh, sA, sB;
  const __nv_bfloat16 *st2b, *Wd2;
  const float* bd;
  const float* PX;
  float* y;
  __device__ const __nv_bfloat16* Aptr(int) const { return st2b; }
  __device__ const __nv_bfloat16* Bptr(int) const { return Wd2; }
  __device__ void store(int, int r, int c, float v) const {
    y[(size_t)r * 512 + c] = v + bd[c] + PX[(size_t)r * 512 + c];
  }
};

// ------------------------------ helper kernels ------------------------------

__global__ void k_wpT2(const float* wpq, const float* wpk, const float* wpv,
                       __nv_bfloat16* wpT2) {
  size_t idx = (size_t)blockIdx.x * blockDim.x + threadIdx.x;
  if (idx >= (size_t)3 * 512 * 512 * 4) return;
  int ti = (int)(idx / (512 * 512 * 4));
  int r = (int)(idx % (512 * 512 * 4));
  int c = r / 2048;
  int d = (r % 2048) >> 2;
  int t = r & 3;
  const float* wp = (ti == 0) ? wpq : ((ti == 1) ? wpk : wpv);
  st2(wpT2, ((size_t)(ti * 4 + t) * 512 + c) * 1024 + d, 512, wp[r]);
}

__global__ void k_wt2(const float* Wq, const float* Wk, const float* Wv,
                      __nv_bfloat16* Wt2) {
  size_t idx = (size_t)blockIdx.x * blockDim.x + threadIdx.x;
  if (idx >= (size_t)3 * 8 * 512 * 512) return;
  int d = (int)(idx & 511);
  int m = (int)((idx >> 9) & 511);
  int n = (int)((idx >> 18) & 7);
  int ti = (int)(idx >> 21);
  const float* W = (ti == 0) ? Wq : ((ti == 1) ? Wk : Wv);
  float v = W[(size_t)(n * 512 + d) * 512 + m];
  st2(Wt2, ((size_t)(ti * 8 + n) * 512 + m) * 1024 + d, 512, v);
}

__global__ void k_wxe2(const float* wpx, __nv_bfloat16* WXe2) {
  size_t idx = (size_t)blockIdx.x * blockDim.x + threadIdx.x;
  if (idx >= (size_t)512 * 2048) return;
  int c = (int)(idx >> 11);
  int col = (int)(idx & 2047);
  int t = col >> 9, m = col & 511;
  float v = wpx[(size_t)c * 2048 + m * 4 + t];
  st2(WXe2, (size_t)c * 4096 + col, 2048, v);
}

__global__ void k_wd2(const float* Wd, __nv_bfloat16* Wd2) {
  size_t idx = (size_t)blockIdx.x * blockDim.x + threadIdx.x;
  if (idx >= (size_t)512 * 4096) return;
  int c = (int)(idx >> 12), k = (int)(idx & 4095);
  st2(Wd2, (size_t)c * 8192 + k, 4096, Wd[idx]);
}

__global__ void k_bpool(const float* wpq, const float* wpk, const float* wpv,
                        const float* bq, const float* bk, const float* bv,
                        float* bpool) {
  int j = blockIdx.x * blockDim.x + threadIdx.x;
  if (j >= 3 * 4096) return;
  int ti = j / 4096, h = j % 4096, n = h >> 9, c = h & 511;
  const float* wp = (ti == 0) ? wpq : ((ti == 1) ? wpk : wpv);
  const float* b = (ti == 0) ? bq : ((ti == 1) ? bk : bv);
  float s = 0.f;
  for (int d = 0; d < 512; d++) {
    float bb = b[n * 512 + d];
    const float* w = wp + (size_t)c * 2048 + d * 4;
    s += (w[0] + w[1] + w[2] + w[3]) * bb;
  }
  bpool[j] = s;
}

__global__ void k_gather2(const float* x, __nv_bfloat16* Xg2) {
  size_t idx = (size_t)blockIdx.x * blockDim.x + threadIdx.x;
  if (idx >= (size_t)3136 * 2048) return;
  int r = (int)(idx >> 11);
  int col = (int)(idx & 2047);
  int t = col >> 9, m = col & 511;
  int b = r / NB_, o = r % NB_;
  int t2 = o / 196, hh = (o / 14) % 14, ww = o % 14;
  int kh = t >> 1, kw = t & 1;
  int row = 1 + (t2 * 28 + 2 * hh + kh) * 28 + 2 * ww + kw;
  float v = x[((size_t)b * L_ + row) * 512 + m];
  st2(Xg2, (size_t)r * 4096 + col, 2048, v);
}

__global__ void k_padpv(__nv_bfloat16* PVt2) {
  int idx = blockIdx.x * blockDim.x + threadIdx.x;
  if (idx >= 16 * 512 * 31) return;
  int j = idx % 31;
  int rc = idx / 31;
  int k = LP_ + j;
  size_t b = (size_t)rc * 3200;
  PVt2[b + k] = __float2bfloat16(0.f);
  PVt2[b + 1600 + k] = __float2bfloat16(0.f);
}

__global__ void k_cls(const float* x, const float* Wq, const float* bq,
                      const float* Wk, const float* bk, const float* Wv,
                      const float* bv, float* PQ, float* PK, float* PX,
                      __nv_bfloat16* PQ2, __nv_bfloat16* PVt2) {
  int idx = blockIdx.x * blockDim.x + threadIdx.x;
  if (idx < 2 * 12288) {
    int b = idx / 12288, j = idx % 12288, ti = j / 4096, jj = j & 4095;
    const float* W = (ti == 0) ? Wq : ((ti == 1) ? Wk : Wv);
    const float* bias = (ti == 0) ? bq : ((ti == 1) ? bk : bv);
    const float* xr = x + (size_t)b * L_ * 512;
    const float* wr = W + (size_t)jj * 512;
    float s = bias[jj];
    for (int m = 0; m < 512; m++) s += xr[m] * wr[m];
    int n = jj >> 9, c = jj & 511;
    int zz = b * 8 + n;
    if (ti == 0) {
      PQ[(size_t)zz * LP_ * 512 + c] = s;
      st2(PQ2, (size_t)zz * LP_ * 1024 + c, 512, s);
    } else if (ti == 1) {
      PK[(size_t)zz * LP_ * 512 + c] = s;
    } else {
      st2(PVt2, ((size_t)zz * 512 + c) * 3200 + 0, 1600, s);
    }
  } else if (idx < 2 * 12288 + 2 * 512) {
    int k = idx - 2 * 12288;
    int b = k >> 9, c = k & 511;
    PX[(size_t)b * LP_ * 512 + c] = x[(size_t)b * L_ * 512 + c];
  }
}

__device__ __forceinline__ float sincos_val(int pos, int c, int dim) {
  int half = dim / 2;
  bool is_cos = c >= half;
  int i = is_cos ? c - half : c;
  float omega = powf(10000.f, -((float)i) / (float)half);
  float ang = (float)pos * omega;
  return is_cos ? cosf(ang) : sinf(ang);
}

__global__ void k_emb(float* emb) {
  size_t idx = (size_t)blockIdx.x * blockDim.x + threadIdx.x;
  if (idx >= SZ_EMB) return;
  int k = (int)(idx >> 9);
  int c = (int)(idx & 511);
  int t2 = k / 196, h2 = (k / 14) % 14, w2 = k % 14;
  float v;
  if (c < 170) v = sincos_val(t2, c, 170);
  else if (c < 340) v = sincos_val(h2, c - 170, 170);
  else v = sincos_val(w2, c - 340, 172);
  emb[idx] = v;
}

__global__ void k_k2(const float* PK, const float* emb, __nv_bfloat16* K22) {
  size_t idx = (size_t)blockIdx.x * blockDim.x + threadIdx.x;
  if (idx >= (size_t)16 * LP_ * 512) return;
  size_t rem = idx % ((size_t)LP_ * 512);
  int k = (int)(rem >> 9);
  int c = (int)(rem & 511);
  size_t z = idx / ((size_t)LP_ * 512);
  float v = SCALE_ * PK[idx];
  if (k > 0) v += emb[(size_t)(k - 1) * 512 + c];
  st2(K22, (z * LP_ + k) * 1024 + c, 512, v);
}

__global__ void k_row0(const float* PQ, const float* PK, float* lg) {
  int z = blockIdx.y;
  int kq = blockIdx.x * 8 + (threadIdx.x >> 5);
  int lane = threadIdx.x & 31;
  if (kq >= LP_) return;
  const float* q = PQ + (size_t)z * LP_ * 512;
  const float* kr = PK + (size_t)z * LP_ * 512 + (size_t)kq * 512;
  float s = 0.f;
  for (int i = lane; i < 512; i += 32) s += q[i] * kr[i];
#pragma unroll
  for (int o = 16; o; o >>= 1) s += __shfl_xor_sync(0xFFFFFFFFu, s, o);
  if (lane == 0) lg[(size_t)z * LP_ * LGLD_ + kq] = s * SCALE_;
}

__global__ void k_softmax(float* lg, __nv_bfloat16* at2) {
  int z = blockIdx.y, q = blockIdx.x;
  float* row = lg + ((size_t)z * LP_ + q) * LGLD_;
  __nv_bfloat16* arow = at2 + ((size_t)z * LP_ + q) * 3200;
  int tid = threadIdx.x;
  __shared__ float red[256];
  float mx = -1e30f;
  for (int i = tid; i < LP_; i += 256) mx = fmaxf(mx, row[i]);
  red[tid] = mx;
  __syncthreads();
  for (int s = 128; s > 0; s >>= 1) {
    if (tid < s) red[tid] = fmaxf(red[tid], red[tid + s]);
    __syncthreads();
  }
  mx = red[0];
  __syncthreads();
  float sum = 0.f;
  for (int i = tid; i < LP_; i += 256) {
    float e = expf(row[i] - mx);
    row[i] = e;
    sum += e;
  }
  red[tid] = sum;
  __syncthreads();
  for (int s = 128; s > 0; s >>= 1) {
    if (tid < s) red[tid] += red[tid + s];
    __syncthreads();
  }
  float inv = 1.f / red[0];
  for (int i = tid; i < LPP_; i += 256) {
    float v = (i < LP_) ? row[i] * inv : 0.f;
    __nv_bfloat16 h = __float2bfloat16(v);
    arow[i] = h;
    arow[1600 + i] = __float2bfloat16(v - __bfloat162float(h));
  }
}

__global__ void k_ln(float* y, const float* gamma, const float* beta) {
  int row = blockIdx.x;
  float* yr = y + (size_t)row * 512;
  int tid = threadIdx.x;
  float v0 = yr[tid], v1 = yr[tid + 256];
  __shared__ float red[256];
  red[tid] = v0 + v1;
  __syncthreads();
  for (int s = 128; s > 0; s >>= 1) {
    if (tid < s) red[tid] += red[tid + s];
    __syncthreads();
  }
  float mu = red[0] * (1.f / 512.f);
  __syncthreads();
  float d0 = v0 - mu, d1 = v1 - mu;
  red[tid] = d0 * d0 + d1 * d1;
  __syncthreads();
  for (int s = 128; s > 0; s >>= 1) {
    if (tid < s) red[tid] += red[tid + s];
    __syncthreads();
  }
  float inv = rsqrtf(red[0] * (1.f / 512.f) + 1e-5f);
  yr[tid] = d0 * inv * gamma[tid] + beta[tid];
  yr[tid + 256] = d1 * inv * gamma[tid + 256] + beta[tid + 256];
}

// --------------------------------- launcher ---------------------------------

extern "C" void kernel_launch(void* const* d_in, const int* in_sizes, int n_in,
                              void* d_out, int out_size) {
  (void)in_sizes; (void)n_in; (void)out_size;
  const float* x   = (const float*)d_in[0];
  const float* Wq  = (const float*)d_in[1];
  const float* bq  = (const float*)d_in[2];
  const float* Wk  = (const float*)d_in[3];
  const float* bk  = (const float*)d_in[4];
  const float* Wv  = (const float*)d_in[5];
  const float* bv  = (const float*)d_in[6];
  const float* wpq = (const float*)d_in[7];
  const float* wpk = (const float*)d_in[8];
  const float* wpv = (const float*)d_in[9];
  const float* wpx = (const float*)d_in[10];
  const float* Wd  = (const float*)d_in[11];
  const float* bd  = (const float*)d_in[12];
  const float* gamma = (const float*)d_in[13];
  const float* beta  = (const float*)d_in[14];
  float* y = (float*)d_out;

  float* S = nullptr;
  cudaGetSymbolAddress((void**)&S, g_scratch);
  __nv_bfloat16* Bf = nullptr;
  cudaGetSymbolAddress((void**)&Bf, g_bf);

  float* PQ    = S + OF_PQ;
  float* PK    = S + OF_PK;
  float* PX    = S + OF_PX;
  float* emb   = S + OF_EMB;
  float* bpool = S + OF_BP;
  float* lg    = S + OF_LG;

  __nv_bfloat16* wpT2  = Bf + OB_WPT2;
  __nv_bfloat16* Wt2   = Bf + OB_WT2;
  __nv_bfloat16* WXe2  = Bf + OB_WXE2;
  __nv_bfloat16* Wd2   = Bf + OB_WD2;
  __nv_bfloat16* Weff2 = Bf + OB_WEFF2;
  __nv_bfloat16* Xg2   = Bf + OB_XG2;
  __nv_bfloat16* PQ2   = Bf + OB_PQ2;
  __nv_bfloat16* K22   = Bf + OB_K22;
  __nv_bfloat16* PVt2  = Bf + OB_PVT2;
  __nv_bfloat16* at2   = Bf + OB_AT2;
  __nv_bfloat16* st2b  = Bf + OB_ST2;

  cudaFuncSetAttribute(gemm_ca<WeffP, true>,
                       cudaFuncAttributeMaxDynamicSharedMemorySize, SMEMB);
  cudaFuncSetAttribute(gemm_ca<PoolQP, true>,
                       cudaFuncAttributeMaxDynamicSharedMemorySize, SMEMB);
  cudaFuncSetAttribute(gemm_ca<PoolKP, false>,
                       cudaFuncAttributeMaxDynamicSharedMemorySize, SMEMB);
  cudaFuncSetAttribute(gemm_ca<PoolVP, true>,
                       cudaFuncAttributeMaxDynamicSharedMemorySize, SMEMB);
  cudaFuncSetAttribute(gemm_ca<PoolXP, true>,
                       cudaFuncAttributeMaxDynamicSharedMemorySize, SMEMB);
  cudaFuncSetAttribute(gemm_ca<LogitsP, true>,
                       cudaFuncAttributeMaxDynamicSharedMemorySize, SMEMB);
  cudaFuncSetAttribute(gemm_ca<AVP, true>,
                       cudaFuncAttributeMaxDynamicSharedMemorySize, SMEMB);
  cudaFuncSetAttribute(gemm_ca<FinalP, true>,
                       cudaFuncAttributeMaxDynamicSharedMemorySize, SMEMB);

  // converters
  k_wpT2<<<(int)((3u * 512 * 512 * 4 + 255) / 256), 256>>>(wpq, wpk, wpv, wpT2);
  k_wt2<<<(int)((3u * 8 * 512 * 512 + 255) / 256), 256>>>(Wq, Wk, Wv, Wt2);
  k_wxe2<<<(512 * 2048 + 255) / 256, 256>>>(wpx, WXe2);
  k_wd2<<<(512 * 4096 + 255) / 256, 256>>>(Wd, Wd2);
  k_bpool<<<(3 * 4096 + 255) / 256, 256>>>(wpq, wpk, wpv, bq, bk, bv, bpool);
  k_gather2<<<(int)((3136u * 2048 + 255) / 256), 256>>>(x, Xg2);
  k_padpv<<<(16 * 512 * 31 + 255) / 256, 256>>>(PVt2);

  {
    WeffP p;
    p.M = 512; p.N = 512; p.nch = 16; p.Kh = 512; p.sA = 1024; p.sB = 1024;
    p.wpT2 = wpT2; p.Wt2 = Wt2; p.Weff2 = Weff2;
    gemm_ca<WeffP, true><<<dim3(4, 4, 96), 128, SMEMB>>>(p);
  }

  {
    PoolQP p;
    p.M = 3136; p.N = 4096; p.nch = 64; p.Kh = 2048; p.sA = 4096; p.sB = 4096;
    p.Xg2 = Xg2; p.W2 = Weff2; p.bias = bpool; p.PQ = PQ; p.PQ2 = PQ2;
    gemm_ca<PoolQP, true><<<dim3(32, 25, 1), 128, SMEMB>>>(p);
  }
  {
    PoolKP p;
    p.M = 3136; p.N = 4096; p.nch = 64; p.Kh = 2048; p.sA = 4096; p.sB = 4096;
    p.Xg2 = Xg2; p.W2 = Weff2 + (size_t)4096 * 4096; p.bias = bpool + 4096;
    p.PK = PK;
    gemm_ca<PoolKP, false><<<dim3(32, 25, 1), 128, SMEMB>>>(p);
  }
  {
    PoolVP p;
    p.M = 3136; p.N = 4096; p.nch = 64; p.Kh = 2048; p.sA = 4096; p.sB = 4096;
    p.Xg2 = Xg2; p.W2 = Weff2 + (size_t)2 * 4096 * 4096; p.bias = bpool + 8192;
    p.PVt2 = PVt2;
    gemm_ca<PoolVP, true><<<dim3(32, 25, 1), 128, SMEMB>>>(p);
  }
  {
    PoolXP p;
    p.M = 3136; p.N = 512; p.nch = 64; p.Kh = 2048; p.sA = 4096; p.sB = 4096;
    p.Xg2 = Xg2; p.W2 = WXe2; p.PX = PX;
    gemm_ca<PoolXP, true><<<dim3(4, 25, 1), 128, SMEMB>>>(p);
  }

  k_cls<<<(2 * 12288 + 2 * 512 + 255) / 256, 256>>>(x, Wq, bq, Wk, bk, Wv, bv,
                                                    PQ, PK, PX, PQ2, PVt2);
  k_emb<<<(int)((SZ_EMB + 255) / 256), 256>>>(emb);
  k_k2<<<(int)(((size_t)16 * LP_ * 512 + 255) / 256), 256>>>(PK, emb, K22);

  {
    LogitsP p;
    p.M = LP_; p.N = LP_; p.nch = 16; p.Kh = 512; p.sA = 1024; p.sB = 1024;
    p.PQ2 = PQ2; p.K22 = K22; p.lg = lg;
    gemm_ca<LogitsP, true><<<dim3(13, 13, 16), 128, SMEMB>>>(p);
  }

  k_row0<<<dim3((LP_ + 7) / 8, 16), 256>>>(PQ, PK, lg);
  k_softmax<<<dim3(LP_, 16), 256>>>(lg, at2);

  {
    AVP p;
    p.M = LP_; p.N = 512; p.nch = 50; p.Kh = 1600; p.sA = 3200; p.sB = 3200;
    p.at2 = at2; p.PVt2 = PVt2; p.PQ = PQ; p.st2b = st2b;
    gemm_ca<AVP, true><<<dim3(4, 13, 16), 128, SMEMB>>>(p);
  }

  {
    FinalP p;
    p.M = B_ * LP_; p.N = 512; p.nch = 128; p.Kh = 4096; p.sA = 8192;
    p.sB = 8192;
    p.st2b = st2b; p.Wd2 = Wd2; p.bd = bd; p.PX = PX; p.y = y;
    gemm_ca<FinalP, true><<<dim3(4, 25, 1), 128, SMEMB>>>(p);
  }

  k_ln<<<B_ * LP_, 256>>>(y, gamma, beta);
}

// round 12
// speedup vs baseline: 1.2096x; 1.0554x over previous
#include <cuda_runtime.h>
#include <cuda_bf16.h>
#include <math.h>
#include <stdint.h>
#include <stddef.h>

// ---------------------------------------------------------------------------
// MultiHeadPooledAttention — bf16 HMMA GEMMs, planar hi/lo operands, cp.async
// 2-stage pipeline, 3 split passes from resident SMEM. Round 12: PoolX merged
// into PoolQ (N=4608); Final GEMM split-K=2 into partials folded into LN.
// ---------------------------------------------------------------------------

namespace {
constexpr int B_  = 2;
constexpr int L_  = 6273;   // 1 + 8*28*28
constexpr int NH_ = 8;
constexpr int LP_ = 1569;   // 1 + 8*14*14
constexpr int LPP_ = 1600;
constexpr int NB_ = 1568;
constexpr int LGLD_ = 1600;
constexpr float SCALE_ = 0.04419417382415922f;  // 512^-0.5

// fp32 scratch
constexpr size_t SZ_PQ  = (size_t)16 * LP_ * 512;
constexpr size_t SZ_PK  = (size_t)16 * LP_ * 512;
constexpr size_t SZ_PX  = (size_t)B_ * LP_ * 512;
constexpr size_t SZ_EMB = (size_t)NB_ * 512;
constexpr size_t SZ_BP  = (size_t)3 * 4096;
constexpr size_t SZ_LG  = (size_t)16 * LP_ * LGLD_;
constexpr size_t SZ_YP  = (size_t)2 * B_ * LP_ * 512;

constexpr size_t OF_PQ  = 0;
constexpr size_t OF_PK  = OF_PQ + SZ_PQ;
constexpr size_t OF_PX  = OF_PK + SZ_PK;
constexpr size_t OF_EMB = OF_PX + SZ_PX;
constexpr size_t OF_BP  = OF_EMB + SZ_EMB;
constexpr size_t OF_LG  = OF_BP + SZ_BP;
constexpr size_t OF_YP  = OF_LG + SZ_LG;
constexpr size_t SZ_F32 = OF_YP + SZ_YP;

// bf16 hi/lo buffers (planar: hi at [0,Kh), lo at [Kh,2Kh), row stride 2Kh)
constexpr size_t SZB_WPT2  = (size_t)12 * 512 * 1024;
constexpr size_t SZB_WT2   = (size_t)24 * 512 * 1024;
constexpr size_t SZB_WD2   = (size_t)512 * 8192;
constexpr size_t SZB_WQX2  = (size_t)4608 * 4096;       // Weff-Q (4096) + WXe (512)
constexpr size_t SZB_WKV2  = (size_t)2 * 4096 * 4096;   // Weff-K, Weff-V
constexpr size_t SZB_XG2   = (size_t)3136 * 4096;
constexpr size_t SZB_PQ2   = (size_t)16 * LP_ * 1024;
constexpr size_t SZB_K22   = (size_t)16 * LP_ * 1024;
constexpr size_t SZB_PVT2  = (size_t)16 * 512 * 3200;
constexpr size_t SZB_AT2   = (size_t)16 * LP_ * 3200;
constexpr size_t SZB_ST2   = (size_t)B_ * LP_ * 8192;

constexpr size_t OB_WPT2  = 0;
constexpr size_t OB_WT2   = OB_WPT2 + SZB_WPT2;
constexpr size_t OB_WD2   = OB_WT2 + SZB_WT2;
constexpr size_t OB_WQX2  = OB_WD2 + SZB_WD2;
constexpr size_t OB_WKV2  = OB_WQX2 + SZB_WQX2;
constexpr size_t OB_XG2   = OB_WKV2 + SZB_WKV2;
constexpr size_t OB_PQ2   = OB_XG2 + SZB_XG2;
constexpr size_t OB_K22   = OB_PQ2 + SZB_PQ2;
constexpr size_t OB_PVT2  = OB_K22 + SZB_K22;
constexpr size_t OB_AT2   = OB_PVT2 + SZB_PVT2;
constexpr size_t OB_ST2   = OB_AT2 + SZB_AT2;
constexpr size_t SZ_BF    = OB_ST2 + SZB_ST2;
}  // namespace

__device__ float g_scratch[SZ_F32];
__device__ __align__(16) __nv_bfloat16 g_bf[SZ_BF];

// ------------------------------- PTX helpers -------------------------------

__device__ __forceinline__ uint32_t smem_u32(const void* p) {
  uint32_t a;
  asm("{ .reg .u64 t; cvta.to.shared.u64 t, %1; cvt.u32.u64 %0, t; }"
      : "=r"(a) : "l"(p));
  return a;
}

__device__ __forceinline__ void ldm4(uint32_t* d, uint32_t addr) {
  asm volatile("ldmatrix.sync.aligned.m8n8.x4.shared.b16 {%0,%1,%2,%3}, [%4];"
               : "=r"(d[0]), "=r"(d[1]), "=r"(d[2]), "=r"(d[3]) : "r"(addr));
}

__device__ __forceinline__ void mma16816(float* c, const uint32_t* a,
                                         const uint32_t* b) {
  asm volatile(
      "mma.sync.aligned.m16n8k16.row.col.f32.bf16.bf16.f32 "
      "{%0,%1,%2,%3}, {%4,%5,%6,%7}, {%8,%9}, {%0,%1,%2,%3};"
      : "+f"(c[0]), "+f"(c[1]), "+f"(c[2]), "+f"(c[3])
      : "r"(a[0]), "r"(a[1]), "r"(a[2]), "r"(a[3]), "r"(b[0]), "r"(b[1]));
}

__device__ __forceinline__ void cpa16(uint32_t dst, const void* src, bool ok) {
  int sz = ok ? 16 : 0;
  asm volatile("cp.async.cg.shared.global [%0], [%1], 16, %2;"
               :: "r"(dst), "l"(src), "r"(sz) : "memory");
}
__device__ __forceinline__ void cpa_commit() {
  asm volatile("cp.async.commit_group;" ::: "memory");
}
template <int N>
__device__ __forceinline__ void cpa_wait() {
  asm volatile("cp.async.wait_group %0;" :: "n"(N) : "memory");
}

// write hi/lo split at planar offset
__device__ __forceinline__ void st2(__nv_bfloat16* p, size_t i, size_t kh,
                                    float v) {
  __nv_bfloat16 h = __float2bfloat16(v);
  p[i] = h;
  p[i + kh] = __float2bfloat16(v - __bfloat162float(h));
}

// --------------------------- cp.async GEMM kernel ----------------------------

constexpr int ROWB = 80;
constexpr int TILEB = 128 * ROWB;        // 10240
constexpr int STAGEB = 4 * TILEB;        // 40960
constexpr int SMEMB = 2 * STAGEB;        // 81920

__device__ __forceinline__ void issue4(const __nv_bfloat16* S, int stride,
                                       int rmax, int r0, int kofs,
                                       uint32_t dstB, int tid) {
#pragma unroll
  for (int i = 0; i < 4; i++) {
    int idx = tid + 128 * i;
    int row = idx >> 2, q = idx & 3;
    int gr = r0 + row;
    bool ok = gr < rmax;
    const __nv_bfloat16* src =
        S + (size_t)(ok ? gr : 0) * stride + kofs + q * 8;
    cpa16(dstB + (uint32_t)(row * ROWB + q * 16), src, ok);
  }
}

template <typename P, bool SPLIT>
__global__ __launch_bounds__(128) void gemm_ca(P p) {
  extern __shared__ __align__(16) char sm[];
  uint32_t base = smem_u32(sm);

  const int tid = threadIdx.x;
  const int wid = tid >> 5, lane = tid & 31;
  const int wm = wid >> 1, wn = wid & 1;
  const int lj = lane >> 3, lr = lane & 7;

  const int z = blockIdx.z;
  const __nv_bfloat16* A = p.Aptr(z);
  const __nv_bfloat16* Bm = p.Bptr(z);
  const int M = p.M, N = p.N;
  const int m0 = blockIdx.y * 128, n0 = blockIdx.x * 128;
  const int nch = p.nch, Kh = p.Kh, sA = p.sA, sB = p.sB;
  const int kb = p.kbase(z);

  float acc[4][8][4];
#pragma unroll
  for (int a = 0; a < 4; a++)
#pragma unroll
    for (int b = 0; b < 8; b++)
#pragma unroll
      for (int c = 0; c < 4; c++) acc[a][b][c] = 0.f;

  const uint32_t aRow = (uint32_t)(wm * 64 + (lj & 1) * 8 + lr);
  const uint32_t aCol = (uint32_t)((lj >> 1) * 16);
  const uint32_t bRow = (uint32_t)(wn * 64 + (lj >> 1) * 8 + lr);
  const uint32_t bCol = (uint32_t)((lj & 1) * 16);

  {
    uint32_t st = base;
    issue4(A, sA, M, m0, kb, st, tid);
    if (SPLIT) issue4(A, sA, M, m0, Kh + kb, st + TILEB, tid);
    issue4(Bm, sB, N, n0, kb, st + 2 * TILEB, tid);
    if (SPLIT) issue4(Bm, sB, N, n0, Kh + kb, st + 3 * TILEB, tid);
    cpa_commit();
  }

  for (int ch = 0; ch < nch; ++ch) {
    int s = ch & 1;
    if (ch + 1 < nch) {
      int k0 = kb + (ch + 1) * 32;
      uint32_t st = base + (uint32_t)((1 - s) * STAGEB);
      issue4(A, sA, M, m0, k0, st, tid);
      if (SPLIT) issue4(A, sA, M, m0, Kh + k0, st + TILEB, tid);
      issue4(Bm, sB, N, n0, k0, st + 2 * TILEB, tid);
      if (SPLIT) issue4(Bm, sB, N, n0, Kh + k0, st + 3 * TILEB, tid);
      cpa_commit();
      cpa_wait<1>();
    } else {
      cpa_wait<0>();
    }
    __syncthreads();

    uint32_t stg = base + (uint32_t)(s * STAGEB);
    const int npass = SPLIT ? 3 : 1;
#pragma unroll 1
    for (int ps = 0; ps < npass; ps++) {
      uint32_t aT = stg + ((ps == 1) ? TILEB : 0);
      uint32_t bT = stg + 2 * TILEB + ((ps == 2) ? TILEB : 0);
#pragma unroll
      for (int ks = 0; ks < 2; ks++) {
        uint32_t afr[4][4];
#pragma unroll
        for (int mi = 0; mi < 4; mi++)
          ldm4(afr[mi], aT + (aRow + mi * 16) * ROWB + ks * 32 + aCol);
        uint32_t bfr[8][2];
#pragma unroll
        for (int nb = 0; nb < 4; nb++) {
          uint32_t t[4];
          ldm4(t, bT + (bRow + nb * 16) * ROWB + ks * 32 + bCol);
          bfr[2 * nb][0] = t[0];
          bfr[2 * nb][1] = t[1];
          bfr[2 * nb + 1][0] = t[2];
          bfr[2 * nb + 1][1] = t[3];
        }
#pragma unroll
        for (int mi = 0; mi < 4; mi++)
#pragma unroll
          for (int ni = 0; ni < 8; ni++)
            mma16816(acc[mi][ni], afr[mi], bfr[ni]);
      }
    }
    __syncthreads();
  }

  const int rr = lane >> 2, cc = (lane & 3) * 2;
#pragma unroll
  for (int mi = 0; mi < 4; mi++) {
#pragma unroll
    for (int ni = 0; ni < 8; ni++) {
      int rb = m0 + wm * 64 + mi * 16 + rr;
      int cb = n0 + wn * 64 + ni * 8 + cc;
      if (rb < M) {
        if (cb < N)     p.store(z, rb, cb,     acc[mi][ni][0]);
        if (cb + 1 < N) p.store(z, rb, cb + 1, acc[mi][ni][1]);
      }
      if (rb + 8 < M) {
        if (cb < N)     p.store(z, rb + 8, cb,     acc[mi][ni][2]);
        if (cb + 1 < N) p.store(z, rb + 8, cb + 1, acc[mi][ni][3]);
      }
    }
  }
}

// ----------------------------- GEMM problem defs ----------------------------

struct WeffP {
  int M, N, nch, Kh, sA, sB;
  const __nv_bfloat16 *wpT2, *Wt2;
  __nv_bfloat16 *WQX2, *WKV2;
  __device__ int kbase(int) const { return 0; }
  __device__ const __nv_bfloat16* Aptr(int z) const {
    int ti = z >> 5, t = z & 3;
    return wpT2 + (size_t)(ti * 4 + t) * 512 * 1024;
  }
  __device__ const __nv_bfloat16* Bptr(int z) const {
    int ti = z >> 5, n = (z & 31) >> 2;
    return Wt2 + (size_t)(ti * 8 + n) * 512 * 1024;
  }
  __device__ void store(int z, int r, int c, float v) const {
    int ti = z >> 5, n = (z & 31) >> 2, t = z & 3;
    size_t row = (size_t)n * 512 + r;
    __nv_bfloat16* dst = (ti == 0) ? WQX2 : (WKV2 + (size_t)(ti - 1) * 4096 * 4096);
    st2(dst, row * 4096 + t * 512 + c, 2048, v);
  }
};

// PoolQ + PoolX merged: B rows [0,4096) = Weff-Q, [4096,4608) = WXe
struct PoolQXP {
  int M, N, nch, Kh, sA, sB;
  const __nv_bfloat16 *Xg2, *WQX2;
  const float* bias;
  float* PQ;
  float* PX;
  __nv_bfloat16* PQ2;
  __device__ int kbase(int) const { return 0; }
  __device__ const __nv_bfloat16* Aptr(int) const { return Xg2; }
  __device__ const __nv_bfloat16* Bptr(int) const { return WQX2; }
  __device__ void store(int, int r, int c, float v) const {
    int b = r / NB_, o = r % NB_;
    if (c < 4096) {
      v += bias[c];
      int n = c >> 9, d = c & 511;
      PQ[((size_t)(b * 8 + n) * LP_ + 1 + o) * 512 + d] = v;
      st2(PQ2, ((size_t)(b * 8 + n) * LP_ + 1 + o) * 1024 + d, 512, v);
    } else {
      PX[((size_t)b * LP_ + 1 + o) * 512 + (c - 4096)] = v;
    }
  }
};

struct PoolKP {
  int M, N, nch, Kh, sA, sB;
  const __nv_bfloat16 *Xg2, *W2;
  const float* bias;
  float* PK;
  __device__ int kbase(int) const { return 0; }
  __device__ const __nv_bfloat16* Aptr(int) const { return Xg2; }
  __device__ const __nv_bfloat16* Bptr(int) const { return W2; }
  __device__ void store(int, int r, int c, float v) const {
    int b = r / NB_, o = r % NB_;
    v += bias[c];
    int n = c >> 9, d = c & 511;
    PK[((size_t)(b * 8 + n) * LP_ + 1 + o) * 512 + d] = v;
  }
};

struct PoolVP {
  int M, N, nch, Kh, sA, sB;
  const __nv_bfloat16 *Xg2, *W2;
  const float* bias;
  __nv_bfloat16* PVt2;
  __device__ int kbase(int) const { return 0; }
  __device__ const __nv_bfloat16* Aptr(int) const { return Xg2; }
  __device__ const __nv_bfloat16* Bptr(int) const { return W2; }
  __device__ void store(int, int r, int c, float v) const {
    int b = r / NB_, o = r % NB_;
    v += bias[c];
    int n = c >> 9, d = c & 511;
    st2(PVt2, ((size_t)(b * 8 + n) * 512 + d) * 3200 + 1 + o, 1600, v);
  }
};

struct LogitsP {
  int M, N, nch, Kh, sA, sB;
  const __nv_bfloat16 *PQ2, *K22;
  float* lg;
  __device__ int kbase(int) const { return 0; }
  __device__ const __nv_bfloat16* Aptr(int z) const {
    return PQ2 + (size_t)z * LP_ * 1024;
  }
  __device__ const __nv_bfloat16* Bptr(int z) const {
    return K22 + (size_t)z * LP_ * 1024;
  }
  __device__ void store(int z, int r, int c, float v) const {
    lg[(size_t)z * LP_ * LGLD_ + (size_t)r * LGLD_ + c] = v;
  }
};

struct AVP {
  int M, N, nch, Kh, sA, sB;
  const __nv_bfloat16 *at2, *PVt2;
  const float* PQ;
  __nv_bfloat16* st2b;
  __device__ int kbase(int) const { return 0; }
  __device__ const __nv_bfloat16* Aptr(int z) const {
    return at2 + (size_t)z * LP_ * 3200;
  }
  __device__ const __nv_bfloat16* Bptr(int z) const {
    return PVt2 + (size_t)z * 512 * 3200;
  }
  __device__ void store(int z, int r, int c, float v) const {
    float pq = PQ[(size_t)z * LP_ * 512 + (size_t)r * 512 + c];
    v += (r > 0 ? 2.f : 1.f) * pq;
    int b = z >> 3, n = z & 7;
    st2(st2b, ((size_t)b * LP_ + r) * 8192 + n * 512 + c, 4096, v);
  }
};

// Final with split-K=2: z selects K half; partials into yp[z].
struct FinalP {
  int M, N, nch, Kh, sA, sB;
  const __nv_bfloat16 *st2b, *Wd2;
  float* yp;
  __device__ int kbase(int z) const { return z * 2048; }
  __device__ const __nv_bfloat16* Aptr(int) const { return st2b; }
  __device__ const __nv_bfloat16* Bptr(int) const { return Wd2; }
  __device__ void store(int z, int r, int c, float v) const {
    yp[(size_t)z * B_ * LP_ * 512 + (size_t)r * 512 + c] = v;
  }
};

// ------------------------------ helper kernels ------------------------------

__global__ void k_wpT2(const float* wpq, const float* wpk, const float* wpv,
                       __nv_bfloat16* wpT2) {
  size_t idx = (size_t)blockIdx.x * blockDim.x + threadIdx.x;
  if (idx >= (size_t)3 * 512 * 512 * 4) return;
  int ti = (int)(idx / (512 * 512 * 4));
  int r = (int)(idx % (512 * 512 * 4));
  int c = r / 2048;
  int d = (r % 2048) >> 2;
  int t = r & 3;
  const float* wp = (ti == 0) ? wpq : ((ti == 1) ? wpk : wpv);
  st2(wpT2, ((size_t)(ti * 4 + t) * 512 + c) * 1024 + d, 512, wp[r]);
}

__global__ void k_wt2(const float* Wq, const float* Wk, const float* Wv,
                      __nv_bfloat16* Wt2) {
  size_t idx = (size_t)blockIdx.x * blockDim.x + threadIdx.x;
  if (idx >= (size_t)3 * 8 * 512 * 512) return;
  int d = (int)(idx & 511);
  int m = (int)((idx >> 9) & 511);
  int n = (int)((idx >> 18) & 7);
  int ti = (int)(idx >> 21);
  const float* W = (ti == 0) ? Wq : ((ti == 1) ? Wk : Wv);
  float v = W[(size_t)(n * 512 + d) * 512 + m];
  st2(Wt2, ((size_t)(ti * 8 + n) * 512 + m) * 1024 + d, 512, v);
}

// WXe rows appended to WQX2 at rows 4096..4607
__global__ void k_wxe2(const float* wpx, __nv_bfloat16* WQX2) {
  size_t idx = (size_t)blockIdx.x * blockDim.x + threadIdx.x;
  if (idx >= (size_t)512 * 2048) return;
  int c = (int)(idx >> 11);
  int col = (int)(idx & 2047);
  int t = col >> 9, m = col & 511;
  float v = wpx[(size_t)c * 2048 + m * 4 + t];
  st2(WQX2, (size_t)(4096 + c) * 4096 + col, 2048, v);
}

__global__ void k_wd2(const float* Wd, __nv_bfloat16* Wd2) {
  size_t idx = (size_t)blockIdx.x * blockDim.x + threadIdx.x;
  if (idx >= (size_t)512 * 4096) return;
  int c = (int)(idx >> 12), k = (int)(idx & 4095);
  st2(Wd2, (size_t)c * 8192 + k, 4096, Wd[idx]);
}

__global__ void k_bpool(const float* wpq, const float* wpk, const float* wpv,
                        const float* bq, const float* bk, const float* bv,
                        float* bpool) {
  int j = blockIdx.x * blockDim.x + threadIdx.x;
  if (j >= 3 * 4096) return;
  int ti = j / 4096, h = j % 4096, n = h >> 9, c = h & 511;
  const float* wp = (ti == 0) ? wpq : ((ti == 1) ? wpk : wpv);
  const float* b = (ti == 0) ? bq : ((ti == 1) ? bk : bv);
  float s = 0.f;
  for (int d = 0; d < 512; d++) {
    float bb = b[n * 512 + d];
    const float* w = wp + (size_t)c * 2048 + d * 4;
    s += (w[0] + w[1] + w[2] + w[3]) * bb;
  }
  bpool[j] = s;
}

__global__ void k_gather2(const float* x, __nv_bfloat16* Xg2) {
  size_t idx = (size_t)blockIdx.x * blockDim.x + threadIdx.x;
  if (idx >= (size_t)3136 * 2048) return;
  int r = (int)(idx >> 11);
  int col = (int)(idx & 2047);
  int t = col >> 9, m = col & 511;
  int b = r / NB_, o = r % NB_;
  int t2 = o / 196, hh = (o / 14) % 14, ww = o % 14;
  int kh = t >> 1, kw = t & 1;
  int row = 1 + (t2 * 28 + 2 * hh + kh) * 28 + 2 * ww + kw;
  float v = x[((size_t)b * L_ + row) * 512 + m];
  st2(Xg2, (size_t)r * 4096 + col, 2048, v);
}

__global__ void k_padpv(__nv_bfloat16* PVt2) {
  int idx = blockIdx.x * blockDim.x + threadIdx.x;
  if (idx >= 16 * 512 * 31) return;
  int j = idx % 31;
  int rc = idx / 31;
  int k = LP_ + j;
  size_t b = (size_t)rc * 3200;
  PVt2[b + k] = __float2bfloat16(0.f);
  PVt2[b + 1600 + k] = __float2bfloat16(0.f);
}

__global__ void k_cls(const float* x, const float* Wq, const float* bq,
                      const float* Wk, const float* bk, const float* Wv,
                      const float* bv, float* PQ, float* PK, float* PX,
                      __nv_bfloat16* PQ2, __nv_bfloat16* PVt2) {
  int idx = blockIdx.x * blockDim.x + threadIdx.x;
  if (idx < 2 * 12288) {
    int b = idx / 12288, j = idx % 12288, ti = j / 4096, jj = j & 4095;
    const float* W = (ti == 0) ? Wq : ((ti == 1) ? Wk : Wv);
    const float* bias = (ti == 0) ? bq : ((ti == 1) ? bk : bv);
    const float* xr = x + (size_t)b * L_ * 512;
    const float* wr = W + (size_t)jj * 512;
    float s = bias[jj];
    for (int m = 0; m < 512; m++) s += xr[m] * wr[m];
    int n = jj >> 9, c = jj & 511;
    int zz = b * 8 + n;
    if (ti == 0) {
      PQ[(size_t)zz * LP_ * 512 + c] = s;
      st2(PQ2, (size_t)zz * LP_ * 1024 + c, 512, s);
    } else if (ti == 1) {
      PK[(size_t)zz * LP_ * 512 + c] = s;
    } else {
      st2(PVt2, ((size_t)zz * 512 + c) * 3200 + 0, 1600, s);
    }
  } else if (idx < 2 * 12288 + 2 * 512) {
    int k = idx - 2 * 12288;
    int b = k >> 9, c = k & 511;
    PX[(size_t)b * LP_ * 512 + c] = x[(size_t)b * L_ * 512 + c];
  }
}

__device__ __forceinline__ float sincos_val(int pos, int c, int dim) {
  int half = dim / 2;
  bool is_cos = c >= half;
  int i = is_cos ? c - half : c;
  float omega = powf(10000.f, -((float)i) / (float)half);
  float ang = (float)pos * omega;
  return is_cos ? cosf(ang) : sinf(ang);
}

__global__ void k_emb(float* emb) {
  size_t idx = (size_t)blockIdx.x * blockDim.x + threadIdx.x;
  if (idx >= SZ_EMB) return;
  int k = (int)(idx >> 9);
  int c = (int)(idx & 511);
  int t2 = k / 196, h2 = (k / 14) % 14, w2 = k % 14;
  float v;
  if (c < 170) v = sincos_val(t2, c, 170);
  else if (c < 340) v = sincos_val(h2, c - 170, 170);
  else v = sincos_val(w2, c - 340, 172);
  emb[idx] = v;
}

__global__ void k_k2(const float* PK, const float* emb, __nv_bfloat16* K22) {
  size_t idx = (size_t)blockIdx.x * blockDim.x + threadIdx.x;
  if (idx >= (size_t)16 * LP_ * 512) return;
  size_t rem = idx % ((size_t)LP_ * 512);
  int k = (int)(rem >> 9);
  int c = (int)(rem & 511);
  size_t z = idx / ((size_t)LP_ * 512);
  float v = SCALE_ * PK[idx];
  if (k > 0) v += emb[(size_t)(k - 1) * 512 + c];
  st2(K22, (z * LP_ + k) * 1024 + c, 512, v);
}

__global__ void k_row0(const float* PQ, const float* PK, float* lg) {
  int z = blockIdx.y;
  int kq = blockIdx.x * 8 + (threadIdx.x >> 5);
  int lane = threadIdx.x & 31;
  if (kq >= LP_) return;
  const float* q = PQ + (size_t)z * LP_ * 512;
  const float* kr = PK + (size_t)z * LP_ * 512 + (size_t)kq * 512;
  float s = 0.f;
  for (int i = lane; i < 512; i += 32) s += q[i] * kr[i];
#pragma unroll
  for (int o = 16; o; o >>= 1) s += __shfl_xor_sync(0xFFFFFFFFu, s, o);
  if (lane == 0) lg[(size_t)z * LP_ * LGLD_ + kq] = s * SCALE_;
}

__global__ void k_softmax(float* lg, __nv_bfloat16* at2) {
  int z = blockIdx.y, q = blockIdx.x;
  float* row = lg + ((size_t)z * LP_ + q) * LGLD_;
  __nv_bfloat16* arow = at2 + ((size_t)z * LP_ + q) * 3200;
  int tid = threadIdx.x;
  __shared__ float red[256];
  float mx = -1e30f;
  for (int i = tid; i < LP_; i += 256) mx = fmaxf(mx, row[i]);
  red[tid] = mx;
  __syncthreads();
  for (int s = 128; s > 0; s >>= 1) {
    if (tid < s) red[tid] = fmaxf(red[tid], red[tid + s]);
    __syncthreads();
  }
  mx = red[0];
  __syncthreads();
  float sum = 0.f;
  for (int i = tid; i < LP_; i += 256) {
    float e = expf(row[i] - mx);
    row[i] = e;
    sum += e;
  }
  red[tid] = sum;
  __syncthreads();
  for (int s = 128; s > 0; s >>= 1) {
    if (tid < s) red[tid] += red[tid + s];
    __syncthreads();
  }
  float inv = 1.f / red[0];
  for (int i = tid; i < LPP_; i += 256) {
    float v = (i < LP_) ? row[i] * inv : 0.f;
    __nv_bfloat16 h = __float2bfloat16(v);
    arow[i] = h;
    arow[1600 + i] = __float2bfloat16(v - __bfloat162float(h));
  }
}

// LN over yp0+yp1+bd+PX -> y
__global__ void k_ln(const float* yp, const float* bd, const float* PX,
                     const float* gamma, const float* beta, float* y) {
  int row = blockIdx.x;
  const float* y0 = yp + (size_t)row * 512;
  const float* y1 = yp + (size_t)B_ * LP_ * 512 + (size_t)row * 512;
  const float* px = PX + (size_t)row * 512;
  float* yr = y + (size_t)row * 512;
  int tid = threadIdx.x;
  float v0 = y0[tid] + y1[tid] + bd[tid] + px[tid];
  float v1 = y0[tid + 256] + y1[tid + 256] + bd[tid + 256] + px[tid + 256];
  __shared__ float red[256];
  red[tid] = v0 + v1;
  __syncthreads();
  for (int s = 128; s > 0; s >>= 1) {
    if (tid < s) red[tid] += red[tid + s];
    __syncthreads();
  }
  float mu = red[0] * (1.f / 512.f);
  __syncthreads();
  float d0 = v0 - mu, d1 = v1 - mu;
  red[tid] = d0 * d0 + d1 * d1;
  __syncthreads();
  for (int s = 128; s > 0; s >>= 1) {
    if (tid < s) red[tid] += red[tid + s];
    __syncthreads();
  }
  float inv = rsqrtf(red[0] * (1.f / 512.f) + 1e-5f);
  yr[tid] = d0 * inv * gamma[tid] + beta[tid];
  yr[tid + 256] = d1 * inv * gamma[tid + 256] + beta[tid + 256];
}

// --------------------------------- launcher ---------------------------------

extern "C" void kernel_launch(void* const* d_in, const int* in_sizes, int n_in,
                              void* d_out, int out_size) {
  (void)in_sizes; (void)n_in; (void)out_size;
  const float* x   = (const float*)d_in[0];
  const float* Wq  = (const float*)d_in[1];
  const float* bq  = (const float*)d_in[2];
  const float* Wk  = (const float*)d_in[3];
  const float* bk  = (const float*)d_in[4];
  const float* Wv  = (const float*)d_in[5];
  const float* bv  = (const float*)d_in[6];
  const float* wpq = (const float*)d_in[7];
  const float* wpk = (const float*)d_in[8];
  const float* wpv = (const float*)d_in[9];
  const float* wpx = (const float*)d_in[10];
  const float* Wd  = (const float*)d_in[11];
  const float* bd  = (const float*)d_in[12];
  const float* gamma = (const float*)d_in[13];
  const float* beta  = (const float*)d_in[14];
  float* y = (float*)d_out;

  float* S = nullptr;
  cudaGetSymbolAddress((void**)&S, g_scratch);
  __nv_bfloat16* Bf = nullptr;
  cudaGetSymbolAddress((void**)&Bf, g_bf);

  float* PQ    = S + OF_PQ;
  float* PK    = S + OF_PK;
  float* PX    = S + OF_PX;
  float* emb   = S + OF_EMB;
  float* bpool = S + OF_BP;
  float* lg    = S + OF_LG;
  float* yp    = S + OF_YP;

  __nv_bfloat16* wpT2 = Bf + OB_WPT2;
  __nv_bfloat16* Wt2  = Bf + OB_WT2;
  __nv_bfloat16* Wd2  = Bf + OB_WD2;
  __nv_bfloat16* WQX2 = Bf + OB_WQX2;
  __nv_bfloat16* WKV2 = Bf + OB_WKV2;
  __nv_bfloat16* Xg2  = Bf + OB_XG2;
  __nv_bfloat16* PQ2  = Bf + OB_PQ2;
  __nv_bfloat16* K22  = Bf + OB_K22;
  __nv_bfloat16* PVt2 = Bf + OB_PVT2;
  __nv_bfloat16* at2  = Bf + OB_AT2;
  __nv_bfloat16* st2b = Bf + OB_ST2;

  cudaFuncSetAttribute(gemm_ca<WeffP, true>,
                       cudaFuncAttributeMaxDynamicSharedMemorySize, SMEMB);
  cudaFuncSetAttribute(gemm_ca<PoolQXP, true>,
                       cudaFuncAttributeMaxDynamicSharedMemorySize, SMEMB);
  cudaFuncSetAttribute(gemm_ca<PoolKP, false>,
                       cudaFuncAttributeMaxDynamicSharedMemorySize, SMEMB);
  cudaFuncSetAttribute(gemm_ca<PoolVP, true>,
                       cudaFuncAttributeMaxDynamicSharedMemorySize, SMEMB);
  cudaFuncSetAttribute(gemm_ca<LogitsP, true>,
                       cudaFuncAttributeMaxDynamicSharedMemorySize, SMEMB);
  cudaFuncSetAttribute(gemm_ca<AVP, true>,
                       cudaFuncAttributeMaxDynamicSharedMemorySize, SMEMB);
  cudaFuncSetAttribute(gemm_ca<FinalP, true>,
                       cudaFuncAttributeMaxDynamicSharedMemorySize, SMEMB);

  // converters
  k_wpT2<<<(int)((3u * 512 * 512 * 4 + 255) / 256), 256>>>(wpq, wpk, wpv, wpT2);
  k_wt2<<<(int)((3u * 8 * 512 * 512 + 255) / 256), 256>>>(Wq, Wk, Wv, Wt2);
  k_wxe2<<<(512 * 2048 + 255) / 256, 256>>>(wpx, WQX2);
  k_wd2<<<(512 * 4096 + 255) / 256, 256>>>(Wd, Wd2);
  k_bpool<<<(3 * 4096 + 255) / 256, 256>>>(wpq, wpk, wpv, bq, bk, bv, bpool);
  k_gather2<<<(int)((3136u * 2048 + 255) / 256), 256>>>(x, Xg2);
  k_padpv<<<(16 * 512 * 31 + 255) / 256, 256>>>(PVt2);

  {
    WeffP p;
    p.M = 512; p.N = 512; p.nch = 16; p.Kh = 512; p.sA = 1024; p.sB = 1024;
    p.wpT2 = wpT2; p.Wt2 = Wt2; p.WQX2 = WQX2; p.WKV2 = WKV2;
    gemm_ca<WeffP, true><<<dim3(4, 4, 96), 128, SMEMB>>>(p);
  }

  {
    PoolQXP p;
    p.M = 3136; p.N = 4608; p.nch = 64; p.Kh = 2048; p.sA = 4096; p.sB = 4096;
    p.Xg2 = Xg2; p.WQX2 = WQX2; p.bias = bpool; p.PQ = PQ; p.PX = PX;
    p.PQ2 = PQ2;
    gemm_ca<PoolQXP, true><<<dim3(36, 25, 1), 128, SMEMB>>>(p);
  }
  {
    PoolKP p;
    p.M = 3136; p.N = 4096; p.nch = 64; p.Kh = 2048; p.sA = 4096; p.sB = 4096;
    p.Xg2 = Xg2; p.W2 = WKV2; p.bias = bpool + 4096; p.PK = PK;
    gemm_ca<PoolKP, false><<<dim3(32, 25, 1), 128, SMEMB>>>(p);
  }
  {
    PoolVP p;
    p.M = 3136; p.N = 4096; p.nch = 64; p.Kh = 2048; p.sA = 4096; p.sB = 4096;
    p.Xg2 = Xg2; p.W2 = WKV2 + (size_t)4096 * 4096; p.bias = bpool + 8192;
    p.PVt2 = PVt2;
    gemm_ca<PoolVP, true><<<dim3(32, 25, 1), 128, SMEMB>>>(p);
  }

  k_cls<<<(2 * 12288 + 2 * 512 + 255) / 256, 256>>>(x, Wq, bq, Wk, bk, Wv, bv,
                                                    PQ, PK, PX, PQ2, PVt2);
  k_emb<<<(int)((SZ_EMB + 255) / 256), 256>>>(emb);
  k_k2<<<(int)(((size_t)16 * LP_ * 512 + 255) / 256), 256>>>(PK, emb, K22);

  {
    LogitsP p;
    p.M = LP_; p.N = LP_; p.nch = 16; p.Kh = 512; p.sA = 1024; p.sB = 1024;
    p.PQ2 = PQ2; p.K22 = K22; p.lg = lg;
    gemm_ca<LogitsP, true><<<dim3(13, 13, 16), 128, SMEMB>>>(p);
  }

  k_row0<<<dim3((LP_ + 7) / 8, 16), 256>>>(PQ, PK, lg);
  k_softmax<<<dim3(LP_, 16), 256>>>(lg, at2);

  {
    AVP p;
    p.M = LP_; p.N = 512; p.nch = 50; p.Kh = 1600; p.sA = 3200; p.sB = 3200;
    p.at2 = at2; p.PVt2 = PVt2; p.PQ = PQ; p.st2b = st2b;
    gemm_ca<AVP, true><<<dim3(4, 13, 16), 128, SMEMB>>>(p);
  }

  {
    FinalP p;
    p.M = B_ * LP_; p.N = 512; p.nch = 64; p.Kh = 4096; p.sA = 8192;
    p.sB = 8192;
    p.st2b = st2b; p.Wd2 = Wd2; p.yp = yp;
    gemm_ca<FinalP, true><<<dim3(4, 25, 2), 128, SMEMB>>>(p);
  }

  k_ln<<<B_ * LP_, 256>>>(yp, bd, PX, gamma, beta, y);
}

// round 13
// speedup vs baseline: 1.4880x; 1.2302x over previous
#include <cuda_runtime.h>
#include <cuda_bf16.h>
#include <cuda_fp16.h>
#include <math.h>
#include <stdint.h>
#include <stddef.h>

// ---------------------------------------------------------------------------
// MultiHeadPooledAttention — mixed-precision HMMA GEMMs:
//   bf16 hi/lo 3-pass: Weff, PoolQX, Logits, Final (sqrt(K)-amplified chain)
//   fp16 single-pass:  PoolK, PoolV, attn·V       (damped/convex chain)
// cp.async 2-stage pipeline, 3 passes from resident SMEM, 64x64 warp tiles.
// ---------------------------------------------------------------------------

namespace {
constexpr int B_  = 2;
constexpr int L_  = 6273;   // 1 + 8*28*28
constexpr int NH_ = 8;
constexpr int LP_ = 1569;   // 1 + 8*14*14
constexpr int LPP_ = 1600;
constexpr int NB_ = 1568;
constexpr int LGLD_ = 1600;
constexpr float SCALE_ = 0.04419417382415922f;  // 512^-0.5

// fp32 scratch
constexpr size_t SZ_PQ  = (size_t)16 * LP_ * 512;
constexpr size_t SZ_PK  = (size_t)16 * LP_ * 512;
constexpr size_t SZ_PX  = (size_t)B_ * LP_ * 512;
constexpr size_t SZ_EMB = (size_t)NB_ * 512;
constexpr size_t SZ_BP  = (size_t)3 * 4096;
constexpr size_t SZ_LG  = (size_t)16 * LP_ * LGLD_;
constexpr size_t SZ_YP  = (size_t)2 * B_ * LP_ * 512;

constexpr size_t OF_PQ  = 0;
constexpr size_t OF_PK  = OF_PQ + SZ_PQ;
constexpr size_t OF_PX  = OF_PK + SZ_PK;
constexpr size_t OF_EMB = OF_PX + SZ_PX;
constexpr size_t OF_BP  = OF_EMB + SZ_EMB;
constexpr size_t OF_LG  = OF_BP + SZ_BP;
constexpr size_t OF_YP  = OF_LG + SZ_LG;
constexpr size_t SZ_F32 = OF_YP + SZ_YP;

// bf16 hi/lo buffers (planar: hi at [0,Kh), lo at [Kh,2Kh), row stride 2Kh)
constexpr size_t SZB_WPT2  = (size_t)12 * 512 * 1024;
constexpr size_t SZB_WT2   = (size_t)24 * 512 * 1024;
constexpr size_t SZB_WD2   = (size_t)512 * 8192;
constexpr size_t SZB_WQX2  = (size_t)4608 * 4096;   // Weff-Q (4096) + WXe (512)
constexpr size_t SZB_XG2   = (size_t)3136 * 4096;
constexpr size_t SZB_PQ2   = (size_t)16 * LP_ * 1024;
constexpr size_t SZB_K22   = (size_t)16 * LP_ * 1024;
constexpr size_t SZB_ST2   = (size_t)B_ * LP_ * 8192;

constexpr size_t OB_WPT2  = 0;
constexpr size_t OB_WT2   = OB_WPT2 + SZB_WPT2;
constexpr size_t OB_WD2   = OB_WT2 + SZB_WT2;
constexpr size_t OB_WQX2  = OB_WD2 + SZB_WD2;
constexpr size_t OB_XG2   = OB_WQX2 + SZB_WQX2;
constexpr size_t OB_PQ2   = OB_XG2 + SZB_XG2;
constexpr size_t OB_K22   = OB_PQ2 + SZB_PQ2;
constexpr size_t OB_ST2   = OB_K22 + SZB_K22;
constexpr size_t SZ_BF    = OB_ST2 + SZB_ST2;

// fp16 single-plane buffers
constexpr size_t SZH_WK1  = (size_t)4096 * 2048;
constexpr size_t SZH_WV1  = (size_t)4096 * 2048;
constexpr size_t SZH_XG1  = (size_t)3136 * 2048;
constexpr size_t SZH_PVT1 = (size_t)16 * 512 * 1600;
constexpr size_t SZH_AT1  = (size_t)16 * LP_ * 1600;

constexpr size_t OH_WK1  = 0;
constexpr size_t OH_WV1  = OH_WK1 + SZH_WK1;
constexpr size_t OH_XG1  = OH_WV1 + SZH_WV1;
constexpr size_t OH_PVT1 = OH_XG1 + SZH_XG1;
constexpr size_t OH_AT1  = OH_PVT1 + SZH_PVT1;
constexpr size_t SZ_HF   = OH_AT1 + SZH_AT1;
}  // namespace

__device__ float g_scratch[SZ_F32];
__device__ __align__(16) __nv_bfloat16 g_bf[SZ_BF];
__device__ __align__(16) __half g_hf[SZ_HF];

// ------------------------------- PTX helpers -------------------------------

__device__ __forceinline__ uint32_t smem_u32(const void* p) {
  uint32_t a;
  asm("{ .reg .u64 t; cvta.to.shared.u64 t, %1; cvt.u32.u64 %0, t; }"
      : "=r"(a) : "l"(p));
  return a;
}

__device__ __forceinline__ void ldm4(uint32_t* d, uint32_t addr) {
  asm volatile("ldmatrix.sync.aligned.m8n8.x4.shared.b16 {%0,%1,%2,%3}, [%4];"
               : "=r"(d[0]), "=r"(d[1]), "=r"(d[2]), "=r"(d[3]) : "r"(addr));
}

__device__ __forceinline__ void mma_bf(float* c, const uint32_t* a,
                                       const uint32_t* b) {
  asm volatile(
      "mma.sync.aligned.m16n8k16.row.col.f32.bf16.bf16.f32 "
      "{%0,%1,%2,%3}, {%4,%5,%6,%7}, {%8,%9}, {%0,%1,%2,%3};"
      : "+f"(c[0]), "+f"(c[1]), "+f"(c[2]), "+f"(c[3])
      : "r"(a[0]), "r"(a[1]), "r"(a[2]), "r"(a[3]), "r"(b[0]), "r"(b[1]));
}
__device__ __forceinline__ void mma_fp(float* c, const uint32_t* a,
                                       const uint32_t* b) {
  asm volatile(
      "mma.sync.aligned.m16n8k16.row.col.f32.f16.f16.f32 "
      "{%0,%1,%2,%3}, {%4,%5,%6,%7}, {%8,%9}, {%0,%1,%2,%3};"
      : "+f"(c[0]), "+f"(c[1]), "+f"(c[2]), "+f"(c[3])
      : "r"(a[0]), "r"(a[1]), "r"(a[2]), "r"(a[3]), "r"(b[0]), "r"(b[1]));
}

__device__ __forceinline__ void cpa16(uint32_t dst, const void* src, bool ok) {
  int sz = ok ? 16 : 0;
  asm volatile("cp.async.cg.shared.global [%0], [%1], 16, %2;"
               :: "r"(dst), "l"(src), "r"(sz) : "memory");
}
__device__ __forceinline__ void cpa_commit() {
  asm volatile("cp.async.commit_group;" ::: "memory");
}
template <int N>
__device__ __forceinline__ void cpa_wait() {
  asm volatile("cp.async.wait_group %0;" :: "n"(N) : "memory");
}

__device__ __forceinline__ void st2(__nv_bfloat16* p, size_t i, size_t kh,
                                    float v) {
  __nv_bfloat16 h = __float2bfloat16(v);
  p[i] = h;
  p[i + kh] = __float2bfloat16(v - __bfloat162float(h));
}

// --------------------------- cp.async GEMM kernel ----------------------------

constexpr int ROWB = 80;
constexpr int TILEB = 128 * ROWB;
constexpr int STAGEB = 4 * TILEB;
constexpr int SMEMB = 2 * STAGEB;  // 81920

__device__ __forceinline__ void issue4(const uint16_t* S, int stride, int rmax,
                                       int r0, int kofs, uint32_t dstB,
                                       int tid) {
#pragma unroll
  for (int i = 0; i < 4; i++) {
    int idx = tid + 128 * i;
    int row = idx >> 2, q = idx & 3;
    int gr = r0 + row;
    bool ok = gr < rmax;
    const uint16_t* src = S + (size_t)(ok ? gr : 0) * stride + kofs + q * 8;
    cpa16(dstB + (uint32_t)(row * ROWB + q * 16), src, ok);
  }
}

template <typename P, bool SPLIT, bool FP16>
__global__ __launch_bounds__(128) void gemm_ca(P p) {
  extern __shared__ __align__(16) char sm[];
  uint32_t base = smem_u32(sm);

  const int tid = threadIdx.x;
  const int wid = tid >> 5, lane = tid & 31;
  const int wm = wid >> 1, wn = wid & 1;
  const int lj = lane >> 3, lr = lane & 7;

  const int z = blockIdx.z;
  const uint16_t* A = p.Aptr(z);
  const uint16_t* Bm = p.Bptr(z);
  const int M = p.M, N = p.N;
  const int m0 = blockIdx.y * 128, n0 = blockIdx.x * 128;
  const int nch = p.nch, Kh = p.Kh, sA = p.sA, sB = p.sB;
  const int kb = p.kbase(z);

  float acc[4][8][4];
#pragma unroll
  for (int a = 0; a < 4; a++)
#pragma unroll
    for (int b = 0; b < 8; b++)
#pragma unroll
      for (int c = 0; c < 4; c++) acc[a][b][c] = 0.f;

  const uint32_t aRow = (uint32_t)(wm * 64 + (lj & 1) * 8 + lr);
  const uint32_t aCol = (uint32_t)((lj >> 1) * 16);
  const uint32_t bRow = (uint32_t)(wn * 64 + (lj >> 1) * 8 + lr);
  const uint32_t bCol = (uint32_t)((lj & 1) * 16);

  {
    uint32_t st = base;
    issue4(A, sA, M, m0, kb, st, tid);
    if (SPLIT) issue4(A, sA, M, m0, Kh + kb, st + TILEB, tid);
    issue4(Bm, sB, N, n0, kb, st + 2 * TILEB, tid);
    if (SPLIT) issue4(Bm, sB, N, n0, Kh + kb, st + 3 * TILEB, tid);
    cpa_commit();
  }

  for (int ch = 0; ch < nch; ++ch) {
    int s = ch & 1;
    if (ch + 1 < nch) {
      int k0 = kb + (ch + 1) * 32;
      uint32_t st = base + (uint32_t)((1 - s) * STAGEB);
      issue4(A, sA, M, m0, k0, st, tid);
      if (SPLIT) issue4(A, sA, M, m0, Kh + k0, st + TILEB, tid);
      issue4(Bm, sB, N, n0, k0, st + 2 * TILEB, tid);
      if (SPLIT) issue4(Bm, sB, N, n0, Kh + k0, st + 3 * TILEB, tid);
      cpa_commit();
      cpa_wait<1>();
    } else {
      cpa_wait<0>();
    }
    __syncthreads();

    uint32_t stg = base + (uint32_t)(s * STAGEB);
    const int npass = SPLIT ? 3 : 1;
#pragma unroll 1
    for (int ps = 0; ps < npass; ps++) {
      uint32_t aT = stg + ((ps == 1) ? TILEB : 0);
      uint32_t bT = stg + 2 * TILEB + ((ps == 2) ? TILEB : 0);
#pragma unroll
      for (int ks = 0; ks < 2; ks++) {
        uint32_t afr[4][4];
#pragma unroll
        for (int mi = 0; mi < 4; mi++)
          ldm4(afr[mi], aT + (aRow + mi * 16) * ROWB + ks * 32 + aCol);
        uint32_t bfr[8][2];
#pragma unroll
        for (int nb = 0; nb < 4; nb++) {
          uint32_t t[4];
          ldm4(t, bT + (bRow + nb * 16) * ROWB + ks * 32 + bCol);
          bfr[2 * nb][0] = t[0];
          bfr[2 * nb][1] = t[1];
          bfr[2 * nb + 1][0] = t[2];
          bfr[2 * nb + 1][1] = t[3];
        }
#pragma unroll
        for (int mi = 0; mi < 4; mi++)
#pragma unroll
          for (int ni = 0; ni < 8; ni++) {
            if (FP16) mma_fp(acc[mi][ni], afr[mi], bfr[ni]);
            else      mma_bf(acc[mi][ni], afr[mi], bfr[ni]);
          }
      }
    }
    __syncthreads();
  }

  const int rr = lane >> 2, cc = (lane & 3) * 2;
#pragma unroll
  for (int mi = 0; mi < 4; mi++) {
#pragma unroll
    for (int ni = 0; ni < 8; ni++) {
      int rb = m0 + wm * 64 + mi * 16 + rr;
      int cb = n0 + wn * 64 + ni * 8 + cc;
      if (rb < M) {
        if (cb < N)     p.store(z, rb, cb,     acc[mi][ni][0]);
        if (cb + 1 < N) p.store(z, rb, cb + 1, acc[mi][ni][1]);
      }
      if (rb + 8 < M) {
        if (cb < N)     p.store(z, rb + 8, cb,     acc[mi][ni][2]);
        if (cb + 1 < N) p.store(z, rb + 8, cb + 1, acc[mi][ni][3]);
      }
    }
  }
}

// ----------------------------- GEMM problem defs ----------------------------

struct WeffP {
  int M, N, nch, Kh, sA, sB;
  const uint16_t *wpT2, *Wt2;
  __nv_bfloat16* WQX2;
  __half *WK1, *WV1;
  __device__ int kbase(int) const { return 0; }
  __device__ const uint16_t* Aptr(int z) const {
    int ti = z >> 5, t = z & 3;
    return wpT2 + (size_t)(ti * 4 + t) * 512 * 1024;
  }
  __device__ const uint16_t* Bptr(int z) const {
    int ti = z >> 5, n = (z & 31) >> 2;
    return Wt2 + (size_t)(ti * 8 + n) * 512 * 1024;
  }
  __device__ void store(int z, int r, int c, float v) const {
    int ti = z >> 5, n = (z & 31) >> 2, t = z & 3;
    size_t idx = ((size_t)n * 512 + r) * 2048 + t * 512 + c;
    if (ti == 0) {
      st2(WQX2, ((size_t)n * 512 + r) * 4096 + t * 512 + c, 2048, v);
    } else if (ti == 1) {
      WK1[idx] = __float2half(v);
    } else {
      WV1[idx] = __float2half(v);
    }
  }
};

// PoolQ + PoolX merged (bf16 3-pass): B rows [0,4096)=Weff-Q, [4096,4608)=WXe
struct PoolQXP {
  int M, N, nch, Kh, sA, sB;
  const uint16_t *Xg2, *WQX2;
  const float* bias;
  float* PQ;
  float* PX;
  __nv_bfloat16* PQ2;
  __device__ int kbase(int) const { return 0; }
  __device__ const uint16_t* Aptr(int) const { return Xg2; }
  __device__ const uint16_t* Bptr(int) const { return WQX2; }
  __device__ void store(int, int r, int c, float v) const {
    int b = r / NB_, o = r % NB_;
    if (c < 4096) {
      v += bias[c];
      int n = c >> 9, d = c & 511;
      PQ[((size_t)(b * 8 + n) * LP_ + 1 + o) * 512 + d] = v;
      st2(PQ2, ((size_t)(b * 8 + n) * LP_ + 1 + o) * 1024 + d, 512, v);
    } else {
      PX[((size_t)b * LP_ + 1 + o) * 512 + (c - 4096)] = v;
    }
  }
};

struct PoolKP {  // fp16 single-pass
  int M, N, nch, Kh, sA, sB;
  const uint16_t *Xg1, *WK1;
  const float* bias;
  float* PK;
  __device__ int kbase(int) const { return 0; }
  __device__ const uint16_t* Aptr(int) const { return Xg1; }
  __device__ const uint16_t* Bptr(int) const { return WK1; }
  __device__ void store(int, int r, int c, float v) const {
    int b = r / NB_, o = r % NB_;
    v += bias[c];
    int n = c >> 9, d = c & 511;
    PK[((size_t)(b * 8 + n) * LP_ + 1 + o) * 512 + d] = v;
  }
};

struct PoolVP {  // fp16 single-pass -> transposed fp16 PVt1
  int M, N, nch, Kh, sA, sB;
  const uint16_t *Xg1, *WV1;
  const float* bias;
  __half* PVt1;
  __device__ int kbase(int) const { return 0; }
  __device__ const uint16_t* Aptr(int) const { return Xg1; }
  __device__ const uint16_t* Bptr(int) const { return WV1; }
  __device__ void store(int, int r, int c, float v) const {
    int b = r / NB_, o = r % NB_;
    v += bias[c];
    int n = c >> 9, d = c & 511;
    PVt1[((size_t)(b * 8 + n) * 512 + d) * 1600 + 1 + o] = __float2half(v);
  }
};

struct LogitsP {
  int M, N, nch, Kh, sA, sB;
  const uint16_t *PQ2, *K22;
  float* lg;
  __device__ int kbase(int) const { return 0; }
  __device__ const uint16_t* Aptr(int z) const {
    return PQ2 + (size_t)z * LP_ * 1024;
  }
  __device__ const uint16_t* Bptr(int z) const {
    return K22 + (size_t)z * LP_ * 1024;
  }
  __device__ void store(int z, int r, int c, float v) const {
    lg[(size_t)z * LP_ * LGLD_ + (size_t)r * LGLD_ + c] = v;
  }
};

struct AVP {  // fp16 single-pass
  int M, N, nch, Kh, sA, sB;
  const uint16_t *at1, *PVt1;
  const float* PQ;
  __nv_bfloat16* st2b;
  __device__ int kbase(int) const { return 0; }
  __device__ const uint16_t* Aptr(int z) const {
    return at1 + (size_t)z * LP_ * 1600;
  }
  __device__ const uint16_t* Bptr(int z) const {
    return PVt1 + (size_t)z * 512 * 1600;
  }
  __device__ void store(int z, int r, int c, float v) const {
    float pq = PQ[(size_t)z * LP_ * 512 + (size_t)r * 512 + c];
    v += (r > 0 ? 2.f : 1.f) * pq;
    int b = z >> 3, n = z & 7;
    st2(st2b, ((size_t)b * LP_ + r) * 8192 + n * 512 + c, 4096, v);
  }
};

struct FinalP {  // bf16 3-pass, split-K=2
  int M, N, nch, Kh, sA, sB;
  const uint16_t *st2b, *Wd2;
  float* yp;
  __device__ int kbase(int z) const { return z * 2048; }
  __device__ const uint16_t* Aptr(int) const { return st2b; }
  __device__ const uint16_t* Bptr(int) const { return Wd2; }
  __device__ void store(int z, int r, int c, float v) const {
    yp[(size_t)z * B_ * LP_ * 512 + (size_t)r * 512 + c] = v;
  }
};

// ------------------------------ helper kernels ------------------------------

__global__ void k_wpT2(const float* wpq, const float* wpk, const float* wpv,
                       __nv_bfloat16* wpT2) {
  size_t idx = (size_t)blockIdx.x * blockDim.x + threadIdx.x;
  if (idx >= (size_t)3 * 512 * 512 * 4) return;
  int ti = (int)(idx / (512 * 512 * 4));
  int r = (int)(idx % (512 * 512 * 4));
  int c = r / 2048;
  int d = (r % 2048) >> 2;
  int t = r & 3;
  const float* wp = (ti == 0) ? wpq : ((ti == 1) ? wpk : wpv);
  st2(wpT2, ((size_t)(ti * 4 + t) * 512 + c) * 1024 + d, 512, wp[r]);
}

__global__ void k_wt2(const float* Wq, const float* Wk, const float* Wv,
                      __nv_bfloat16* Wt2) {
  size_t idx = (size_t)blockIdx.x * blockDim.x + threadIdx.x;
  if (idx >= (size_t)3 * 8 * 512 * 512) return;
  int d = (int)(idx & 511);
  int m = (int)((idx >> 9) & 511);
  int n = (int)((idx >> 18) & 7);
  int ti = (int)(idx >> 21);
  const float* W = (ti == 0) ? Wq : ((ti == 1) ? Wk : Wv);
  float v = W[(size_t)(n * 512 + d) * 512 + m];
  st2(Wt2, ((size_t)(ti * 8 + n) * 512 + m) * 1024 + d, 512, v);
}

__global__ void k_wxe2(const float* wpx, __nv_bfloat16* WQX2) {
  size_t idx = (size_t)blockIdx.x * blockDim.x + threadIdx.x;
  if (idx >= (size_t)512 * 2048) return;
  int c = (int)(idx >> 11);
  int col = (int)(idx & 2047);
  int t = col >> 9, m = col & 511;
  float v = wpx[(size_t)c * 2048 + m * 4 + t];
  st2(WQX2, (size_t)(4096 + c) * 4096 + col, 2048, v);
}

__global__ void k_wd2(const float* Wd, __nv_bfloat16* Wd2) {
  size_t idx = (size_t)blockIdx.x * blockDim.x + threadIdx.x;
  if (idx >= (size_t)512 * 4096) return;
  int c = (int)(idx >> 12), k = (int)(idx & 4095);
  st2(Wd2, (size_t)c * 8192 + k, 4096, Wd[idx]);
}

__global__ void k_bpool(const float* wpq, const float* wpk, const float* wpv,
                        const float* bq, const float* bk, const float* bv,
                        float* bpool) {
  int j = blockIdx.x * blockDim.x + threadIdx.x;
  if (j >= 3 * 4096) return;
  int ti = j / 4096, h = j % 4096, n = h >> 9, c = h & 511;
  const float* wp = (ti == 0) ? wpq : ((ti == 1) ? wpk : wpv);
  const float* b = (ti == 0) ? bq : ((ti == 1) ? bk : bv);
  float s = 0.f;
  for (int d = 0; d < 512; d++) {
    float bb = b[n * 512 + d];
    const float* w = wp + (size_t)c * 2048 + d * 4;
    s += (w[0] + w[1] + w[2] + w[3]) * bb;
  }
  bpool[j] = s;
}

__global__ void k_gather2(const float* x, __nv_bfloat16* Xg2, __half* Xg1) {
  size_t idx = (size_t)blockIdx.x * blockDim.x + threadIdx.x;
  if (idx >= (size_t)3136 * 2048) return;
  int r = (int)(idx >> 11);
  int col = (int)(idx & 2047);
  int t = col >> 9, m = col & 511;
  int b = r / NB_, o = r % NB_;
  int t2 = o / 196, hh = (o / 14) % 14, ww = o % 14;
  int kh = t >> 1, kw = t & 1;
  int row = 1 + (t2 * 28 + 2 * hh + kh) * 28 + 2 * ww + kw;
  float v = x[((size_t)b * L_ + row) * 512 + m];
  st2(Xg2, (size_t)r * 4096 + col, 2048, v);
  Xg1[(size_t)r * 2048 + col] = __float2half(v);
}

__global__ void k_padpv(__half* PVt1) {
  int idx = blockIdx.x * blockDim.x + threadIdx.x;
  if (idx >= 16 * 512 * 31) return;
  int j = idx % 31;
  int rc = idx / 31;
  PVt1[(size_t)rc * 1600 + LP_ + j] = __float2half(0.f);
}

__global__ void k_cls(const float* x, const float* Wq, const float* bq,
                      const float* Wk, const float* bk, const float* Wv,
                      const float* bv, float* PQ, float* PK, float* PX,
                      __nv_bfloat16* PQ2, __half* PVt1) {
  int idx = blockIdx.x * blockDim.x + threadIdx.x;
  if (idx < 2 * 12288) {
    int b = idx / 12288, j = idx % 12288, ti = j / 4096, jj = j & 4095;
    const float* W = (ti == 0) ? Wq : ((ti == 1) ? Wk : Wv);
    const float* bias = (ti == 0) ? bq : ((ti == 1) ? bk : bv);
    const float* xr = x + (size_t)b * L_ * 512;
    const float* wr = W + (size_t)jj * 512;
    float s = bias[jj];
    for (int m = 0; m < 512; m++) s += xr[m] * wr[m];
    int n = jj >> 9, c = jj & 511;
    int zz = b * 8 + n;
    if (ti == 0) {
      PQ[(size_t)zz * LP_ * 512 + c] = s;
      st2(PQ2, (size_t)zz * LP_ * 1024 + c, 512, s);
    } else if (ti == 1) {
      PK[(size_t)zz * LP_ * 512 + c] = s;
    } else {
      PVt1[((size_t)zz * 512 + c) * 1600 + 0] = __float2half(s);
    }
  } else if (idx < 2 * 12288 + 2 * 512) {
    int k = idx - 2 * 12288;
    int b = k >> 9, c = k & 511;
    PX[(size_t)b * LP_ * 512 + c] = x[(size_t)b * L_ * 512 + c];
  }
}

__device__ __forceinline__ float sincos_val(int pos, int c, int dim) {
  int half = dim / 2;
  bool is_cos = c >= half;
  int i = is_cos ? c - half : c;
  float omega = powf(10000.f, -((float)i) / (float)half);
  float ang = (float)pos * omega;
  return is_cos ? cosf(ang) : sinf(ang);
}

__global__ void k_emb(float* emb) {
  size_t idx = (size_t)blockIdx.x * blockDim.x + threadIdx.x;
  if (idx >= SZ_EMB) return;
  int k = (int)(idx >> 9);
  int c = (int)(idx & 511);
  int t2 = k / 196, h2 = (k / 14) % 14, w2 = k % 14;
  float v;
  if (c < 170) v = sincos_val(t2, c, 170);
  else if (c < 340) v = sincos_val(h2, c - 170, 170);
  else v = sincos_val(w2, c - 340, 172);
  emb[idx] = v;
}

__global__ void k_k2(const float* PK, const float* emb, __nv_bfloat16* K22) {
  size_t idx = (size_t)blockIdx.x * blockDim.x + threadIdx.x;
  if (idx >= (size_t)16 * LP_ * 512) return;
  size_t rem = idx % ((size_t)LP_ * 512);
  int k = (int)(rem >> 9);
  int c = (int)(rem & 511);
  size_t z = idx / ((size_t)LP_ * 512);
  float v = SCALE_ * PK[idx];
  if (k > 0) v += emb[(size_t)(k - 1) * 512 + c];
  st2(K22, (z * LP_ + k) * 1024 + c, 512, v);
}

__global__ void k_row0(const float* PQ, const float* PK, float* lg) {
  int z = blockIdx.y;
  int kq = blockIdx.x * 8 + (threadIdx.x >> 5);
  int lane = threadIdx.x & 31;
  if (kq >= LP_) return;
  const float* q = PQ + (size_t)z * LP_ * 512;
  const float* kr = PK + (size_t)z * LP_ * 512 + (size_t)kq * 512;
  float s = 0.f;
  for (int i = lane; i < 512; i += 32) s += q[i] * kr[i];
#pragma unroll
  for (int o = 16; o; o >>= 1) s += __shfl_xor_sync(0xFFFFFFFFu, s, o);
  if (lane == 0) lg[(size_t)z * LP_ * LGLD_ + kq] = s * SCALE_;
}

__global__ void k_softmax(float* lg, __half* at1) {
  int z = blockIdx.y, q = blockIdx.x;
  float* row = lg + ((size_t)z * LP_ + q) * LGLD_;
  __half* arow = at1 + ((size_t)z * LP_ + q) * 1600;
  int tid = threadIdx.x;
  __shared__ float red[256];
  float mx = -1e30f;
  for (int i = tid; i < LP_; i += 256) mx = fmaxf(mx, row[i]);
  red[tid] = mx;
  __syncthreads();
  for (int s = 128; s > 0; s >>= 1) {
    if (tid < s) red[tid] = fmaxf(red[tid], red[tid + s]);
    __syncthreads();
  }
  mx = red[0];
  __syncthreads();
  float sum = 0.f;
  for (int i = tid; i < LP_; i += 256) {
    float e = expf(row[i] - mx);
    row[i] = e;
    sum += e;
  }
  red[tid] = sum;
  __syncthreads();
  for (int s = 128; s > 0; s >>= 1) {
    if (tid < s) red[tid] += red[tid + s];
    __syncthreads();
  }
  float inv = 1.f / red[0];
  for (int i = tid; i < LPP_; i += 256) {
    float v = (i < LP_) ? row[i] * inv : 0.f;
    arow[i] = __float2half(v);
  }
}

__global__ void k_ln(const float* yp, const float* bd, const float* PX,
                     const float* gamma, const float* beta, float* y) {
  int row = blockIdx.x;
  const float* y0 = yp + (size_t)row * 512;
  const float* y1 = yp + (size_t)B_ * LP_ * 512 + (size_t)row * 512;
  const float* px = PX + (size_t)row * 512;
  float* yr = y + (size_t)row * 512;
  int tid = threadIdx.x;
  float v0 = y0[tid] + y1[tid] + bd[tid] + px[tid];
  float v1 = y0[tid + 256] + y1[tid + 256] + bd[tid + 256] + px[tid + 256];
  __shared__ float red[256];
  red[tid] = v0 + v1;
  __syncthreads();
  for (int s = 128; s > 0; s >>= 1) {
    if (tid < s) red[tid] += red[tid + s];
    __syncthreads();
  }
  float mu = red[0] * (1.f / 512.f);
  __syncthreads();
  float d0 = v0 - mu, d1 = v1 - mu;
  red[tid] = d0 * d0 + d1 * d1;
  __syncthreads();
  for (int s = 128; s > 0; s >>= 1) {
    if (tid < s) red[tid] += red[tid + s];
    __syncthreads();
  }
  float inv = rsqrtf(red[0] * (1.f / 512.f) + 1e-5f);
  yr[tid] = d0 * inv * gamma[tid] + beta[tid];
  yr[tid + 256] = d1 * inv * gamma[tid + 256] + beta[tid + 256];
}

// --------------------------------- launcher ---------------------------------

extern "C" void kernel_launch(void* const* d_in, const int* in_sizes, int n_in,
                              void* d_out, int out_size) {
  (void)in_sizes; (void)n_in; (void)out_size;
  const float* x   = (const float*)d_in[0];
  const float* Wq  = (const float*)d_in[1];
  const float* bq  = (const float*)d_in[2];
  const float* Wk  = (const float*)d_in[3];
  const float* bk  = (const float*)d_in[4];
  const float* Wv  = (const float*)d_in[5];
  const float* bv  = (const float*)d_in[6];
  const float* wpq = (const float*)d_in[7];
  const float* wpk = (const float*)d_in[8];
  const float* wpv = (const float*)d_in[9];
  const float* wpx = (const float*)d_in[10];
  const float* Wd  = (const float*)d_in[11];
  const float* bd  = (const float*)d_in[12];
  const float* gamma = (const float*)d_in[13];
  const float* beta  = (const float*)d_in[14];
  float* y = (float*)d_out;

  float* S = nullptr;
  cudaGetSymbolAddress((void**)&S, g_scratch);
  __nv_bfloat16* Bf = nullptr;
  cudaGetSymbolAddress((void**)&Bf, g_bf);
  __half* Hf = nullptr;
  cudaGetSymbolAddress((void**)&Hf, g_hf);

  float* PQ    = S + OF_PQ;
  float* PK    = S + OF_PK;
  float* PX    = S + OF_PX;
  float* emb   = S + OF_EMB;
  float* bpool = S + OF_BP;
  float* lg    = S + OF_LG;
  float* yp    = S + OF_YP;

  __nv_bfloat16* wpT2 = Bf + OB_WPT2;
  __nv_bfloat16* Wt2  = Bf + OB_WT2;
  __nv_bfloat16* Wd2  = Bf + OB_WD2;
  __nv_bfloat16* WQX2 = Bf + OB_WQX2;
  __nv_bfloat16* Xg2  = Bf + OB_XG2;
  __nv_bfloat16* PQ2  = Bf + OB_PQ2;
  __nv_bfloat16* K22  = Bf + OB_K22;
  __nv_bfloat16* st2b = Bf + OB_ST2;

  __half* WK1  = Hf + OH_WK1;
  __half* WV1  = Hf + OH_WV1;
  __half* Xg1  = Hf + OH_XG1;
  __half* PVt1 = Hf + OH_PVT1;
  __half* at1  = Hf + OH_AT1;

  cudaFuncSetAttribute(gemm_ca<WeffP, true, false>,
                       cudaFuncAttributeMaxDynamicSharedMemorySize, SMEMB);
  cudaFuncSetAttribute(gemm_ca<PoolQXP, true, false>,
                       cudaFuncAttributeMaxDynamicSharedMemorySize, SMEMB);
  cudaFuncSetAttribute(gemm_ca<PoolKP, false, true>,
                       cudaFuncAttributeMaxDynamicSharedMemorySize, SMEMB);
  cudaFuncSetAttribute(gemm_ca<PoolVP, false, true>,
                       cudaFuncAttributeMaxDynamicSharedMemorySize, SMEMB);
  cudaFuncSetAttribute(gemm_ca<LogitsP, true, false>,
                       cudaFuncAttributeMaxDynamicSharedMemorySize, SMEMB);
  cudaFuncSetAttribute(gemm_ca<AVP, false, true>,
                       cudaFuncAttributeMaxDynamicSharedMemorySize, SMEMB);
  cudaFuncSetAttribute(gemm_ca<FinalP, true, false>,
                       cudaFuncAttributeMaxDynamicSharedMemorySize, SMEMB);

  // converters
  k_wpT2<<<(int)((3u * 512 * 512 * 4 + 255) / 256), 256>>>(wpq, wpk, wpv, wpT2);
  k_wt2<<<(int)((3u * 8 * 512 * 512 + 255) / 256), 256>>>(Wq, Wk, Wv, Wt2);
  k_wxe2<<<(512 * 2048 + 255) / 256, 256>>>(wpx, WQX2);
  k_wd2<<<(512 * 4096 + 255) / 256, 256>>>(Wd, Wd2);
  k_bpool<<<(3 * 4096 + 255) / 256, 256>>>(wpq, wpk, wpv, bq, bk, bv, bpool);
  k_gather2<<<(int)((3136u * 2048 + 255) / 256), 256>>>(x, Xg2, Xg1);
  k_padpv<<<(16 * 512 * 31 + 255) / 256, 256>>>(PVt1);

  {
    WeffP p;
    p.M = 512; p.N = 512; p.nch = 16; p.Kh = 512; p.sA = 1024; p.sB = 1024;
    p.wpT2 = (const uint16_t*)wpT2; p.Wt2 = (const uint16_t*)Wt2;
    p.WQX2 = WQX2; p.WK1 = WK1; p.WV1 = WV1;
    gemm_ca<WeffP, true, false><<<dim3(4, 4, 96), 128, SMEMB>>>(p);
  }

  {
    PoolQXP p;
    p.M = 3136; p.N = 4608; p.nch = 64; p.Kh = 2048; p.sA = 4096; p.sB = 4096;
    p.Xg2 = (const uint16_t*)Xg2; p.WQX2 = (const uint16_t*)WQX2;
    p.bias = bpool; p.PQ = PQ; p.PX = PX; p.PQ2 = PQ2;
    gemm_ca<PoolQXP, true, false><<<dim3(36, 25, 1), 128, SMEMB>>>(p);
  }
  {
    PoolKP p;
    p.M = 3136; p.N = 4096; p.nch = 64; p.Kh = 0; p.sA = 2048; p.sB = 2048;
    p.Xg1 = (const uint16_t*)Xg1; p.WK1 = (const uint16_t*)WK1;
    p.bias = bpool + 4096; p.PK = PK;
    gemm_ca<PoolKP, false, true><<<dim3(32, 25, 1), 128, SMEMB>>>(p);
  }
  {
    PoolVP p;
    p.M = 3136; p.N = 4096; p.nch = 64; p.Kh = 0; p.sA = 2048; p.sB = 2048;
    p.Xg1 = (const uint16_t*)Xg1; p.WV1 = (const uint16_t*)WV1;
    p.bias = bpool + 8192; p.PVt1 = PVt1;
    gemm_ca<PoolVP, false, true><<<dim3(32, 25, 1), 128, SMEMB>>>(p);
  }

  k_cls<<<(2 * 12288 + 2 * 512 + 255) / 256, 256>>>(x, Wq, bq, Wk, bk, Wv, bv,
                                                    PQ, PK, PX, PQ2, PVt1);
  k_emb<<<(int)((SZ_EMB + 255) / 256), 256>>>(emb);
  k_k2<<<(int)(((size_t)16 * LP_ * 512 + 255) / 256), 256>>>(PK, emb, K22);

  {
    LogitsP p;
    p.M = LP_; p.N = LP_; p.nch = 16; p.Kh = 512; p.sA = 1024; p.sB = 1024;
    p.PQ2 = (const uint16_t*)PQ2; p.K22 = (const uint16_t*)K22; p.lg = lg;
    gemm_ca<LogitsP, true, false><<<dim3(13, 13, 16), 128, SMEMB>>>(p);
  }

  k_row0<<<dim3((LP_ + 7) / 8, 16), 256>>>(PQ, PK, lg);
  k_softmax<<<dim3(LP_, 16), 256>>>(lg, at1);

  {
    AVP p;
    p.M = LP_; p.N = 512; p.nch = 50; p.Kh = 0; p.sA = 1600; p.sB = 1600;
    p.at1 = (const uint16_t*)at1; p.PVt1 = (const uint16_t*)PVt1;
    p.PQ = PQ; p.st2b = st2b;
    gemm_ca<AVP, false, true><<<dim3(4, 13, 16), 128, SMEMB>>>(p);
  }

  {
    FinalP p;
    p.M = B_ * LP_; p.N = 512; p.nch = 64; p.Kh = 4096; p.sA = 8192;
    p.sB = 8192;
    p.st2b = (const uint16_t*)st2b; p.Wd2 = (const uint16_t*)Wd2; p.yp = yp;
    gemm_ca<FinalP, true, false><<<dim3(4, 25, 2), 128, SMEMB>>>(p);
  }

  k_ln<<<B_ * LP_, 256>>>(yp, bd, PX, gamma, beta, y);
}

// round 14
// speedup vs baseline: 1.5362x; 1.0324x over previous
#include <cuda_runtime.h>
#include <cuda_bf16.h>
#include <cuda_fp16.h>
#include <math.h>
#include <stdint.h>
#include <stddef.h>

// ---------------------------------------------------------------------------
// MultiHeadPooledAttention — mixed-precision HMMA GEMMs.
//   bf16 hi/lo 3-pass: Weff-Q, PoolQX, Final
//   fp16 single-pass:  Weff-KV, PoolK, PoolV, Logits (scale-damped), attn·V
// Positional logits factored out of the big GEMM: qr = qt+qh+qw from three
// tiny fp32 GEMMs, added exactly in the softmax kernel.
// ---------------------------------------------------------------------------

namespace {
constexpr int B_  = 2;
constexpr int L_  = 6273;   // 1 + 8*28*28
constexpr int NH_ = 8;
constexpr int LP_ = 1569;   // 1 + 8*14*14
constexpr int LPP_ = 1600;
constexpr int NB_ = 1568;
constexpr int LGLD_ = 1600;
constexpr float SCALE_ = 0.04419417382415922f;  // 512^-0.5

// fp32 scratch
constexpr size_t SZ_PQ  = (size_t)16 * LP_ * 512;
constexpr size_t SZ_PX  = (size_t)B_ * LP_ * 512;
constexpr size_t SZ_EMB = (size_t)NB_ * 512;
constexpr size_t SZ_BP  = (size_t)3 * 4096;
constexpr size_t SZ_LG  = (size_t)16 * LP_ * LGLD_;
constexpr size_t SZ_YP  = (size_t)2 * B_ * LP_ * 512;
constexpr size_t SZ_QTW = (size_t)16 * LP_ * 36;

constexpr size_t OF_PQ  = 0;
constexpr size_t OF_PX  = OF_PQ + SZ_PQ;
constexpr size_t OF_EMB = OF_PX + SZ_PX;
constexpr size_t OF_BP  = OF_EMB + SZ_EMB;
constexpr size_t OF_LG  = OF_BP + SZ_BP;
constexpr size_t OF_YP  = OF_LG + SZ_LG;
constexpr size_t OF_QTW = OF_YP + SZ_YP;
constexpr size_t SZ_F32 = OF_QTW + SZ_QTW;

// bf16 hi/lo buffers (planar: hi at [0,Kh), lo at [Kh,2Kh), row stride 2Kh)
constexpr size_t SZB_WPT2  = (size_t)4 * 512 * 1024;    // Q pool taps
constexpr size_t SZB_WT2   = (size_t)8 * 512 * 1024;    // Wq heads (transposed)
constexpr size_t SZB_WD2   = (size_t)512 * 8192;
constexpr size_t SZB_WQX2  = (size_t)4608 * 4096;       // Weff-Q + WXe
constexpr size_t SZB_XG2   = (size_t)3136 * 4096;
constexpr size_t SZB_ST2   = (size_t)B_ * LP_ * 8192;

constexpr size_t OB_WPT2  = 0;
constexpr size_t OB_WT2   = OB_WPT2 + SZB_WPT2;
constexpr size_t OB_WD2   = OB_WT2 + SZB_WT2;
constexpr size_t OB_WQX2  = OB_WD2 + SZB_WD2;
constexpr size_t OB_XG2   = OB_WQX2 + SZB_WQX2;
constexpr size_t OB_ST2   = OB_XG2 + SZB_XG2;
constexpr size_t SZ_BF    = OB_ST2 + SZB_ST2;

// fp16 single-plane buffers
constexpr size_t SZH_WPT1 = (size_t)8 * 512 * 512;      // K,V pool taps
constexpr size_t SZH_WT1  = (size_t)16 * 512 * 512;     // Wk,Wv heads
constexpr size_t SZH_WK1  = (size_t)4096 * 2048;
constexpr size_t SZH_WV1  = (size_t)4096 * 2048;
constexpr size_t SZH_XG1  = (size_t)3136 * 2048;
constexpr size_t SZH_PQ1  = (size_t)16 * LP_ * 512;
constexpr size_t SZH_PK1  = (size_t)16 * LP_ * 512;
constexpr size_t SZH_PVT1 = (size_t)16 * 512 * 1600;
constexpr size_t SZH_AT1  = (size_t)16 * LP_ * 1600;

constexpr size_t OH_WPT1 = 0;
constexpr size_t OH_WT1  = OH_WPT1 + SZH_WPT1;
constexpr size_t OH_WK1  = OH_WT1 + SZH_WT1;
constexpr size_t OH_WV1  = OH_WK1 + SZH_WK1;
constexpr size_t OH_XG1  = OH_WV1 + SZH_WV1;
constexpr size_t OH_PQ1  = OH_XG1 + SZH_XG1;
constexpr size_t OH_PK1  = OH_PQ1 + SZH_PQ1;
constexpr size_t OH_PVT1 = OH_PK1 + SZH_PK1;
constexpr size_t OH_AT1  = OH_PVT1 + SZH_PVT1;
constexpr size_t SZ_HF   = OH_AT1 + SZH_AT1;
}  // namespace

__device__ float g_scratch[SZ_F32];
__device__ __align__(16) __nv_bfloat16 g_bf[SZ_BF];
__device__ __align__(16) __half g_hf[SZ_HF];

// ------------------------------- PTX helpers -------------------------------

__device__ __forceinline__ uint32_t smem_u32(const void* p) {
  uint32_t a;
  asm("{ .reg .u64 t; cvta.to.shared.u64 t, %1; cvt.u32.u64 %0, t; }"
      : "=r"(a) : "l"(p));
  return a;
}

__device__ __forceinline__ void ldm4(uint32_t* d, uint32_t addr) {
  asm volatile("ldmatrix.sync.aligned.m8n8.x4.shared.b16 {%0,%1,%2,%3}, [%4];"
               : "=r"(d[0]), "=r"(d[1]), "=r"(d[2]), "=r"(d[3]) : "r"(addr));
}

__device__ __forceinline__ void mma_bf(float* c, const uint32_t* a,
                                       const uint32_t* b) {
  asm volatile(
      "mma.sync.aligned.m16n8k16.row.col.f32.bf16.bf16.f32 "
      "{%0,%1,%2,%3}, {%4,%5,%6,%7}, {%8,%9}, {%0,%1,%2,%3};"
      : "+f"(c[0]), "+f"(c[1]), "+f"(c[2]), "+f"(c[3])
      : "r"(a[0]), "r"(a[1]), "r"(a[2]), "r"(a[3]), "r"(b[0]), "r"(b[1]));
}
__device__ __forceinline__ void mma_fp(float* c, const uint32_t* a,
                                       const uint32_t* b) {
  asm volatile(
      "mma.sync.aligned.m16n8k16.row.col.f32.f16.f16.f32 "
      "{%0,%1,%2,%3}, {%4,%5,%6,%7}, {%8,%9}, {%0,%1,%2,%3};"
      : "+f"(c[0]), "+f"(c[1]), "+f"(c[2]), "+f"(c[3])
      : "r"(a[0]), "r"(a[1]), "r"(a[2]), "r"(a[3]), "r"(b[0]), "r"(b[1]));
}

__device__ __forceinline__ void cpa16(uint32_t dst, const void* src, bool ok) {
  int sz = ok ? 16 : 0;
  asm volatile("cp.async.cg.shared.global [%0], [%1], 16, %2;"
               :: "r"(dst), "l"(src), "r"(sz) : "memory");
}
__device__ __forceinline__ void cpa_commit() {
  asm volatile("cp.async.commit_group;" ::: "memory");
}
template <int N>
__device__ __forceinline__ void cpa_wait() {
  asm volatile("cp.async.wait_group %0;" :: "n"(N) : "memory");
}

__device__ __forceinline__ void st2(__nv_bfloat16* p, size_t i, size_t kh,
                                    float v) {
  __nv_bfloat16 h = __float2bfloat16(v);
  p[i] = h;
  p[i + kh] = __float2bfloat16(v - __bfloat162float(h));
}

// --------------------------- cp.async GEMM kernel ----------------------------

constexpr int ROWB = 80;
constexpr int TILEB = 128 * ROWB;
constexpr int STAGEB = 4 * TILEB;
constexpr int SMEMB = 2 * STAGEB;  // 81920

__device__ __forceinline__ void issue4(const uint16_t* S, int stride, int rmax,
                                       int r0, int kofs, uint32_t dstB,
                                       int tid) {
#pragma unroll
  for (int i = 0; i < 4; i++) {
    int idx = tid + 128 * i;
    int row = idx >> 2, q = idx & 3;
    int gr = r0 + row;
    bool ok = gr < rmax;
    const uint16_t* src = S + (size_t)(ok ? gr : 0) * stride + kofs + q * 8;
    cpa16(dstB + (uint32_t)(row * ROWB + q * 16), src, ok);
  }
}

template <typename P, bool SPLIT, bool FP16>
__global__ __launch_bounds__(128) void gemm_ca(P p) {
  extern __shared__ __align__(16) char sm[];
  uint32_t base = smem_u32(sm);

  const int tid = threadIdx.x;
  const int wid = tid >> 5, lane = tid & 31;
  const int wm = wid >> 1, wn = wid & 1;
  const int lj = lane >> 3, lr = lane & 7;

  const int z = blockIdx.z;
  const uint16_t* A = p.Aptr(z);
  const uint16_t* Bm = p.Bptr(z);
  const int M = p.M, N = p.N;
  const int m0 = blockIdx.y * 128, n0 = blockIdx.x * 128;
  const int nch = p.nch, Kh = p.Kh, sA = p.sA, sB = p.sB;
  const int kb = p.kbase(z);

  float acc[4][8][4];
#pragma unroll
  for (int a = 0; a < 4; a++)
#pragma unroll
    for (int b = 0; b < 8; b++)
#pragma unroll
      for (int c = 0; c < 4; c++) acc[a][b][c] = 0.f;

  const uint32_t aRow = (uint32_t)(wm * 64 + (lj & 1) * 8 + lr);
  const uint32_t aCol = (uint32_t)((lj >> 1) * 16);
  const uint32_t bRow = (uint32_t)(wn * 64 + (lj >> 1) * 8 + lr);
  const uint32_t bCol = (uint32_t)((lj & 1) * 16);

  {
    uint32_t st = base;
    issue4(A, sA, M, m0, kb, st, tid);
    if (SPLIT) issue4(A, sA, M, m0, Kh + kb, st + TILEB, tid);
    issue4(Bm, sB, N, n0, kb, st + 2 * TILEB, tid);
    if (SPLIT) issue4(Bm, sB, N, n0, Kh + kb, st + 3 * TILEB, tid);
    cpa_commit();
  }

  for (int ch = 0; ch < nch; ++ch) {
    int s = ch & 1;
    if (ch + 1 < nch) {
      int k0 = kb + (ch + 1) * 32;
      uint32_t st = base + (uint32_t)((1 - s) * STAGEB);
      issue4(A, sA, M, m0, k0, st, tid);
      if (SPLIT) issue4(A, sA, M, m0, Kh + k0, st + TILEB, tid);
      issue4(Bm, sB, N, n0, k0, st + 2 * TILEB, tid);
      if (SPLIT) issue4(Bm, sB, N, n0, Kh + k0, st + 3 * TILEB, tid);
      cpa_commit();
      cpa_wait<1>();
    } else {
      cpa_wait<0>();
    }
    __syncthreads();

    uint32_t stg = base + (uint32_t)(s * STAGEB);
    const int npass = SPLIT ? 3 : 1;
#pragma unroll 1
    for (int ps = 0; ps < npass; ps++) {
      uint32_t aT = stg + ((ps == 1) ? TILEB : 0);
      uint32_t bT = stg + 2 * TILEB + ((ps == 2) ? TILEB : 0);
#pragma unroll
      for (int ks = 0; ks < 2; ks++) {
        uint32_t afr[4][4];
#pragma unroll
        for (int mi = 0; mi < 4; mi++)
          ldm4(afr[mi], aT + (aRow + mi * 16) * ROWB + ks * 32 + aCol);
        uint32_t bfr[8][2];
#pragma unroll
        for (int nb = 0; nb < 4; nb++) {
          uint32_t t[4];
          ldm4(t, bT + (bRow + nb * 16) * ROWB + ks * 32 + bCol);
          bfr[2 * nb][0] = t[0];
          bfr[2 * nb][1] = t[1];
          bfr[2 * nb + 1][0] = t[2];
          bfr[2 * nb + 1][1] = t[3];
        }
#pragma unroll
        for (int mi = 0; mi < 4; mi++)
#pragma unroll
          for (int ni = 0; ni < 8; ni++) {
            if (FP16) mma_fp(acc[mi][ni], afr[mi], bfr[ni]);
            else      mma_bf(acc[mi][ni], afr[mi], bfr[ni]);
          }
      }
    }
    __syncthreads();
  }

  const int rr = lane >> 2, cc = (lane & 3) * 2;
#pragma unroll
  for (int mi = 0; mi < 4; mi++) {
#pragma unroll
    for (int ni = 0; ni < 8; ni++) {
      int rb = m0 + wm * 64 + mi * 16 + rr;
      int cb = n0 + wn * 64 + ni * 8 + cc;
      if (rb < M) {
        if (cb < N)     p.store(z, rb, cb,     acc[mi][ni][0]);
        if (cb + 1 < N) p.store(z, rb, cb + 1, acc[mi][ni][1]);
      }
      if (rb + 8 < M) {
        if (cb < N)     p.store(z, rb + 8, cb,     acc[mi][ni][2]);
        if (cb + 1 < N) p.store(z, rb + 8, cb + 1, acc[mi][ni][3]);
      }
    }
  }
}

// ----------------------------- GEMM problem defs ----------------------------

struct WeffQP {  // bf16 3-pass, z = n*4+t (32 blocks)
  int M, N, nch, Kh, sA, sB;
  const uint16_t *wpT2, *Wt2;
  __nv_bfloat16* WQX2;
  __device__ int kbase(int) const { return 0; }
  __device__ const uint16_t* Aptr(int z) const {
    return wpT2 + (size_t)(z & 3) * 512 * 1024;
  }
  __device__ const uint16_t* Bptr(int z) const {
    return Wt2 + (size_t)(z >> 2) * 512 * 1024;
  }
  __device__ void store(int z, int r, int c, float v) const {
    int n = z >> 2, t = z & 3;
    st2(WQX2, ((size_t)n * 512 + r) * 4096 + t * 512 + c, 2048, v);
  }
};

struct WeffKVP {  // fp16 1-pass, z = tv*32 + n*4 + t (64 blocks)
  int M, N, nch, Kh, sA, sB;
  const uint16_t *wpT1, *Wt1;
  __half *WK1, *WV1;
  __device__ int kbase(int) const { return 0; }
  __device__ const uint16_t* Aptr(int z) const {
    int tv = z >> 5, t = z & 3;
    return wpT1 + (size_t)(tv * 4 + t) * 512 * 512;
  }
  __device__ const uint16_t* Bptr(int z) const {
    int tv = z >> 5, n = (z & 31) >> 2;
    return Wt1 + (size_t)(tv * 8 + n) * 512 * 512;
  }
  __device__ void store(int z, int r, int c, float v) const {
    int tv = z >> 5, n = (z & 31) >> 2, t = z & 3;
    __half* dst = tv ? WV1 : WK1;
    dst[((size_t)n * 512 + r) * 2048 + t * 512 + c] = __float2half(v);
  }
};

struct PoolQXP {  // bf16 3-pass
  int M, N, nch, Kh, sA, sB;
  const uint16_t *Xg2, *WQX2;
  const float* bias;
  float* PQ;
  float* PX;
  __half* PQ1;
  __device__ int kbase(int) const { return 0; }
  __device__ const uint16_t* Aptr(int) const { return Xg2; }
  __device__ const uint16_t* Bptr(int) const { return WQX2; }
  __device__ void store(int, int r, int c, float v) const {
    int b = r / NB_, o = r % NB_;
    if (c < 4096) {
      v += bias[c];
      int n = c >> 9, d = c & 511;
      size_t idx = ((size_t)(b * 8 + n) * LP_ + 1 + o) * 512 + d;
      PQ[idx] = v;
      PQ1[idx] = __float2half(v);
    } else {
      PX[((size_t)b * LP_ + 1 + o) * 512 + (c - 4096)] = v;
    }
  }
};

struct PoolKP {  // fp16 1-pass
  int M, N, nch, Kh, sA, sB;
  const uint16_t *Xg1, *WK1;
  const float* bias;
  __half* PK1;
  __device__ int kbase(int) const { return 0; }
  __device__ const uint16_t* Aptr(int) const { return Xg1; }
  __device__ const uint16_t* Bptr(int) const { return WK1; }
  __device__ void store(int, int r, int c, float v) const {
    int b = r / NB_, o = r % NB_;
    v += bias[c];
    int n = c >> 9, d = c & 511;
    PK1[((size_t)(b * 8 + n) * LP_ + 1 + o) * 512 + d] = __float2half(v);
  }
};

struct PoolVP {  // fp16 1-pass -> transposed fp16 PVt1
  int M, N, nch, Kh, sA, sB;
  const uint16_t *Xg1, *WV1;
  const float* bias;
  __half* PVt1;
  __device__ int kbase(int) const { return 0; }
  __device__ const uint16_t* Aptr(int) const { return Xg1; }
  __device__ const uint16_t* Bptr(int) const { return WV1; }
  __device__ void store(int, int r, int c, float v) const {
    int b = r / NB_, o = r % NB_;
    v += bias[c];
    int n = c >> 9, d = c & 511;
    PVt1[((size_t)(b * 8 + n) * 512 + d) * 1600 + 1 + o] = __float2half(v);
  }
};

struct LogitsP {  // fp16 1-pass, raw PQ·PK^T (scale + qr applied in softmax)
  int M, N, nch, Kh, sA, sB;
  const uint16_t *PQ1, *PK1;
  float* lg;
  __device__ int kbase(int) const { return 0; }
  __device__ const uint16_t* Aptr(int z) const {
    return PQ1 + (size_t)z * LP_ * 512;
  }
  __device__ const uint16_t* Bptr(int z) const {
    return PK1 + (size_t)z * LP_ * 512;
  }
  __device__ void store(int z, int r, int c, float v) const {
    lg[(size_t)z * LP_ * LGLD_ + (size_t)r * LGLD_ + c] = v;
  }
};

struct AVP {  // fp16 1-pass
  int M, N, nch, Kh, sA, sB;
  const uint16_t *at1, *PVt1;
  const float* PQ;
  __nv_bfloat16* st2b;
  __device__ int kbase(int) const { return 0; }
  __device__ const uint16_t* Aptr(int z) const {
    return at1 + (size_t)z * LP_ * 1600;
  }
  __device__ const uint16_t* Bptr(int z) const {
    return PVt1 + (size_t)z * 512 * 1600;
  }
  __device__ void store(int z, int r, int c, float v) const {
    float pq = PQ[(size_t)z * LP_ * 512 + (size_t)r * 512 + c];
    v += (r > 0 ? 2.f : 1.f) * pq;
    int b = z >> 3, n = z & 7;
    st2(st2b, ((size_t)b * LP_ + r) * 8192 + n * 512 + c, 4096, v);
  }
};

struct FinalP {  // bf16 3-pass, split-K=2
  int M, N, nch, Kh, sA, sB;
  const uint16_t *st2b, *Wd2;
  float* yp;
  __device__ int kbase(int z) const { return z * 2048; }
  __device__ const uint16_t* Aptr(int) const { return st2b; }
  __device__ const uint16_t* Bptr(int) const { return Wd2; }
  __device__ void store(int z, int r, int c, float v) const {
    yp[(size_t)z * B_ * LP_ * 512 + (size_t)r * 512 + c] = v;
  }
};

// ------------------------------ helper kernels ------------------------------

__global__ void k_wpT(const float* wpq, const float* wpk, const float* wpv,
                      __nv_bfloat16* wpT2, __half* wpT1) {
  size_t idx = (size_t)blockIdx.x * blockDim.x + threadIdx.x;
  if (idx >= (size_t)3 * 512 * 512 * 4) return;
  int ti = (int)(idx / (512 * 512 * 4));
  int r = (int)(idx % (512 * 512 * 4));
  int c = r / 2048;
  int d = (r % 2048) >> 2;
  int t = r & 3;
  const float* wp = (ti == 0) ? wpq : ((ti == 1) ? wpk : wpv);
  float v = wp[r];
  if (ti == 0)
    st2(wpT2, ((size_t)t * 512 + c) * 1024 + d, 512, v);
  else
    wpT1[((size_t)((ti - 1) * 4 + t) * 512 + c) * 512 + d] = __float2half(v);
}

__global__ void k_wt(const float* Wq, const float* Wk, const float* Wv,
                     __nv_bfloat16* Wt2, __half* Wt1) {
  size_t idx = (size_t)blockIdx.x * blockDim.x + threadIdx.x;
  if (idx >= (size_t)3 * 8 * 512 * 512) return;
  int d = (int)(idx & 511);
  int m = (int)((idx >> 9) & 511);
  int n = (int)((idx >> 18) & 7);
  int ti = (int)(idx >> 21);
  const float* W = (ti == 0) ? Wq : ((ti == 1) ? Wk : Wv);
  float v = W[(size_t)(n * 512 + d) * 512 + m];
  if (ti == 0)
    st2(Wt2, ((size_t)n * 512 + m) * 1024 + d, 512, v);
  else
    Wt1[((size_t)((ti - 1) * 8 + n) * 512 + m) * 512 + d] = __float2half(v);
}

__global__ void k_wxe2(const float* wpx, __nv_bfloat16* WQX2) {
  size_t idx = (size_t)blockIdx.x * blockDim.x + threadIdx.x;
  if (idx >= (size_t)512 * 2048) return;
  int c = (int)(idx >> 11);
  int col = (int)(idx & 2047);
  int t = col >> 9, m = col & 511;
  float v = wpx[(size_t)c * 2048 + m * 4 + t];
  st2(WQX2, (size_t)(4096 + c) * 4096 + col, 2048, v);
}

__global__ void k_wd2(const float* Wd, __nv_bfloat16* Wd2) {
  size_t idx = (size_t)blockIdx.x * blockDim.x + threadIdx.x;
  if (idx >= (size_t)512 * 4096) return;
  int c = (int)(idx >> 12), k = (int)(idx & 4095);
  st2(Wd2, (size_t)c * 8192 + k, 4096, Wd[idx]);
}

__global__ void k_bpool(const float* wpq, const float* wpk, const float* wpv,
                        const float* bq, const float* bk, const float* bv,
                        float* bpool) {
  int j = blockIdx.x * blockDim.x + threadIdx.x;
  if (j >= 3 * 4096) return;
  int ti = j / 4096, h = j % 4096, n = h >> 9, c = h & 511;
  const float* wp = (ti == 0) ? wpq : ((ti == 1) ? wpk : wpv);
  const float* b = (ti == 0) ? bq : ((ti == 1) ? bk : bv);
  float s = 0.f;
  for (int d = 0; d < 512; d++) {
    float bb = b[n * 512 + d];
    const float* w = wp + (size_t)c * 2048 + d * 4;
    s += (w[0] + w[1] + w[2] + w[3]) * bb;
  }
  bpool[j] = s;
}

__global__ void k_gather2(const float* x, __nv_bfloat16* Xg2, __half* Xg1) {
  size_t idx = (size_t)blockIdx.x * blockDim.x + threadIdx.x;
  if (idx >= (size_t)3136 * 2048) return;
  int r = (int)(idx >> 11);
  int col = (int)(idx & 2047);
  int t = col >> 9, m = col & 511;
  int b = r / NB_, o = r % NB_;
  int t2 = o / 196, hh = (o / 14) % 14, ww = o % 14;
  int kh = t >> 1, kw = t & 1;
  int row = 1 + (t2 * 28 + 2 * hh + kh) * 28 + 2 * ww + kw;
  float v = x[((size_t)b * L_ + row) * 512 + m];
  st2(Xg2, (size_t)r * 4096 + col, 2048, v);
  Xg1[(size_t)r * 2048 + col] = __float2half(v);
}

__global__ void k_padpv(__half* PVt1) {
  int idx = blockIdx.x * blockDim.x + threadIdx.x;
  if (idx >= 16 * 512 * 31) return;
  int j = idx % 31;
  int rc = idx / 31;
  PVt1[(size_t)rc * 1600 + LP_ + j] = __float2half(0.f);
}

__global__ void k_cls(const float* x, const float* Wq, const float* bq,
                      const float* Wk, const float* bk, const float* Wv,
                      const float* bv, float* PQ, float* PX, __half* PQ1,
                      __half* PK1, __half* PVt1) {
  int idx = blockIdx.x * blockDim.x + threadIdx.x;
  if (idx < 2 * 12288) {
    int b = idx / 12288, j = idx % 12288, ti = j / 4096, jj = j & 4095;
    const float* W = (ti == 0) ? Wq : ((ti == 1) ? Wk : Wv);
    const float* bias = (ti == 0) ? bq : ((ti == 1) ? bk : bv);
    const float* xr = x + (size_t)b * L_ * 512;
    const float* wr = W + (size_t)jj * 512;
    float s = bias[jj];
    for (int m = 0; m < 512; m++) s += xr[m] * wr[m];
    int n = jj >> 9, c = jj & 511;
    int zz = b * 8 + n;
    if (ti == 0) {
      PQ[(size_t)zz * LP_ * 512 + c] = s;
      PQ1[(size_t)zz * LP_ * 512 + c] = __float2half(s);
    } else if (ti == 1) {
      PK1[(size_t)zz * LP_ * 512 + c] = __float2half(s);
    } else {
      PVt1[((size_t)zz * 512 + c) * 1600 + 0] = __float2half(s);
    }
  } else if (idx < 2 * 12288 + 2 * 512) {
    int k = idx - 2 * 12288;
    int b = k >> 9, c = k & 511;
    PX[(size_t)b * LP_ * 512 + c] = x[(size_t)b * L_ * 512 + c];
  }
}

__device__ __forceinline__ float sincos_val(int pos, int c, int dim) {
  int half = dim / 2;
  bool is_cos = c >= half;
  int i = is_cos ? c - half : c;
  float omega = powf(10000.f, -((float)i) / (float)half);
  float ang = (float)pos * omega;
  return is_cos ? cosf(ang) : sinf(ang);
}

__global__ void k_emb(float* emb) {
  size_t idx = (size_t)blockIdx.x * blockDim.x + threadIdx.x;
  if (idx >= SZ_EMB) return;
  int k = (int)(idx >> 9);
  int c = (int)(idx & 511);
  int t2 = k / 196, h2 = (k / 14) % 14, w2 = k % 14;
  float v;
  if (c < 170) v = sincos_val(t2, c, 170);
  else if (c < 340) v = sincos_val(h2, c - 170, 170);
  else v = sincos_val(w2, c - 340, 172);
  emb[idx] = v;
}

// qt/qh/qw: 36 positional dots per (z, q) in exact fp32.
__global__ void k_qr(const float* PQ, const float* emb, float* qtw) {
  int q = blockIdx.x, z = blockIdx.y;
  __shared__ float row[512];
  const float* pq = PQ + ((size_t)z * LP_ + q) * 512;
  for (int i = threadIdx.x; i < 512; i += 256) row[i] = pq[i];
  __syncthreads();
  int j = threadIdx.x;
  if (j < 36) {
    int d0, dn, kk;
    if (j < 8)       { d0 = 0;   dn = 170; kk = j * 196; }
    else if (j < 22) { d0 = 170; dn = 170; kk = (j - 8) * 14; }
    else             { d0 = 340; dn = 172; kk = j - 22; }
    const float* e = emb + (size_t)kk * 512 + d0;
    float s = 0.f;
    for (int d = 0; d < dn; d++) s += row[d0 + d] * e[d];
    qtw[((size_t)z * LP_ + q) * 36 + j] = s;
  }
}

__global__ void k_softmax(float* lg, const float* qtw, __half* at1) {
  int z = blockIdx.y, q = blockIdx.x;
  float* row = lg + ((size_t)z * LP_ + q) * LGLD_;
  __half* arow = at1 + ((size_t)z * LP_ + q) * 1600;
  int tid = threadIdx.x;
  __shared__ float red[256];
  __shared__ float qv[36];
  if (tid < 36) qv[tid] = qtw[((size_t)z * LP_ + q) * 36 + tid];
  __syncthreads();
  float mx = -1e30f;
  for (int i = tid; i < LP_; i += 256) {
    float l = SCALE_ * row[i];
    if (q > 0 && i > 0) {
      int k = i - 1;
      int t2 = k / 196;
      int rm = k - t2 * 196;
      int h2 = rm / 14;
      int w2 = rm - h2 * 14;
      l += qv[t2] + qv[8 + h2] + qv[22 + w2];
    }
    row[i] = l;
    mx = fmaxf(mx, l);
  }
  red[tid] = mx;
  __syncthreads();
  for (int s = 128; s > 0; s >>= 1) {
    if (tid < s) red[tid] = fmaxf(red[tid], red[tid + s]);
    __syncthreads();
  }
  mx = red[0];
  __syncthreads();
  float sum = 0.f;
  for (int i = tid; i < LP_; i += 256) {
    float e = expf(row[i] - mx);
    row[i] = e;
    sum += e;
  }
  red[tid] = sum;
  __syncthreads();
  for (int s = 128; s > 0; s >>= 1) {
    if (tid < s) red[tid] += red[tid + s];
    __syncthreads();
  }
  float inv = 1.f / red[0];
  for (int i = tid; i < LPP_; i += 256) {
    float v = (i < LP_) ? row[i] * inv : 0.f;
    arow[i] = __float2half(v);
  }
}

__global__ void k_ln(const float* yp, const float* bd, const float* PX,
                     const float* gamma, const float* beta, float* y) {
  int row = blockIdx.x;
  const float* y0 = yp + (size_t)row * 512;
  const float* y1 = yp + (size_t)B_ * LP_ * 512 + (size_t)row * 512;
  const float* px = PX + (size_t)row * 512;
  float* yr = y + (size_t)row * 512;
  int tid = threadIdx.x;
  float v0 = y0[tid] + y1[tid] + bd[tid] + px[tid];
  float v1 = y0[tid + 256] + y1[tid + 256] + bd[tid + 256] + px[tid + 256];
  __shared__ float red[256];
  red[tid] = v0 + v1;
  __syncthreads();
  for (int s = 128; s > 0; s >>= 1) {
    if (tid < s) red[tid] += red[tid + s];
    __syncthreads();
  }
  float mu = red[0] * (1.f / 512.f);
  __syncthreads();
  float d0 = v0 - mu, d1 = v1 - mu;
  red[tid] = d0 * d0 + d1 * d1;
  __syncthreads();
  for (int s = 128; s > 0; s >>= 1) {
    if (tid < s) red[tid] += red[tid + s];
    __syncthreads();
  }
  float inv = rsqrtf(red[0] * (1.f / 512.f) + 1e-5f);
  yr[tid] = d0 * inv * gamma[tid] + beta[tid];
  yr[tid + 256] = d1 * inv * gamma[tid + 256] + beta[tid + 256];
}

// --------------------------------- launcher ---------------------------------

extern "C" void kernel_launch(void* const* d_in, const int* in_sizes, int n_in,
                              void* d_out, int out_size) {
  (void)in_sizes; (void)n_in; (void)out_size;
  const float* x   = (const float*)d_in[0];
  const float* Wq  = (const float*)d_in[1];
  const float* bq  = (const float*)d_in[2];
  const float* Wk  = (const float*)d_in[3];
  const float* bk  = (const float*)d_in[4];
  const float* Wv  = (const float*)d_in[5];
  const float* bv  = (const float*)d_in[6];
  const float* wpq = (const float*)d_in[7];
  const float* wpk = (const float*)d_in[8];
  const float* wpv = (const float*)d_in[9];
  const float* wpx = (const float*)d_in[10];
  const float* Wd  = (const float*)d_in[11];
  const float* bd  = (const float*)d_in[12];
  const float* gamma = (const float*)d_in[13];
  const float* beta  = (const float*)d_in[14];
  float* y = (float*)d_out;

  float* S = nullptr;
  cudaGetSymbolAddress((void**)&S, g_scratch);
  __nv_bfloat16* Bf = nullptr;
  cudaGetSymbolAddress((void**)&Bf, g_bf);
  __half* Hf = nullptr;
  cudaGetSymbolAddress((void**)&Hf, g_hf);

  float* PQ    = S + OF_PQ;
  float* PX    = S + OF_PX;
  float* emb   = S + OF_EMB;
  float* bpool = S + OF_BP;
  float* lg    = S + OF_LG;
  float* yp    = S + OF_YP;
  float* qtw   = S + OF_QTW;

  __nv_bfloat16* wpT2 = Bf + OB_WPT2;
  __nv_bfloat16* Wt2  = Bf + OB_WT2;
  __nv_bfloat16* Wd2  = Bf + OB_WD2;
  __nv_bfloat16* WQX2 = Bf + OB_WQX2;
  __nv_bfloat16* Xg2  = Bf + OB_XG2;
  __nv_bfloat16* st2b = Bf + OB_ST2;

  __half* wpT1 = Hf + OH_WPT1;
  __half* Wt1  = Hf + OH_WT1;
  __half* WK1  = Hf + OH_WK1;
  __half* WV1  = Hf + OH_WV1;
  __half* Xg1  = Hf + OH_XG1;
  __half* PQ1  = Hf + OH_PQ1;
  __half* PK1  = Hf + OH_PK1;
  __half* PVt1 = Hf + OH_PVT1;
  __half* at1  = Hf + OH_AT1;

  cudaFuncSetAttribute(gemm_ca<WeffQP, true, false>,
                       cudaFuncAttributeMaxDynamicSharedMemorySize, SMEMB);
  cudaFuncSetAttribute(gemm_ca<WeffKVP, false, true>,
                       cudaFuncAttributeMaxDynamicSharedMemorySize, SMEMB);
  cudaFuncSetAttribute(gemm_ca<PoolQXP, true, false>,
                       cudaFuncAttributeMaxDynamicSharedMemorySize, SMEMB);
  cudaFuncSetAttribute(gemm_ca<PoolKP, false, true>,
                       cudaFuncAttributeMaxDynamicSharedMemorySize, SMEMB);
  cudaFuncSetAttribute(gemm_ca<PoolVP, false, true>,
                       cudaFuncAttributeMaxDynamicSharedMemorySize, SMEMB);
  cudaFuncSetAttribute(gemm_ca<LogitsP, false, true>,
                       cudaFuncAttributeMaxDynamicSharedMemorySize, SMEMB);
  cudaFuncSetAttribute(gemm_ca<AVP, false, true>,
                       cudaFuncAttributeMaxDynamicSharedMemorySize, SMEMB);
  cudaFuncSetAttribute(gemm_ca<FinalP, true, false>,
                       cudaFuncAttributeMaxDynamicSharedMemorySize, SMEMB);

  // converters
  k_wpT<<<(int)((3u * 512 * 512 * 4 + 255) / 256), 256>>>(wpq, wpk, wpv, wpT2,
                                                          wpT1);
  k_wt<<<(int)((3u * 8 * 512 * 512 + 255) / 256), 256>>>(Wq, Wk, Wv, Wt2, Wt1);
  k_wxe2<<<(512 * 2048 + 255) / 256, 256>>>(wpx, WQX2);
  k_wd2<<<(512 * 4096 + 255) / 256, 256>>>(Wd, Wd2);
  k_bpool<<<(3 * 4096 + 255) / 256, 256>>>(wpq, wpk, wpv, bq, bk, bv, bpool);
  k_gather2<<<(int)((3136u * 2048 + 255) / 256), 256>>>(x, Xg2, Xg1);
  k_padpv<<<(16 * 512 * 31 + 255) / 256, 256>>>(PVt1);
  k_emb<<<(int)((SZ_EMB + 255) / 256), 256>>>(emb);

  {
    WeffQP p;
    p.M = 512; p.N = 512; p.nch = 16; p.Kh = 512; p.sA = 1024; p.sB = 1024;
    p.wpT2 = (const uint16_t*)wpT2; p.Wt2 = (const uint16_t*)Wt2;
    p.WQX2 = WQX2;
    gemm_ca<WeffQP, true, false><<<dim3(4, 4, 32), 128, SMEMB>>>(p);
  }
  {
    WeffKVP p;
    p.M = 512; p.N = 512; p.nch = 16; p.Kh = 0; p.sA = 512; p.sB = 512;
    p.wpT1 = (const uint16_t*)wpT1; p.Wt1 = (const uint16_t*)Wt1;
    p.WK1 = WK1; p.WV1 = WV1;
    gemm_ca<WeffKVP, false, true><<<dim3(4, 4, 64), 128, SMEMB>>>(p);
  }

  {
    PoolQXP p;
    p.M = 3136; p.N = 4608; p.nch = 64; p.Kh = 2048; p.sA = 4096; p.sB = 4096;
    p.Xg2 = (const uint16_t*)Xg2; p.WQX2 = (const uint16_t*)WQX2;
    p.bias = bpool; p.PQ = PQ; p.PX = PX; p.PQ1 = PQ1;
    gemm_ca<PoolQXP, true, false><<<dim3(36, 25, 1), 128, SMEMB>>>(p);
  }
  {
    PoolKP p;
    p.M = 3136; p.N = 4096; p.nch = 64; p.Kh = 0; p.sA = 2048; p.sB = 2048;
    p.Xg1 = (const uint16_t*)Xg1; p.WK1 = (const uint16_t*)WK1;
    p.bias = bpool + 4096; p.PK1 = PK1;
    gemm_ca<PoolKP, false, true><<<dim3(32, 25, 1), 128, SMEMB>>>(p);
  }
  {
    PoolVP p;
    p.M = 3136; p.N = 4096; p.nch = 64; p.Kh = 0; p.sA = 2048; p.sB = 2048;
    p.Xg1 = (const uint16_t*)Xg1; p.WV1 = (const uint16_t*)WV1;
    p.bias = bpool + 8192; p.PVt1 = PVt1;
    gemm_ca<PoolVP, false, true><<<dim3(32, 25, 1), 128, SMEMB>>>(p);
  }

  k_cls<<<(2 * 12288 + 2 * 512 + 255) / 256, 256>>>(x, Wq, bq, Wk, bk, Wv, bv,
                                                    PQ, PX, PQ1, PK1, PVt1);
  k_qr<<<dim3(LP_, 16), 256>>>(PQ, emb, qtw);

  {
    LogitsP p;
    p.M = LP_; p.N = LP_; p.nch = 16; p.Kh = 0; p.sA = 512; p.sB = 512;
    p.PQ1 = (const uint16_t*)PQ1; p.PK1 = (const uint16_t*)PK1; p.lg = lg;
    gemm_ca<LogitsP, false, true><<<dim3(13, 13, 16), 128, SMEMB>>>(p);
  }

  k_softmax<<<dim3(LP_, 16), 256>>>(lg, qtw, at1);

  {
    AVP p;
    p.M = LP_; p.N = 512; p.nch = 50; p.Kh = 0; p.sA = 1600; p.sB = 1600;
    p.at1 = (const uint16_t*)at1; p.PVt1 = (const uint16_t*)PVt1;
    p.PQ = PQ; p.st2b = st2b;
    gemm_ca<AVP, false, true><<<dim3(4, 13, 16), 128, SMEMB>>>(p);
  }

  {
    FinalP p;
    p.M = B_ * LP_; p.N = 512; p.nch = 64; p.Kh = 4096; p.sA = 8192;
    p.sB = 8192;
    p.st2b = (const uint16_t*)st2b; p.Wd2 = (const uint16_t*)Wd2; p.yp = yp;
    gemm_ca<FinalP, true, false><<<dim3(4, 25, 2), 128, SMEMB>>>(p);
  }

  k_ln<<<B_ * LP_, 256>>>(yp, bd, PX, gamma, beta, y);
}

// round 15
// speedup vs baseline: 1.8131x; 1.1802x over previous
#include <cuda_runtime.h>
#include <cuda_bf16.h>
#include <cuda_fp16.h>
#include <math.h>
#include <stdint.h>
#include <stddef.h>

// ---------------------------------------------------------------------------
// MultiHeadPooledAttention — mixed-precision HMMA GEMMs.
//   bf16 hi/lo 3-pass: Weff-Q, QtwX (positional+PX), Final
//   fp16 single-pass:  Weff-KV, PoolQ, PoolK, PoolV, Logits, attn·V
// Positional logits factored to weights: qtw = Xg·F, F = WeffQ^T·emb-basis
// (exact chain), added in a fused single-read softmax.
// ---------------------------------------------------------------------------

namespace {
constexpr int B_  = 2;
constexpr int L_  = 6273;   // 1 + 8*28*28
constexpr int NH_ = 8;
constexpr int LP_ = 1569;   // 1 + 8*14*14
constexpr int LPP_ = 1600;
constexpr int NB_ = 1568;
constexpr int LGLD_ = 1600;
constexpr float SCALE_ = 0.04419417382415922f;  // 512^-0.5

// fp32 scratch
constexpr size_t SZ_PQ  = (size_t)16 * LP_ * 512;
constexpr size_t SZ_PX  = (size_t)B_ * LP_ * 512;
constexpr size_t SZ_EMB = (size_t)NB_ * 512;
constexpr size_t SZ_BP  = (size_t)3 * 4096;
constexpr size_t SZ_LG  = (size_t)16 * LP_ * LGLD_;
constexpr size_t SZ_YP  = (size_t)2 * B_ * LP_ * 512;
constexpr size_t SZ_QTW = (size_t)16 * LP_ * 36;
constexpr size_t SZ_WQF = (size_t)4096 * 2048;

constexpr size_t OF_PQ  = 0;
constexpr size_t OF_PX  = OF_PQ + SZ_PQ;
constexpr size_t OF_EMB = OF_PX + SZ_PX;
constexpr size_t OF_BP  = OF_EMB + SZ_EMB;
constexpr size_t OF_LG  = OF_BP + SZ_BP;
constexpr size_t OF_YP  = OF_LG + SZ_LG;
constexpr size_t OF_QTW = OF_YP + SZ_YP;
constexpr size_t OF_WQF = OF_QTW + SZ_QTW;
constexpr size_t SZ_F32 = OF_WQF + SZ_WQF;

// bf16 hi/lo buffers (planar: hi at [0,Kh), lo at [Kh,2Kh), row stride 2Kh)
constexpr size_t SZB_WPT2 = (size_t)4 * 512 * 1024;   // Q pool taps
constexpr size_t SZB_WT2  = (size_t)8 * 512 * 1024;   // Wq heads (transposed)
constexpr size_t SZB_WD2  = (size_t)512 * 8192;
constexpr size_t SZB_WFX2 = (size_t)896 * 4096;       // F (384 rows) + WXe (512)
constexpr size_t SZB_XG2  = (size_t)3136 * 4096;
constexpr size_t SZB_ST2  = (size_t)B_ * LP_ * 8192;

constexpr size_t OB_WPT2 = 0;
constexpr size_t OB_WT2  = OB_WPT2 + SZB_WPT2;
constexpr size_t OB_WD2  = OB_WT2 + SZB_WT2;
constexpr size_t OB_WFX2 = OB_WD2 + SZB_WD2;
constexpr size_t OB_XG2  = OB_WFX2 + SZB_WFX2;
constexpr size_t OB_ST2  = OB_XG2 + SZB_XG2;
constexpr size_t SZ_BF   = OB_ST2 + SZB_ST2;

// fp16 single-plane buffers
constexpr size_t SZH_WPT1 = (size_t)8 * 512 * 512;    // K,V pool taps
constexpr size_t SZH_WT1  = (size_t)16 * 512 * 512;   // Wk,Wv heads
constexpr size_t SZH_WQ1  = (size_t)4096 * 2048;
constexpr size_t SZH_WK1  = (size_t)4096 * 2048;
constexpr size_t SZH_WV1  = (size_t)4096 * 2048;
constexpr size_t SZH_XG1  = (size_t)3136 * 2048;
constexpr size_t SZH_PQ1  = (size_t)16 * LP_ * 512;
constexpr size_t SZH_PK1  = (size_t)16 * LP_ * 512;
constexpr size_t SZH_PVT1 = (size_t)16 * 512 * 1600;
constexpr size_t SZH_AT1  = (size_t)16 * LP_ * 1600;

constexpr size_t OH_WPT1 = 0;
constexpr size_t OH_WT1  = OH_WPT1 + SZH_WPT1;
constexpr size_t OH_WQ1  = OH_WT1 + SZH_WT1;
constexpr size_t OH_WK1  = OH_WQ1 + SZH_WQ1;
constexpr size_t OH_WV1  = OH_WK1 + SZH_WK1;
constexpr size_t OH_XG1  = OH_WV1 + SZH_WV1;
constexpr size_t OH_PQ1  = OH_XG1 + SZH_XG1;
constexpr size_t OH_PK1  = OH_PQ1 + SZH_PQ1;
constexpr size_t OH_PVT1 = OH_PK1 + SZH_PK1;
constexpr size_t OH_AT1  = OH_PVT1 + SZH_PVT1;
constexpr size_t SZ_HF   = OH_AT1 + SZH_AT1;
}  // namespace

__device__ float g_scratch[SZ_F32];
__device__ __align__(16) __nv_bfloat16 g_bf[SZ_BF];
__device__ __align__(16) __half g_hf[SZ_HF];

// ------------------------------- PTX helpers -------------------------------

__device__ __forceinline__ uint32_t smem_u32(const void* p) {
  uint32_t a;
  asm("{ .reg .u64 t; cvta.to.shared.u64 t, %1; cvt.u32.u64 %0, t; }"
      : "=r"(a) : "l"(p));
  return a;
}

__device__ __forceinline__ void ldm4(uint32_t* d, uint32_t addr) {
  asm volatile("ldmatrix.sync.aligned.m8n8.x4.shared.b16 {%0,%1,%2,%3}, [%4];"
               : "=r"(d[0]), "=r"(d[1]), "=r"(d[2]), "=r"(d[3]) : "r"(addr));
}

__device__ __forceinline__ void mma_bf(float* c, const uint32_t* a,
                                       const uint32_t* b) {
  asm volatile(
      "mma.sync.aligned.m16n8k16.row.col.f32.bf16.bf16.f32 "
      "{%0,%1,%2,%3}, {%4,%5,%6,%7}, {%8,%9}, {%0,%1,%2,%3};"
      : "+f"(c[0]), "+f"(c[1]), "+f"(c[2]), "+f"(c[3])
      : "r"(a[0]), "r"(a[1]), "r"(a[2]), "r"(a[3]), "r"(b[0]), "r"(b[1]));
}
__device__ __forceinline__ void mma_fp(float* c, const uint32_t* a,
                                       const uint32_t* b) {
  asm volatile(
      "mma.sync.aligned.m16n8k16.row.col.f32.f16.f16.f32 "
      "{%0,%1,%2,%3}, {%4,%5,%6,%7}, {%8,%9}, {%0,%1,%2,%3};"
      : "+f"(c[0]), "+f"(c[1]), "+f"(c[2]), "+f"(c[3])
      : "r"(a[0]), "r"(a[1]), "r"(a[2]), "r"(a[3]), "r"(b[0]), "r"(b[1]));
}

__device__ __forceinline__ void cpa16(uint32_t dst, const void* src, bool ok) {
  int sz = ok ? 16 : 0;
  asm volatile("cp.async.cg.shared.global [%0], [%1], 16, %2;"
               :: "r"(dst), "l"(src), "r"(sz) : "memory");
}
__device__ __forceinline__ void cpa_commit() {
  asm volatile("cp.async.commit_group;" ::: "memory");
}
template <int N>
__device__ __forceinline__ void cpa_wait() {
  asm volatile("cp.async.wait_group %0;" :: "n"(N) : "memory");
}

__device__ __forceinline__ void st2(__nv_bfloat16* p, size_t i, size_t kh,
                                    float v) {
  __nv_bfloat16 h = __float2bfloat16(v);
  p[i] = h;
  p[i + kh] = __float2bfloat16(v - __bfloat162float(h));
}

// --------------------------- cp.async GEMM kernel ----------------------------

constexpr int ROWB = 80;
constexpr int TILEB = 128 * ROWB;
constexpr int STAGEB = 4 * TILEB;
constexpr int SMEMB = 2 * STAGEB;  // 81920

__device__ __forceinline__ void issue4(const uint16_t* S, int stride, int rmax,
                                       int r0, int kofs, uint32_t dstB,
                                       int tid) {
#pragma unroll
  for (int i = 0; i < 4; i++) {
    int idx = tid + 128 * i;
    int row = idx >> 2, q = idx & 3;
    int gr = r0 + row;
    bool ok = gr < rmax;
    const uint16_t* src = S + (size_t)(ok ? gr : 0) * stride + kofs + q * 8;
    cpa16(dstB + (uint32_t)(row * ROWB + q * 16), src, ok);
  }
}

template <typename P, bool SPLIT, bool FP16>
__global__ __launch_bounds__(128) void gemm_ca(P p) {
  extern __shared__ __align__(16) char sm[];
  uint32_t base = smem_u32(sm);

  const int tid = threadIdx.x;
  const int wid = tid >> 5, lane = tid & 31;
  const int wm = wid >> 1, wn = wid & 1;
  const int lj = lane >> 3, lr = lane & 7;

  const int z = blockIdx.z;
  const uint16_t* A = p.Aptr(z);
  const uint16_t* Bm = p.Bptr(z);
  const int M = p.M, N = p.N;
  const int m0 = blockIdx.y * 128, n0 = blockIdx.x * 128;
  const int nch = p.nch, Kh = p.Kh, sA = p.sA, sB = p.sB;
  const int kb = p.kbase(z);

  float acc[4][8][4];
#pragma unroll
  for (int a = 0; a < 4; a++)
#pragma unroll
    for (int b = 0; b < 8; b++)
#pragma unroll
      for (int c = 0; c < 4; c++) acc[a][b][c] = 0.f;

  const uint32_t aRow = (uint32_t)(wm * 64 + (lj & 1) * 8 + lr);
  const uint32_t aCol = (uint32_t)((lj >> 1) * 16);
  const uint32_t bRow = (uint32_t)(wn * 64 + (lj >> 1) * 8 + lr);
  const uint32_t bCol = (uint32_t)((lj & 1) * 16);

  {
    uint32_t st = base;
    issue4(A, sA, M, m0, kb, st, tid);
    if (SPLIT) issue4(A, sA, M, m0, Kh + kb, st + TILEB, tid);
    issue4(Bm, sB, N, n0, kb, st + 2 * TILEB, tid);
    if (SPLIT) issue4(Bm, sB, N, n0, Kh + kb, st + 3 * TILEB, tid);
    cpa_commit();
  }

  for (int ch = 0; ch < nch; ++ch) {
    int s = ch & 1;
    if (ch + 1 < nch) {
      int k0 = kb + (ch + 1) * 32;
      uint32_t st = base + (uint32_t)((1 - s) * STAGEB);
      issue4(A, sA, M, m0, k0, st, tid);
      if (SPLIT) issue4(A, sA, M, m0, Kh + k0, st + TILEB, tid);
      issue4(Bm, sB, N, n0, k0, st + 2 * TILEB, tid);
      if (SPLIT) issue4(Bm, sB, N, n0, Kh + k0, st + 3 * TILEB, tid);
      cpa_commit();
      cpa_wait<1>();
    } else {
      cpa_wait<0>();
    }
    __syncthreads();

    uint32_t stg = base + (uint32_t)(s * STAGEB);
    const int npass = SPLIT ? 3 : 1;
#pragma unroll 1
    for (int ps = 0; ps < npass; ps++) {
      uint32_t aT = stg + ((ps == 1) ? TILEB : 0);
      uint32_t bT = stg + 2 * TILEB + ((ps == 2) ? TILEB : 0);
#pragma unroll
      for (int ks = 0; ks < 2; ks++) {
        uint32_t afr[4][4];
#pragma unroll
        for (int mi = 0; mi < 4; mi++)
          ldm4(afr[mi], aT + (aRow + mi * 16) * ROWB + ks * 32 + aCol);
        uint32_t bfr[8][2];
#pragma unroll
        for (int nb = 0; nb < 4; nb++) {
          uint32_t t[4];
          ldm4(t, bT + (bRow + nb * 16) * ROWB + ks * 32 + bCol);
          bfr[2 * nb][0] = t[0];
          bfr[2 * nb][1] = t[1];
          bfr[2 * nb + 1][0] = t[2];
          bfr[2 * nb + 1][1] = t[3];
        }
#pragma unroll
        for (int mi = 0; mi < 4; mi++)
#pragma unroll
          for (int ni = 0; ni < 8; ni++) {
            if (FP16) mma_fp(acc[mi][ni], afr[mi], bfr[ni]);
            else      mma_bf(acc[mi][ni], afr[mi], bfr[ni]);
          }
      }
    }
    __syncthreads();
  }

  const int rr = lane >> 2, cc = (lane & 3) * 2;
#pragma unroll
  for (int mi = 0; mi < 4; mi++) {
#pragma unroll
    for (int ni = 0; ni < 8; ni++) {
      int rb = m0 + wm * 64 + mi * 16 + rr;
      int cb = n0 + wn * 64 + ni * 8 + cc;
      if (rb < M) {
        if (cb < N)     p.store(z, rb, cb,     acc[mi][ni][0]);
        if (cb + 1 < N) p.store(z, rb, cb + 1, acc[mi][ni][1]);
      }
      if (rb + 8 < M) {
        if (cb < N)     p.store(z, rb + 8, cb,     acc[mi][ni][2]);
        if (cb + 1 < N) p.store(z, rb + 8, cb + 1, acc[mi][ni][3]);
      }
    }
  }
}

// ----------------------------- GEMM problem defs ----------------------------

struct WeffQP {  // bf16 3-pass, z = n*4+t (32 blocks); outputs fp32 + fp16
  int M, N, nch, Kh, sA, sB;
  const uint16_t *wpT2, *Wt2;
  float* WQF;
  __half* WQ1;
  __device__ int kbase(int) const { return 0; }
  __device__ const uint16_t* Aptr(int z) const {
    return wpT2 + (size_t)(z & 3) * 512 * 1024;
  }
  __device__ const uint16_t* Bptr(int z) const {
    return Wt2 + (size_t)(z >> 2) * 512 * 1024;
  }
  __device__ void store(int z, int r, int c, float v) const {
    int n = z >> 2, t = z & 3;
    size_t idx = ((size_t)n * 512 + r) * 2048 + t * 512 + c;
    WQF[idx] = v;
    WQ1[idx] = __float2half(v);
  }
};

struct WeffKVP {  // fp16 1-pass, z = tv*32 + n*4 + t (64 blocks)
  int M, N, nch, Kh, sA, sB;
  const uint16_t *wpT1, *Wt1;
  __half *WK1, *WV1;
  __device__ int kbase(int) const { return 0; }
  __device__ const uint16_t* Aptr(int z) const {
    int tv = z >> 5, t = z & 3;
    return wpT1 + (size_t)(tv * 4 + t) * 512 * 512;
  }
  __device__ const uint16_t* Bptr(int z) const {
    int tv = z >> 5, n = (z & 31) >> 2;
    return Wt1 + (size_t)(tv * 8 + n) * 512 * 512;
  }
  __device__ void store(int z, int r, int c, float v) const {
    int tv = z >> 5, n = (z & 31) >> 2, t = z & 3;
    __half* dst = tv ? WV1 : WK1;
    dst[((size_t)n * 512 + r) * 2048 + t * 512 + c] = __float2half(v);
  }
};

struct QtwXP {  // bf16 3-pass: N=896 (F rows 0..383, WXe rows 384..895)
  int M, N, nch, Kh, sA, sB;
  const uint16_t *Xg2, *WFX2;
  float* qtw;
  float* PX;
  __device__ int kbase(int) const { return 0; }
  __device__ const uint16_t* Aptr(int) const { return Xg2; }
  __device__ const uint16_t* Bptr(int) const { return WFX2; }
  __device__ void store(int, int r, int c, float v) const {
    int b = r / NB_, o = r % NB_;
    if (c < 288) {
      int n = c / 36, j = c - n * 36;
      qtw[((size_t)(b * 8 + n) * LP_ + 1 + o) * 36 + j] = v;
    } else if (c >= 384) {
      PX[((size_t)b * LP_ + 1 + o) * 512 + (c - 384)] = v;
    }
  }
};

struct PoolQP {  // fp16 1-pass
  int M, N, nch, Kh, sA, sB;
  const uint16_t *Xg1, *WQ1;
  const float* bias;
  float* PQ;
  __half* PQ1;
  __device__ int kbase(int) const { return 0; }
  __device__ const uint16_t* Aptr(int) const { return Xg1; }
  __device__ const uint16_t* Bptr(int) const { return WQ1; }
  __device__ void store(int, int r, int c, float v) const {
    int b = r / NB_, o = r % NB_;
    v += bias[c];
    int n = c >> 9, d = c & 511;
    size_t idx = ((size_t)(b * 8 + n) * LP_ + 1 + o) * 512 + d;
    PQ[idx] = v;
    PQ1[idx] = __float2half(v);
  }
};

struct PoolKP {  // fp16 1-pass
  int M, N, nch, Kh, sA, sB;
  const uint16_t *Xg1, *WK1;
  const float* bias;
  __half* PK1;
  __device__ int kbase(int) const { return 0; }
  __device__ const uint16_t* Aptr(int) const { return Xg1; }
  __device__ const uint16_t* Bptr(int) const { return WK1; }
  __device__ void store(int, int r, int c, float v) const {
    int b = r / NB_, o = r % NB_;
    v += bias[c];
    int n = c >> 9, d = c & 511;
    PK1[((size_t)(b * 8 + n) * LP_ + 1 + o) * 512 + d] = __float2half(v);
  }
};

struct PoolVP {  // fp16 1-pass -> transposed fp16 PVt1
  int M, N, nch, Kh, sA, sB;
  const uint16_t *Xg1, *WV1;
  const float* bias;
  __half* PVt1;
  __device__ int kbase(int) const { return 0; }
  __device__ const uint16_t* Aptr(int) const { return Xg1; }
  __device__ const uint16_t* Bptr(int) const { return WV1; }
  __device__ void store(int, int r, int c, float v) const {
    int b = r / NB_, o = r % NB_;
    v += bias[c];
    int n = c >> 9, d = c & 511;
    PVt1[((size_t)(b * 8 + n) * 512 + d) * 1600 + 1 + o] = __float2half(v);
  }
};

struct LogitsP {  // fp16 1-pass, raw PQ·PK^T (scale + qr applied in softmax)
  int M, N, nch, Kh, sA, sB;
  const uint16_t *PQ1, *PK1;
  float* lg;
  __device__ int kbase(int) const { return 0; }
  __device__ const uint16_t* Aptr(int z) const {
    return PQ1 + (size_t)z * LP_ * 512;
  }
  __device__ const uint16_t* Bptr(int z) const {
    return PK1 + (size_t)z * LP_ * 512;
  }
  __device__ void store(int z, int r, int c, float v) const {
    lg[(size_t)z * LP_ * LGLD_ + (size_t)r * LGLD_ + c] = v;
  }
};

struct AVP {  // fp16 1-pass
  int M, N, nch, Kh, sA, sB;
  const uint16_t *at1, *PVt1;
  const float* PQ;
  __nv_bfloat16* st2b;
  __device__ int kbase(int) const { return 0; }
  __device__ const uint16_t* Aptr(int z) const {
    return at1 + (size_t)z * LP_ * 1600;
  }
  __device__ const uint16_t* Bptr(int z) const {
    return PVt1 + (size_t)z * 512 * 1600;
  }
  __device__ void store(int z, int r, int c, float v) const {
    float pq = PQ[(size_t)z * LP_ * 512 + (size_t)r * 512 + c];
    v += (r > 0 ? 2.f : 1.f) * pq;
    int b = z >> 3, n = z & 7;
    st2(st2b, ((size_t)b * LP_ + r) * 8192 + n * 512 + c, 4096, v);
  }
};

struct FinalP {  // bf16 3-pass, split-K=2
  int M, N, nch, Kh, sA, sB;
  const uint16_t *st2b, *Wd2;
  float* yp;
  __device__ int kbase(int z) const { return z * 2048; }
  __device__ const uint16_t* Aptr(int) const { return st2b; }
  __device__ const uint16_t* Bptr(int) const { return Wd2; }
  __device__ void store(int z, int r, int c, float v) const {
    yp[(size_t)z * B_ * LP_ * 512 + (size_t)r * 512 + c] = v;
  }
};

// ------------------------------ helper kernels ------------------------------

__global__ void k_wpT(const float* wpq, const float* wpk, const float* wpv,
                      __nv_bfloat16* wpT2, __half* wpT1) {
  size_t idx = (size_t)blockIdx.x * blockDim.x + threadIdx.x;
  if (idx >= (size_t)3 * 512 * 512 * 4) return;
  int ti = (int)(idx / (512 * 512 * 4));
  int r = (int)(idx % (512 * 512 * 4));
  int c = r / 2048;
  int d = (r % 2048) >> 2;
  int t = r & 3;
  const float* wp = (ti == 0) ? wpq : ((ti == 1) ? wpk : wpv);
  float v = wp[r];
  if (ti == 0)
    st2(wpT2, ((size_t)t * 512 + c) * 1024 + d, 512, v);
  else
    wpT1[((size_t)((ti - 1) * 4 + t) * 512 + c) * 512 + d] = __float2half(v);
}

__global__ void k_wt(const float* Wq, const float* Wk, const float* Wv,
                     __nv_bfloat16* Wt2, __half* Wt1) {
  size_t idx = (size_t)blockIdx.x * blockDim.x + threadIdx.x;
  if (idx >= (size_t)3 * 8 * 512 * 512) return;
  int d = (int)(idx & 511);
  int m = (int)((idx >> 9) & 511);
  int n = (int)((idx >> 18) & 7);
  int ti = (int)(idx >> 21);
  const float* W = (ti == 0) ? Wq : ((ti == 1) ? Wk : Wv);
  float v = W[(size_t)(n * 512 + d) * 512 + m];
  if (ti == 0)
    st2(Wt2, ((size_t)n * 512 + m) * 1024 + d, 512, v);
  else
    Wt1[((size_t)((ti - 1) * 8 + n) * 512 + m) * 512 + d] = __float2half(v);
}

// WXe rows into WFX2 at rows 384..895
__global__ void k_wxe2(const float* wpx, __nv_bfloat16* WFX2) {
  size_t idx = (size_t)blockIdx.x * blockDim.x + threadIdx.x;
  if (idx >= (size_t)512 * 2048) return;
  int c = (int)(idx >> 11);
  int col = (int)(idx & 2047);
  int t = col >> 9, m = col & 511;
  float v = wpx[(size_t)c * 2048 + m * 4 + t];
  st2(WFX2, (size_t)(384 + c) * 4096 + col, 2048, v);
}

// F rows 0..383 of WFX2: F[n*36+j, k] = sum_d WQF[n*512+d, k] * e_j[d]
__global__ void k_F(const float* WQF, const float* emb, __nv_bfloat16* WFX2) {
  size_t idx = (size_t)blockIdx.x * blockDim.x + threadIdx.x;
  if (idx >= (size_t)384 * 2048) return;
  int k = (int)(idx & 2047);
  int nj = (int)(idx >> 11);
  float s = 0.f;
  if (nj < 288) {
    int n = nj / 36, j = nj - n * 36;
    int d0, dn, kk;
    if (j < 8)       { d0 = 0;   dn = 170; kk = j * 196; }
    else if (j < 22) { d0 = 170; dn = 170; kk = (j - 8) * 14; }
    else             { d0 = 340; dn = 172; kk = j - 22; }
    const float* e = emb + (size_t)kk * 512 + d0;
    const float* w = WQF + (size_t)(n * 512 + d0) * 2048 + k;
    for (int d = 0; d < dn; d++) s += w[(size_t)d * 2048] * e[d];
  }
  st2(WFX2, (size_t)nj * 4096 + k, 2048, s);
}

__global__ void k_wd2(const float* Wd, __nv_bfloat16* Wd2) {
  size_t idx = (size_t)blockIdx.x * blockDim.x + threadIdx.x;
  if (idx >= (size_t)512 * 4096) return;
  int c = (int)(idx >> 12), k = (int)(idx & 4095);
  st2(Wd2, (size_t)c * 8192 + k, 4096, Wd[idx]);
}

__global__ void k_bpool(const float* wpq, const float* wpk, const float* wpv,
                        const float* bq, const float* bk, const float* bv,
                        float* bpool) {
  int j = blockIdx.x * blockDim.x + threadIdx.x;
  if (j >= 3 * 4096) return;
  int ti = j / 4096, h = j % 4096, n = h >> 9, c = h & 511;
  const float* wp = (ti == 0) ? wpq : ((ti == 1) ? wpk : wpv);
  const float* b = (ti == 0) ? bq : ((ti == 1) ? bk : bv);
  float s = 0.f;
  for (int d = 0; d < 512; d++) {
    float bb = b[n * 512 + d];
    const float* w = wp + (size_t)c * 2048 + d * 4;
    s += (w[0] + w[1] + w[2] + w[3]) * bb;
  }
  bpool[j] = s;
}

__global__ void k_gather2(const float* x, __nv_bfloat16* Xg2, __half* Xg1) {
  size_t idx = (size_t)blockIdx.x * blockDim.x + threadIdx.x;
  if (idx >= (size_t)3136 * 2048) return;
  int r = (int)(idx >> 11);
  int col = (int)(idx & 2047);
  int t = col >> 9, m = col & 511;
  int b = r / NB_, o = r % NB_;
  int t2 = o / 196, hh = (o / 14) % 14, ww = o % 14;
  int kh = t >> 1, kw = t & 1;
  int row = 1 + (t2 * 28 + 2 * hh + kh) * 28 + 2 * ww + kw;
  float v = x[((size_t)b * L_ + row) * 512 + m];
  st2(Xg2, (size_t)r * 4096 + col, 2048, v);
  Xg1[(size_t)r * 2048 + col] = __float2half(v);
}

__global__ void k_padpv(__half* PVt1) {
  int idx = blockIdx.x * blockDim.x + threadIdx.x;
  if (idx >= 16 * 512 * 31) return;
  int j = idx % 31;
  int rc = idx / 31;
  PVt1[(size_t)rc * 1600 + LP_ + j] = __float2half(0.f);
}

__global__ void k_cls(const float* x, const float* Wq, const float* bq,
                      const float* Wk, const float* bk, const float* Wv,
                      const float* bv, float* PQ, float* PX, __half* PQ1,
                      __half* PK1, __half* PVt1) {
  int idx = blockIdx.x * blockDim.x + threadIdx.x;
  if (idx < 2 * 12288) {
    int b = idx / 12288, j = idx % 12288, ti = j / 4096, jj = j & 4095;
    const float* W = (ti == 0) ? Wq : ((ti == 1) ? Wk : Wv);
    const float* bias = (ti == 0) ? bq : ((ti == 1) ? bk : bv);
    const float* xr = x + (size_t)b * L_ * 512;
    const float* wr = W + (size_t)jj * 512;
    float s = bias[jj];
    for (int m = 0; m < 512; m++) s += xr[m] * wr[m];
    int n = jj >> 9, c = jj & 511;
    int zz = b * 8 + n;
    if (ti == 0) {
      PQ[(size_t)zz * LP_ * 512 + c] = s;
      PQ1[(size_t)zz * LP_ * 512 + c] = __float2half(s);
    } else if (ti == 1) {
      PK1[(size_t)zz * LP_ * 512 + c] = __float2half(s);
    } else {
      PVt1[((size_t)zz * 512 + c) * 1600 + 0] = __float2half(s);
    }
  } else if (idx < 2 * 12288 + 2 * 512) {
    int k = idx - 2 * 12288;
    int b = k >> 9, c = k & 511;
    PX[(size_t)b * LP_ * 512 + c] = x[(size_t)b * L_ * 512 + c];
  }
}

__device__ __forceinline__ float sincos_val(int pos, int c, int dim) {
  int half = dim / 2;
  bool is_cos = c >= half;
  int i = is_cos ? c - half : c;
  float omega = powf(10000.f, -((float)i) / (float)half);
  float ang = (float)pos * omega;
  return is_cos ? cosf(ang) : sinf(ang);
}

__global__ void k_emb(float* emb) {
  size_t idx = (size_t)blockIdx.x * blockDim.x + threadIdx.x;
  if (idx >= SZ_EMB) return;
  int k = (int)(idx >> 9);
  int c = (int)(idx & 511);
  int t2 = k / 196, h2 = (k / 14) % 14, w2 = k % 14;
  float v;
  if (c < 170) v = sincos_val(t2, c, 170);
  else if (c < 340) v = sincos_val(h2, c - 170, 170);
  else v = sincos_val(w2, c - 340, 172);
  emb[idx] = v;
}

// Fused softmax: single global read of logits row into SMEM, single at1 write.
__global__ void k_softmax(const float* lg, const float* qtw, __half* at1) {
  int z = blockIdx.y, q = blockIdx.x;
  const float* row = lg + ((size_t)z * LP_ + q) * LGLD_;
  __half* arow = at1 + ((size_t)z * LP_ + q) * 1600;
  int tid = threadIdx.x;
  __shared__ float sr[LPP_];
  __shared__ float red[256];
  __shared__ float qv[36];
  if (tid < 36) qv[tid] = (q > 0) ? qtw[((size_t)z * LP_ + q) * 36 + tid] : 0.f;
  __syncthreads();
  float mx = -1e30f;
  for (int i = tid; i < LP_; i += 256) {
    float l = SCALE_ * row[i];
    if (q > 0 && i > 0) {
      int k = i - 1;
      int t2 = k / 196;
      int rm = k - t2 * 196;
      int h2 = rm / 14;
      int w2 = rm - h2 * 14;
      l += qv[t2] + qv[8 + h2] + qv[22 + w2];
    }
    sr[i] = l;
    mx = fmaxf(mx, l);
  }
  red[tid] = mx;
  __syncthreads();
  for (int s = 128; s > 0; s >>= 1) {
    if (tid < s) red[tid] = fmaxf(red[tid], red[tid + s]);
    __syncthreads();
  }
  mx = red[0];
  __syncthreads();
  float sum = 0.f;
  for (int i = tid; i < LP_; i += 256) {
    float e = expf(sr[i] - mx);
    sr[i] = e;
    sum += e;
  }
  red[tid] = sum;
  __syncthreads();
  for (int s = 128; s > 0; s >>= 1) {
    if (tid < s) red[tid] += red[tid + s];
    __syncthreads();
  }
  float inv = 1.f / red[0];
  for (int i = tid; i < LPP_; i += 256) {
    float v = (i < LP_) ? sr[i] * inv : 0.f;
    arow[i] = __float2half(v);
  }
}

__global__ void k_ln(const float* yp, const float* bd, const float* PX,
                     const float* gamma, const float* beta, float* y) {
  int row = blockIdx.x;
  const float* y0 = yp + (size_t)row * 512;
  const float* y1 = yp + (size_t)B_ * LP_ * 512 + (size_t)row * 512;
  const float* px = PX + (size_t)row * 512;
  float* yr = y + (size_t)row * 512;
  int tid = threadIdx.x;
  float v0 = y0[tid] + y1[tid] + bd[tid] + px[tid];
  float v1 = y0[tid + 256] + y1[tid + 256] + bd[tid + 256] + px[tid + 256];
  __shared__ float red[256];
  red[tid] = v0 + v1;
  __syncthreads();
  for (int s = 128; s > 0; s >>= 1) {
    if (tid < s) red[tid] += red[tid + s];
    __syncthreads();
  }
  float mu = red[0] * (1.f / 512.f);
  __syncthreads();
  float d0 = v0 - mu, d1 = v1 - mu;
  red[tid] = d0 * d0 + d1 * d1;
  __syncthreads();
  for (int s = 128; s > 0; s >>= 1) {
    if (tid < s) red[tid] += red[tid + s];
    __syncthreads();
  }
  float inv = rsqrtf(red[0] * (1.f / 512.f) + 1e-5f);
  yr[tid] = d0 * inv * gamma[tid] + beta[tid];
  yr[tid + 256] = d1 * inv * gamma[tid + 256] + beta[tid + 256];
}

// --------------------------------- launcher ---------------------------------

extern "C" void kernel_launch(void* const* d_in, const int* in_sizes, int n_in,
                              void* d_out, int out_size) {
  (void)in_sizes; (void)n_in; (void)out_size;
  const float* x   = (const float*)d_in[0];
  const float* Wq  = (const float*)d_in[1];
  const float* bq  = (const float*)d_in[2];
  const float* Wk  = (const float*)d_in[3];
  const float* bk  = (const float*)d_in[4];
  const float* Wv  = (const float*)d_in[5];
  const float* bv  = (const float*)d_in[6];
  const float* wpq = (const float*)d_in[7];
  const float* wpk = (const float*)d_in[8];
  const float* wpv = (const float*)d_in[9];
  const float* wpx = (const float*)d_in[10];
  const float* Wd  = (const float*)d_in[11];
  const float* bd  = (const float*)d_in[12];
  const float* gamma = (const float*)d_in[13];
  const float* beta  = (const float*)d_in[14];
  float* y = (float*)d_out;

  float* S = nullptr;
  cudaGetSymbolAddress((void**)&S, g_scratch);
  __nv_bfloat16* Bf = nullptr;
  cudaGetSymbolAddress((void**)&Bf, g_bf);
  __half* Hf = nullptr;
  cudaGetSymbolAddress((void**)&Hf, g_hf);

  float* PQ    = S + OF_PQ;
  float* PX    = S + OF_PX;
  float* emb   = S + OF_EMB;
  float* bpool = S + OF_BP;
  float* lg    = S + OF_LG;
  float* yp    = S + OF_YP;
  float* qtw   = S + OF_QTW;
  float* WQF   = S + OF_WQF;

  __nv_bfloat16* wpT2 = Bf + OB_WPT2;
  __nv_bfloat16* Wt2  = Bf + OB_WT2;
  __nv_bfloat16* Wd2  = Bf + OB_WD2;
  __nv_bfloat16* WFX2 = Bf + OB_WFX2;
  __nv_bfloat16* Xg2  = Bf + OB_XG2;
  __nv_bfloat16* st2b = Bf + OB_ST2;

  __half* wpT1 = Hf + OH_WPT1;
  __half* Wt1  = Hf + OH_WT1;
  __half* WQ1  = Hf + OH_WQ1;
  __half* WK1  = Hf + OH_WK1;
  __half* WV1  = Hf + OH_WV1;
  __half* Xg1  = Hf + OH_XG1;
  __half* PQ1  = Hf + OH_PQ1;
  __half* PK1  = Hf + OH_PK1;
  __half* PVt1 = Hf + OH_PVT1;
  __half* at1  = Hf + OH_AT1;

  cudaFuncSetAttribute(gemm_ca<WeffQP, true, false>,
                       cudaFuncAttributeMaxDynamicSharedMemorySize, SMEMB);
  cudaFuncSetAttribute(gemm_ca<WeffKVP, false, true>,
                       cudaFuncAttributeMaxDynamicSharedMemorySize, SMEMB);
  cudaFuncSetAttribute(gemm_ca<QtwXP, true, false>,
                       cudaFuncAttributeMaxDynamicSharedMemorySize, SMEMB);
  cudaFuncSetAttribute(gemm_ca<PoolQP, false, true>,
                       cudaFuncAttributeMaxDynamicSharedMemorySize, SMEMB);
  cudaFuncSetAttribute(gemm_ca<PoolKP, false, true>,
                       cudaFuncAttributeMaxDynamicSharedMemorySize, SMEMB);
  cudaFuncSetAttribute(gemm_ca<PoolVP, false, true>,
                       cudaFuncAttributeMaxDynamicSharedMemorySize, SMEMB);
  cudaFuncSetAttribute(gemm_ca<LogitsP, false, true>,
                       cudaFuncAttributeMaxDynamicSharedMemorySize, SMEMB);
  cudaFuncSetAttribute(gemm_ca<AVP, false, true>,
                       cudaFuncAttributeMaxDynamicSharedMemorySize, SMEMB);
  cudaFuncSetAttribute(gemm_ca<FinalP, true, false>,
                       cudaFuncAttributeMaxDynamicSharedMemorySize, SMEMB);

  // converters
  k_wpT<<<(int)((3u * 512 * 512 * 4 + 255) / 256), 256>>>(wpq, wpk, wpv, wpT2,
                                                          wpT1);
  k_wt<<<(int)((3u * 8 * 512 * 512 + 255) / 256), 256>>>(Wq, Wk, Wv, Wt2, Wt1);
  k_wxe2<<<(512 * 2048 + 255) / 256, 256>>>(wpx, WFX2);
  k_wd2<<<(512 * 4096 + 255) / 256, 256>>>(Wd, Wd2);
  k_bpool<<<(3 * 4096 + 255) / 256, 256>>>(wpq, wpk, wpv, bq, bk, bv, bpool);
  k_gather2<<<(int)((3136u * 2048 + 255) / 256), 256>>>(x, Xg2, Xg1);
  k_padpv<<<(16 * 512 * 31 + 255) / 256, 256>>>(PVt1);
  k_emb<<<(int)((SZ_EMB + 255) / 256), 256>>>(emb);

  {
    WeffQP p;
    p.M = 512; p.N = 512; p.nch = 16; p.Kh = 512; p.sA = 1024; p.sB = 1024;
    p.wpT2 = (const uint16_t*)wpT2; p.Wt2 = (const uint16_t*)Wt2;
    p.WQF = WQF; p.WQ1 = WQ1;
    gemm_ca<WeffQP, true, false><<<dim3(4, 4, 32), 128, SMEMB>>>(p);
  }
  {
    WeffKVP p;
    p.M = 512; p.N = 512; p.nch = 16; p.Kh = 0; p.sA = 512; p.sB = 512;
    p.wpT1 = (const uint16_t*)wpT1; p.Wt1 = (const uint16_t*)Wt1;
    p.WK1 = WK1; p.WV1 = WV1;
    gemm_ca<WeffKVP, false, true><<<dim3(4, 4, 64), 128, SMEMB>>>(p);
  }

  k_F<<<(int)((384u * 2048 + 255) / 256), 256>>>(WQF, emb, WFX2);

  {
    QtwXP p;
    p.M = 3136; p.N = 896; p.nch = 64; p.Kh = 2048; p.sA = 4096; p.sB = 4096;
    p.Xg2 = (const uint16_t*)Xg2; p.WFX2 = (const uint16_t*)WFX2;
    p.qtw = qtw; p.PX = PX;
    gemm_ca<QtwXP, true, false><<<dim3(7, 25, 1), 128, SMEMB>>>(p);
  }
  {
    PoolQP p;
    p.M = 3136; p.N = 4096; p.nch = 64; p.Kh = 0; p.sA = 2048; p.sB = 2048;
    p.Xg1 = (const uint16_t*)Xg1; p.WQ1 = (const uint16_t*)WQ1;
    p.bias = bpool; p.PQ = PQ; p.PQ1 = PQ1;
    gemm_ca<PoolQP, false, true><<<dim3(32, 25, 1), 128, SMEMB>>>(p);
  }
  {
    PoolKP p;
    p.M = 3136; p.N = 4096; p.nch = 64; p.Kh = 0; p.sA = 2048; p.sB = 2048;
    p.Xg1 = (const uint16_t*)Xg1; p.WK1 = (const uint16_t*)WK1;
    p.bias = bpool + 4096; p.PK1 = PK1;
    gemm_ca<PoolKP, false, true><<<dim3(32, 25, 1), 128, SMEMB>>>(p);
  }
  {
    PoolVP p;
    p.M = 3136; p.N = 4096; p.nch = 64; p.Kh = 0; p.sA = 2048; p.sB = 2048;
    p.Xg1 = (const uint16_t*)Xg1; p.WV1 = (const uint16_t*)WV1;
    p.bias = bpool + 8192; p.PVt1 = PVt1;
    gemm_ca<PoolVP, false, true><<<dim3(32, 25, 1), 128, SMEMB>>>(p);
  }

  k_cls<<<(2 * 12288 + 2 * 512 + 255) / 256, 256>>>(x, Wq, bq, Wk, bk, Wv, bv,
                                                    PQ, PX, PQ1, PK1, PVt1);

  {
    LogitsP p;
    p.M = LP_; p.N = LP_; p.nch = 16; p.Kh = 0; p.sA = 512; p.sB = 512;
    p.PQ1 = (const uint16_t*)PQ1; p.PK1 = (const uint16_t*)PK1; p.lg = lg;
    gemm_ca<LogitsP, false, true><<<dim3(13, 13, 16), 128, SMEMB>>>(p);
  }

  k_softmax<<<dim3(LP_, 16), 256>>>(lg, qtw, at1);

  {
    AVP p;
    p.M = LP_; p.N = 512; p.nch = 50; p.Kh = 0; p.sA = 1600; p.sB = 1600;
    p.at1 = (const uint16_t*)at1; p.PVt1 = (const uint16_t*)PVt1;
    p.PQ = PQ; p.st2b = st2b;
    gemm_ca<AVP, false, true><<<dim3(4, 13, 16), 128, SMEMB>>>(p);
  }

  {
    FinalP p;
    p.M = B_ * LP_; p.N = 512; p.nch = 64; p.Kh = 4096; p.sA = 8192;
    p.sB = 8192;
    p.st2b = (const uint16_t*)st2b; p.Wd2 = (const uint16_t*)Wd2; p.yp = yp;
    gemm_ca<FinalP, true, false><<<dim3(4, 25, 2), 128, SMEMB>>>(p);
  }

  k_ln<<<B_ * LP_, 256>>>(yp, bd, PX, gamma, beta, y);
}

// round 16
// speedup vs baseline: 1.8286x; 1.0086x over previous
#include <cuda_runtime.h>
#include <cuda_bf16.h>
#include <cuda_fp16.h>
#include <math.h>
#include <stdint.h>
#include <stddef.h>

// ---------------------------------------------------------------------------
// MultiHeadPooledAttention — mixed-precision HMMA GEMMs.
//   bf16 hi/lo 3-pass (2-stage pipe): Weff-Q, QtwX (positional+PX), Final
//   fp16 single-pass (4-stage pipe): Weff-KV, PoolQKV (merged), Logits, attn·V
// qr factored to weights (exact chain), added in fused softmax.
// ---------------------------------------------------------------------------

namespace {
constexpr int B_  = 2;
constexpr int L_  = 6273;   // 1 + 8*28*28
constexpr int NH_ = 8;
constexpr int LP_ = 1569;   // 1 + 8*14*14
constexpr int LPP_ = 1600;
constexpr int NB_ = 1568;
constexpr int LGLD_ = 1600;
constexpr float SCALE_ = 0.04419417382415922f;  // 512^-0.5

// fp32 scratch
constexpr size_t SZ_PQ  = (size_t)16 * LP_ * 512;
constexpr size_t SZ_PX  = (size_t)B_ * LP_ * 512;
constexpr size_t SZ_EMB = (size_t)NB_ * 512;
constexpr size_t SZ_BP  = (size_t)3 * 4096;
constexpr size_t SZ_LG  = (size_t)16 * LP_ * LGLD_;
constexpr size_t SZ_YP  = (size_t)2 * B_ * LP_ * 512;
constexpr size_t SZ_QTW = (size_t)16 * LP_ * 36;
constexpr size_t SZ_WQF = (size_t)4096 * 2048;

constexpr size_t OF_PQ  = 0;
constexpr size_t OF_PX  = OF_PQ + SZ_PQ;
constexpr size_t OF_EMB = OF_PX + SZ_PX;
constexpr size_t OF_BP  = OF_EMB + SZ_EMB;
constexpr size_t OF_LG  = OF_BP + SZ_BP;
constexpr size_t OF_YP  = OF_LG + SZ_LG;
constexpr size_t OF_QTW = OF_YP + SZ_YP;
constexpr size_t OF_WQF = OF_QTW + SZ_QTW;
constexpr size_t SZ_F32 = OF_WQF + SZ_WQF;

// bf16 hi/lo buffers (planar: hi at [0,Kh), lo at [Kh,2Kh), row stride 2Kh)
constexpr size_t SZB_WPT2 = (size_t)4 * 512 * 1024;
constexpr size_t SZB_WT2  = (size_t)8 * 512 * 1024;
constexpr size_t SZB_WD2  = (size_t)512 * 8192;
constexpr size_t SZB_WFX2 = (size_t)896 * 4096;   // F (384 rows) + WXe (512)
constexpr size_t SZB_XG2  = (size_t)3136 * 4096;
constexpr size_t SZB_ST2  = (size_t)B_ * LP_ * 8192;

constexpr size_t OB_WPT2 = 0;
constexpr size_t OB_WT2  = OB_WPT2 + SZB_WPT2;
constexpr size_t OB_WD2  = OB_WT2 + SZB_WT2;
constexpr size_t OB_WFX2 = OB_WD2 + SZB_WD2;
constexpr size_t OB_XG2  = OB_WFX2 + SZB_WFX2;
constexpr size_t OB_ST2  = OB_XG2 + SZB_XG2;
constexpr size_t SZ_BF   = OB_ST2 + SZB_ST2;

// fp16 single-plane buffers (WQ1/WK1/WV1 contiguous => merged PoolQKV B)
constexpr size_t SZH_WPT1 = (size_t)8 * 512 * 512;
constexpr size_t SZH_WT1  = (size_t)16 * 512 * 512;
constexpr size_t SZH_WQ1  = (size_t)4096 * 2048;
constexpr size_t SZH_WK1  = (size_t)4096 * 2048;
constexpr size_t SZH_WV1  = (size_t)4096 * 2048;
constexpr size_t SZH_XG1  = (size_t)3136 * 2048;
constexpr size_t SZH_PQ1  = (size_t)16 * LP_ * 512;
constexpr size_t SZH_PK1  = (size_t)16 * LP_ * 512;
constexpr size_t SZH_PVT1 = (size_t)16 * 512 * 1600;
constexpr size_t SZH_AT1  = (size_t)16 * LP_ * 1600;

constexpr size_t OH_WPT1 = 0;
constexpr size_t OH_WT1  = OH_WPT1 + SZH_WPT1;
constexpr size_t OH_WQ1  = OH_WT1 + SZH_WT1;
constexpr size_t OH_WK1  = OH_WQ1 + SZH_WQ1;
constexpr size_t OH_WV1  = OH_WK1 + SZH_WK1;
constexpr size_t OH_XG1  = OH_WV1 + SZH_WV1;
constexpr size_t OH_PQ1  = OH_XG1 + SZH_XG1;
constexpr size_t OH_PK1  = OH_PQ1 + SZH_PQ1;
constexpr size_t OH_PVT1 = OH_PK1 + SZH_PK1;
constexpr size_t OH_AT1  = OH_PVT1 + SZH_PVT1;
constexpr size_t SZ_HF   = OH_AT1 + SZH_AT1;
}  // namespace

__device__ float g_scratch[SZ_F32];
__device__ __align__(16) __nv_bfloat16 g_bf[SZ_BF];
__device__ __align__(16) __half g_hf[SZ_HF];

// ------------------------------- PTX helpers -------------------------------

__device__ __forceinline__ uint32_t smem_u32(const void* p) {
  uint32_t a;
  asm("{ .reg .u64 t; cvta.to.shared.u64 t, %1; cvt.u32.u64 %0, t; }"
      : "=r"(a) : "l"(p));
  return a;
}

__device__ __forceinline__ void ldm4(uint32_t* d, uint32_t addr) {
  asm volatile("ldmatrix.sync.aligned.m8n8.x4.shared.b16 {%0,%1,%2,%3}, [%4];"
               : "=r"(d[0]), "=r"(d[1]), "=r"(d[2]), "=r"(d[3]) : "r"(addr));
}

__device__ __forceinline__ void mma_bf(float* c, const uint32_t* a,
                                       const uint32_t* b) {
  asm volatile(
      "mma.sync.aligned.m16n8k16.row.col.f32.bf16.bf16.f32 "
      "{%0,%1,%2,%3}, {%4,%5,%6,%7}, {%8,%9}, {%0,%1,%2,%3};"
      : "+f"(c[0]), "+f"(c[1]), "+f"(c[2]), "+f"(c[3])
      : "r"(a[0]), "r"(a[1]), "r"(a[2]), "r"(a[3]), "r"(b[0]), "r"(b[1]));
}
__device__ __forceinline__ void mma_fp(float* c, const uint32_t* a,
                                       const uint32_t* b) {
  asm volatile(
      "mma.sync.aligned.m16n8k16.row.col.f32.f16.f16.f32 "
      "{%0,%1,%2,%3}, {%4,%5,%6,%7}, {%8,%9}, {%0,%1,%2,%3};"
      : "+f"(c[0]), "+f"(c[1]), "+f"(c[2]), "+f"(c[3])
      : "r"(a[0]), "r"(a[1]), "r"(a[2]), "r"(a[3]), "r"(b[0]), "r"(b[1]));
}

__device__ __forceinline__ void cpa16(uint32_t dst, const void* src, bool ok) {
  int sz = ok ? 16 : 0;
  asm volatile("cp.async.cg.shared.global [%0], [%1], 16, %2;"
               :: "r"(dst), "l"(src), "r"(sz) : "memory");
}
__device__ __forceinline__ void cpa_commit() {
  asm volatile("cp.async.commit_group;" ::: "memory");
}
template <int N>
__device__ __forceinline__ void cpa_wait() {
  asm volatile("cp.async.wait_group %0;" :: "n"(N) : "memory");
}

__device__ __forceinline__ void st2(__nv_bfloat16* p, size_t i, size_t kh,
                                    float v) {
  __nv_bfloat16 h = __float2bfloat16(v);
  p[i] = h;
  p[i + kh] = __float2bfloat16(v - __bfloat162float(h));
}

// --------------------------- cp.async GEMM kernel ----------------------------
// FP16: 4-stage pipeline, 2 planes/stage. SPLIT(bf16-3): 2-stage, 4 planes.

constexpr int ROWB = 80;
constexpr int TILEB = 128 * ROWB;
constexpr int SMEMB = 8 * TILEB;  // 81920 both configs

__device__ __forceinline__ void issue4(const uint16_t* S, int stride, int rmax,
                                       int r0, int kofs, uint32_t dstB,
                                       int tid) {
#pragma unroll
  for (int i = 0; i < 4; i++) {
    int idx = tid + 128 * i;
    int row = idx >> 2, q = idx & 3;
    int gr = r0 + row;
    bool ok = gr < rmax;
    const uint16_t* src = S + (size_t)(ok ? gr : 0) * stride + kofs + q * 8;
    cpa16(dstB + (uint32_t)(row * ROWB + q * 16), src, ok);
  }
}

template <typename P, bool SPLIT, bool FP16>
__global__ __launch_bounds__(128) void gemm_ca(P p) {
  extern __shared__ __align__(16) char sm[];
  uint32_t base = smem_u32(sm);

  constexpr int NST = FP16 ? 4 : 2;
  constexpr int STB = FP16 ? 2 * TILEB : 4 * TILEB;

  const int tid = threadIdx.x;
  const int wid = tid >> 5, lane = tid & 31;
  const int wm = wid >> 1, wn = wid & 1;
  const int lj = lane >> 3, lr = lane & 7;

  const int z = blockIdx.z;
  const uint16_t* A = p.Aptr(z);
  const uint16_t* Bm = p.Bptr(z);
  const int M = p.M, N = p.N;
  const int m0 = blockIdx.y * 128, n0 = blockIdx.x * 128;
  const int nch = p.nch, Kh = p.Kh, sA = p.sA, sB = p.sB;
  const int kb = p.kbase(z);

  float acc[4][8][4];
#pragma unroll
  for (int a = 0; a < 4; a++)
#pragma unroll
    for (int b = 0; b < 8; b++)
#pragma unroll
      for (int c = 0; c < 4; c++) acc[a][b][c] = 0.f;

  const uint32_t aRow = (uint32_t)(wm * 64 + (lj & 1) * 8 + lr);
  const uint32_t aCol = (uint32_t)((lj >> 1) * 16);
  const uint32_t bRow = (uint32_t)(wn * 64 + (lj >> 1) * 8 + lr);
  const uint32_t bCol = (uint32_t)((lj & 1) * 16);

  // prologue: issue chunks 0..NST-2
#pragma unroll
  for (int pc = 0; pc < NST - 1; pc++) {
    if (pc < nch) {
      int k0 = kb + pc * 32;
      uint32_t st = base + (uint32_t)(pc * STB);
      issue4(A, sA, M, m0, k0, st, tid);
      if (SPLIT) issue4(A, sA, M, m0, Kh + k0, st + TILEB, tid);
      issue4(Bm, sB, N, n0, k0, st + (SPLIT ? 2 : 1) * TILEB, tid);
      if (SPLIT) issue4(Bm, sB, N, n0, Kh + k0, st + 3 * TILEB, tid);
    }
    cpa_commit();
  }

  for (int ch = 0; ch < nch; ++ch) {
    cpa_wait<NST - 2>();
    __syncthreads();

    // issue chunk ch+NST-1 into the stage freed by chunk ch-1
    int nc = ch + NST - 1;
    if (nc < nch) {
      int k0 = kb + nc * 32;
      uint32_t st = base + (uint32_t)((nc % NST) * STB);
      issue4(A, sA, M, m0, k0, st, tid);
      if (SPLIT) issue4(A, sA, M, m0, Kh + k0, st + TILEB, tid);
      issue4(Bm, sB, N, n0, k0, st + (SPLIT ? 2 : 1) * TILEB, tid);
      if (SPLIT) issue4(Bm, sB, N, n0, Kh + k0, st + 3 * TILEB, tid);
    }
    cpa_commit();

    uint32_t stg = base + (uint32_t)((ch % NST) * STB);
    const int npass = SPLIT ? 3 : 1;
#pragma unroll 1
    for (int ps = 0; ps < npass; ps++) {
      uint32_t aT = stg + ((ps == 1) ? TILEB : 0);
      uint32_t bT = stg + (SPLIT ? 2 : 1) * TILEB + ((ps == 2) ? TILEB : 0);
#pragma unroll
      for (int ks = 0; ks < 2; ks++) {
        uint32_t afr[4][4];
#pragma unroll
        for (int mi = 0; mi < 4; mi++)
          ldm4(afr[mi], aT + (aRow + mi * 16) * ROWB + ks * 32 + aCol);
        uint32_t bfr[8][2];
#pragma unroll
        for (int nb = 0; nb < 4; nb++) {
          uint32_t t[4];
          ldm4(t, bT + (bRow + nb * 16) * ROWB + ks * 32 + bCol);
          bfr[2 * nb][0] = t[0];
          bfr[2 * nb][1] = t[1];
          bfr[2 * nb + 1][0] = t[2];
          bfr[2 * nb + 1][1] = t[3];
        }
#pragma unroll
        for (int mi = 0; mi < 4; mi++)
#pragma unroll
          for (int ni = 0; ni < 8; ni++) {
            if (FP16) mma_fp(acc[mi][ni], afr[mi], bfr[ni]);
            else      mma_bf(acc[mi][ni], afr[mi], bfr[ni]);
          }
      }
    }
    __syncthreads();
  }

  const int rr = lane >> 2, cc = (lane & 3) * 2;
#pragma unroll
  for (int mi = 0; mi < 4; mi++) {
#pragma unroll
    for (int ni = 0; ni < 8; ni++) {
      int rb = m0 + wm * 64 + mi * 16 + rr;
      int cb = n0 + wn * 64 + ni * 8 + cc;
      if (rb < M) {
        if (cb < N)     p.store(z, rb, cb,     acc[mi][ni][0]);
        if (cb + 1 < N) p.store(z, rb, cb + 1, acc[mi][ni][1]);
      }
      if (rb + 8 < M) {
        if (cb < N)     p.store(z, rb + 8, cb,     acc[mi][ni][2]);
        if (cb + 1 < N) p.store(z, rb + 8, cb + 1, acc[mi][ni][3]);
      }
    }
  }
}

// ----------------------------- GEMM problem defs ----------------------------

struct WeffQP {  // bf16 3-pass, z = n*4+t (32 blocks); outputs fp32 + fp16
  int M, N, nch, Kh, sA, sB;
  const uint16_t *wpT2, *Wt2;
  float* WQF;
  __half* WQ1;
  __device__ int kbase(int) const { return 0; }
  __device__ const uint16_t* Aptr(int z) const {
    return wpT2 + (size_t)(z & 3) * 512 * 1024;
  }
  __device__ const uint16_t* Bptr(int z) const {
    return Wt2 + (size_t)(z >> 2) * 512 * 1024;
  }
  __device__ void store(int z, int r, int c, float v) const {
    int n = z >> 2, t = z & 3;
    size_t idx = ((size_t)n * 512 + r) * 2048 + t * 512 + c;
    WQF[idx] = v;
    WQ1[idx] = __float2half(v);
  }
};

struct WeffKVP {  // fp16 1-pass, z = tv*32 + n*4 + t (64 blocks)
  int M, N, nch, Kh, sA, sB;
  const uint16_t *wpT1, *Wt1;
  __half *WK1, *WV1;
  __device__ int kbase(int) const { return 0; }
  __device__ const uint16_t* Aptr(int z) const {
    int tv = z >> 5, t = z & 3;
    return wpT1 + (size_t)(tv * 4 + t) * 512 * 512;
  }
  __device__ const uint16_t* Bptr(int z) const {
    int tv = z >> 5, n = (z & 31) >> 2;
    return Wt1 + (size_t)(tv * 8 + n) * 512 * 512;
  }
  __device__ void store(int z, int r, int c, float v) const {
    int tv = z >> 5, n = (z & 31) >> 2, t = z & 3;
    __half* dst = tv ? WV1 : WK1;
    dst[((size_t)n * 512 + r) * 2048 + t * 512 + c] = __float2half(v);
  }
};

struct QtwXP {  // bf16 3-pass: N=896 (F rows 0..383, WXe rows 384..895)
  int M, N, nch, Kh, sA, sB;
  const uint16_t *Xg2, *WFX2;
  float* qtw;
  float* PX;
  __device__ int kbase(int) const { return 0; }
  __device__ const uint16_t* Aptr(int) const { return Xg2; }
  __device__ const uint16_t* Bptr(int) const { return WFX2; }
  __device__ void store(int, int r, int c, float v) const {
    int b = r / NB_, o = r % NB_;
    if (c < 288) {
      int n = c / 36, j = c - n * 36;
      qtw[((size_t)(b * 8 + n) * LP_ + 1 + o) * 36 + j] = v;
    } else if (c >= 384) {
      PX[((size_t)b * LP_ + 1 + o) * 512 + (c - 384)] = v;
    }
  }
};

struct PoolQKVP {  // fp16 1-pass, merged N=12288 (WQ1|WK1|WV1 contiguous)
  int M, N, nch, Kh, sA, sB;
  const uint16_t *Xg1, *W1;
  const float* bias;  // bpool, [3][4096] matching q,k,v column order
  float* PQ;
  __half* PQ1;
  __half* PK1;
  __half* PVt1;
  __device__ int kbase(int) const { return 0; }
  __device__ const uint16_t* Aptr(int) const { return Xg1; }
  __device__ const uint16_t* Bptr(int) const { return W1; }
  __device__ void store(int, int r, int c, float v) const {
    int b = r / NB_, o = r % NB_;
    v += bias[c];
    int ti = c >> 12;
    int h = c & 4095;
    int n = h >> 9, d = h & 511;
    int zz = b * 8 + n;
    if (ti == 0) {
      size_t idx = ((size_t)zz * LP_ + 1 + o) * 512 + d;
      PQ[idx] = v;
      PQ1[idx] = __float2half(v);
    } else if (ti == 1) {
      PK1[((size_t)zz * LP_ + 1 + o) * 512 + d] = __float2half(v);
    } else {
      PVt1[((size_t)zz * 512 + d) * 1600 + 1 + o] = __float2half(v);
    }
  }
};

struct LogitsP {  // fp16 1-pass, raw PQ·PK^T (scale + qr applied in softmax)
  int M, N, nch, Kh, sA, sB;
  const uint16_t *PQ1, *PK1;
  float* lg;
  __device__ int kbase(int) const { return 0; }
  __device__ const uint16_t* Aptr(int z) const {
    return PQ1 + (size_t)z * LP_ * 512;
  }
  __device__ const uint16_t* Bptr(int z) const {
    return PK1 + (size_t)z * LP_ * 512;
  }
  __device__ void store(int z, int r, int c, float v) const {
    lg[(size_t)z * LP_ * LGLD_ + (size_t)r * LGLD_ + c] = v;
  }
};

struct AVP {  // fp16 1-pass
  int M, N, nch, Kh, sA, sB;
  const uint16_t *at1, *PVt1;
  const float* PQ;
  __nv_bfloat16* st2b;
  __device__ int kbase(int) const { return 0; }
  __device__ const uint16_t* Aptr(int z) const {
    return at1 + (size_t)z * LP_ * 1600;
  }
  __device__ const uint16_t* Bptr(int z) const {
    return PVt1 + (size_t)z * 512 * 1600;
  }
  __device__ void store(int z, int r, int c, float v) const {
    float pq = PQ[(size_t)z * LP_ * 512 + (size_t)r * 512 + c];
    v += (r > 0 ? 2.f : 1.f) * pq;
    int b = z >> 3, n = z & 7;
    st2(st2b, ((size_t)b * LP_ + r) * 8192 + n * 512 + c, 4096, v);
  }
};

struct FinalP {  // bf16 3-pass, split-K=2
  int M, N, nch, Kh, sA, sB;
  const uint16_t *st2b, *Wd2;
  float* yp;
  __device__ int kbase(int z) const { return z * 2048; }
  __device__ const uint16_t* Aptr(int) const { return st2b; }
  __device__ const uint16_t* Bptr(int) const { return Wd2; }
  __device__ void store(int z, int r, int c, float v) const {
    yp[(size_t)z * B_ * LP_ * 512 + (size_t)r * 512 + c] = v;
  }
};

// ------------------------------ helper kernels ------------------------------

__global__ void k_wpT(const float* wpq, const float* wpk, const float* wpv,
                      __nv_bfloat16* wpT2, __half* wpT1) {
  size_t idx = (size_t)blockIdx.x * blockDim.x + threadIdx.x;
  if (idx >= (size_t)3 * 512 * 512 * 4) return;
  int ti = (int)(idx / (512 * 512 * 4));
  int r = (int)(idx % (512 * 512 * 4));
  int c = r / 2048;
  int d = (r % 2048) >> 2;
  int t = r & 3;
  const float* wp = (ti == 0) ? wpq : ((ti == 1) ? wpk : wpv);
  float v = wp[r];
  if (ti == 0)
    st2(wpT2, ((size_t)t * 512 + c) * 1024 + d, 512, v);
  else
    wpT1[((size_t)((ti - 1) * 4 + t) * 512 + c) * 512 + d] = __float2half(v);
}

__global__ void k_wt(const float* Wq, const float* Wk, const float* Wv,
                     __nv_bfloat16* Wt2, __half* Wt1) {
  size_t idx = (size_t)blockIdx.x * blockDim.x + threadIdx.x;
  if (idx >= (size_t)3 * 8 * 512 * 512) return;
  int d = (int)(idx & 511);
  int m = (int)((idx >> 9) & 511);
  int n = (int)((idx >> 18) & 7);
  int ti = (int)(idx >> 21);
  const float* W = (ti == 0) ? Wq : ((ti == 1) ? Wk : Wv);
  float v = W[(size_t)(n * 512 + d) * 512 + m];
  if (ti == 0)
    st2(Wt2, ((size_t)n * 512 + m) * 1024 + d, 512, v);
  else
    Wt1[((size_t)((ti - 1) * 8 + n) * 512 + m) * 512 + d] = __float2half(v);
}

__global__ void k_wxe2(const float* wpx, __nv_bfloat16* WFX2) {
  size_t idx = (size_t)blockIdx.x * blockDim.x + threadIdx.x;
  if (idx >= (size_t)512 * 2048) return;
  int c = (int)(idx >> 11);
  int col = (int)(idx & 2047);
  int t = col >> 9, m = col & 511;
  float v = wpx[(size_t)c * 2048 + m * 4 + t];
  st2(WFX2, (size_t)(384 + c) * 4096 + col, 2048, v);
}

__global__ void k_F(const float* WQF, const float* emb, __nv_bfloat16* WFX2) {
  size_t idx = (size_t)blockIdx.x * blockDim.x + threadIdx.x;
  if (idx >= (size_t)384 * 2048) return;
  int k = (int)(idx & 2047);
  int nj = (int)(idx >> 11);
  float s = 0.f;
  if (nj < 288) {
    int n = nj / 36, j = nj - n * 36;
    int d0, dn, kk;
    if (j < 8)       { d0 = 0;   dn = 170; kk = j * 196; }
    else if (j < 22) { d0 = 170; dn = 170; kk = (j - 8) * 14; }
    else             { d0 = 340; dn = 172; kk = j - 22; }
    const float* e = emb + (size_t)kk * 512 + d0;
    const float* w = WQF + (size_t)(n * 512 + d0) * 2048 + k;
    for (int d = 0; d < dn; d++) s += w[(size_t)d * 2048] * e[d];
  }
  st2(WFX2, (size_t)nj * 4096 + k, 2048, s);
}

__global__ void k_wd2(const float* Wd, __nv_bfloat16* Wd2) {
  size_t idx = (size_t)blockIdx.x * blockDim.x + threadIdx.x;
  if (idx >= (size_t)512 * 4096) return;
  int c = (int)(idx >> 12), k = (int)(idx & 4095);
  st2(Wd2, (size_t)c * 8192 + k, 4096, Wd[idx]);
}

__global__ void k_bpool(const float* wpq, const float* wpk, const float* wpv,
                        const float* bq, const float* bk, const float* bv,
                        float* bpool) {
  int j = blockIdx.x * blockDim.x + threadIdx.x;
  if (j >= 3 * 4096) return;
  int ti = j / 4096, h = j % 4096, n = h >> 9, c = h & 511;
  const float* wp = (ti == 0) ? wpq : ((ti == 1) ? wpk : wpv);
  const float* b = (ti == 0) ? bq : ((ti == 1) ? bk : bv);
  float s = 0.f;
  for (int d = 0; d < 512; d++) {
    float bb = b[n * 512 + d];
    const float* w = wp + (size_t)c * 2048 + d * 4;
    s += (w[0] + w[1] + w[2] + w[3]) * bb;
  }
  bpool[j] = s;
}

__global__ void k_gather2(const float* x, __nv_bfloat16* Xg2, __half* Xg1) {
  size_t idx = (size_t)blockIdx.x * blockDim.x + threadIdx.x;
  if (idx >= (size_t)3136 * 2048) return;
  int r = (int)(idx >> 11);
  int col = (int)(idx & 2047);
  int t = col >> 9, m = col & 511;
  int b = r / NB_, o = r % NB_;
  int t2 = o / 196, hh = (o / 14) % 14, ww = o % 14;
  int kh = t >> 1, kw = t & 1;
  int row = 1 + (t2 * 28 + 2 * hh + kh) * 28 + 2 * ww + kw;
  float v = x[((size_t)b * L_ + row) * 512 + m];
  st2(Xg2, (size_t)r * 4096 + col, 2048, v);
  Xg1[(size_t)r * 2048 + col] = __float2half(v);
}

__global__ void k_padpv(__half* PVt1) {
  int idx = blockIdx.x * blockDim.x + threadIdx.x;
  if (idx >= 16 * 512 * 31) return;
  int j = idx % 31;
  int rc = idx / 31;
  PVt1[(size_t)rc * 1600 + LP_ + j] = __float2half(0.f);
}

__global__ void k_cls(const float* x, const float* Wq, const float* bq,
                      const float* Wk, const float* bk, const float* Wv,
                      const float* bv, float* PQ, float* PX, __half* PQ1,
                      __half* PK1, __half* PVt1) {
  int idx = blockIdx.x * blockDim.x + threadIdx.x;
  if (idx < 2 * 12288) {
    int b = idx / 12288, j = idx % 12288, ti = j / 4096, jj = j & 4095;
    const float* W = (ti == 0) ? Wq : ((ti == 1) ? Wk : Wv);
    const float* bias = (ti == 0) ? bq : ((ti == 1) ? bk : bv);
    const float* xr = x + (size_t)b * L_ * 512;
    const float* wr = W + (size_t)jj * 512;
    float s = bias[jj];
    for (int m = 0; m < 512; m++) s += xr[m] * wr[m];
    int n = jj >> 9, c = jj & 511;
    int zz = b * 8 + n;
    if (ti == 0) {
      PQ[(size_t)zz * LP_ * 512 + c] = s;
      PQ1[(size_t)zz * LP_ * 512 + c] = __float2half(s);
    } else if (ti == 1) {
      PK1[(size_t)zz * LP_ * 512 + c] = __float2half(s);
    } else {
      PVt1[((size_t)zz * 512 + c) * 1600 + 0] = __float2half(s);
    }
  } else if (idx < 2 * 12288 + 2 * 512) {
    int k = idx - 2 * 12288;
    int b = k >> 9, c = k & 511;
    PX[(size_t)b * LP_ * 512 + c] = x[(size_t)b * L_ * 512 + c];
  }
}

__device__ __forceinline__ float sincos_val(int pos, int c, int dim) {
  int half = dim / 2;
  bool is_cos = c >= half;
  int i = is_cos ? c - half : c;
  float omega = powf(10000.f, -((float)i) / (float)half);
  float ang = (float)pos * omega;
  return is_cos ? cosf(ang) : sinf(ang);
}

__global__ void k_emb(float* emb) {
  size_t idx = (size_t)blockIdx.x * blockDim.x + threadIdx.x;
  if (idx >= SZ_EMB) return;
  int k = (int)(idx >> 9);
  int c = (int)(idx & 511);
  int t2 = k / 196, h2 = (k / 14) % 14, w2 = k % 14;
  float v;
  if (c < 170) v = sincos_val(t2, c, 170);
  else if (c < 340) v = sincos_val(h2, c - 170, 170);
  else v = sincos_val(w2, c - 340, 172);
  emb[idx] = v;
}

__global__ void k_softmax(const float* lg, const float* qtw, __half* at1) {
  int z = blockIdx.y, q = blockIdx.x;
  const float* row = lg + ((size_t)z * LP_ + q) * LGLD_;
  __half* arow = at1 + ((size_t)z * LP_ + q) * 1600;
  int tid = threadIdx.x;
  __shared__ float sr[LPP_];
  __shared__ float red[256];
  __shared__ float qv[36];
  if (tid < 36) qv[tid] = (q > 0) ? qtw[((size_t)z * LP_ + q) * 36 + tid] : 0.f;
  __syncthreads();
  float mx = -1e30f;
  for (int i = tid; i < LP_; i += 256) {
    float l = SCALE_ * row[i];
    if (q > 0 && i > 0) {
      int k = i - 1;
      int t2 = k / 196;
      int rm = k - t2 * 196;
      int h2 = rm / 14;
      int w2 = rm - h2 * 14;
      l += qv[t2] + qv[8 + h2] + qv[22 + w2];
    }
    sr[i] = l;
    mx = fmaxf(mx, l);
  }
  red[tid] = mx;
  __syncthreads();
  for (int s = 128; s > 0; s >>= 1) {
    if (tid < s) red[tid] = fmaxf(red[tid], red[tid + s]);
    __syncthreads();
  }
  mx = red[0];
  __syncthreads();
  float sum = 0.f;
  for (int i = tid; i < LP_; i += 256) {
    float e = expf(sr[i] - mx);
    sr[i] = e;
    sum += e;
  }
  red[tid] = sum;
  __syncthreads();
  for (int s = 128; s > 0; s >>= 1) {
    if (tid < s) red[tid] += red[tid + s];
    __syncthreads();
  }
  float inv = 1.f / red[0];
  for (int i = tid; i < LPP_; i += 256) {
    float v = (i < LP_) ? sr[i] * inv : 0.f;
    arow[i] = __float2half(v);
  }
}

__global__ void k_ln(const float* yp, const float* bd, const float* PX,
                     const float* gamma, const float* beta, float* y) {
  int row = blockIdx.x;
  const float* y0 = yp + (size_t)row * 512;
  const float* y1 = yp + (size_t)B_ * LP_ * 512 + (size_t)row * 512;
  const float* px = PX + (size_t)row * 512;
  float* yr = y + (size_t)row * 512;
  int tid = threadIdx.x;
  float v0 = y0[tid] + y1[tid] + bd[tid] + px[tid];
  float v1 = y0[tid + 256] + y1[tid + 256] + bd[tid + 256] + px[tid + 256];
  __shared__ float red[256];
  red[tid] = v0 + v1;
  __syncthreads();
  for (int s = 128; s > 0; s >>= 1) {
    if (tid < s) red[tid] += red[tid + s];
    __syncthreads();
  }
  float mu = red[0] * (1.f / 512.f);
  __syncthreads();
  float d0 = v0 - mu, d1 = v1 - mu;
  red[tid] = d0 * d0 + d1 * d1;
  __syncthreads();
  for (int s = 128; s > 0; s >>= 1) {
    if (tid < s) red[tid] += red[tid + s];
    __syncthreads();
  }
  float inv = rsqrtf(red[0] * (1.f / 512.f) + 1e-5f);
  yr[tid] = d0 * inv * gamma[tid] + beta[tid];
  yr[tid + 256] = d1 * inv * gamma[tid + 256] + beta[tid + 256];
}

// --------------------------------- launcher ---------------------------------

extern "C" void kernel_launch(void* const* d_in, const int* in_sizes, int n_in,
                              void* d_out, int out_size) {
  (void)in_sizes; (void)n_in; (void)out_size;
  const float* x   = (const float*)d_in[0];
  const float* Wq  = (const float*)d_in[1];
  const float* bq  = (const float*)d_in[2];
  const float* Wk  = (const float*)d_in[3];
  const float* bk  = (const float*)d_in[4];
  const float* Wv  = (const float*)d_in[5];
  const float* bv  = (const float*)d_in[6];
  const float* wpq = (const float*)d_in[7];
  const float* wpk = (const float*)d_in[8];
  const float* wpv = (const float*)d_in[9];
  const float* wpx = (const float*)d_in[10];
  const float* Wd  = (const float*)d_in[11];
  const float* bd  = (const float*)d_in[12];
  const float* gamma = (const float*)d_in[13];
  const float* beta  = (const float*)d_in[14];
  float* y = (float*)d_out;

  float* S = nullptr;
  cudaGetSymbolAddress((void**)&S, g_scratch);
  __nv_bfloat16* Bf = nullptr;
  cudaGetSymbolAddress((void**)&Bf, g_bf);
  __half* Hf = nullptr;
  cudaGetSymbolAddress((void**)&Hf, g_hf);

  float* PQ    = S + OF_PQ;
  float* PX    = S + OF_PX;
  float* emb   = S + OF_EMB;
  float* bpool = S + OF_BP;
  float* lg    = S + OF_LG;
  float* yp    = S + OF_YP;
  float* qtw   = S + OF_QTW;
  float* WQF   = S + OF_WQF;

  __nv_bfloat16* wpT2 = Bf + OB_WPT2;
  __nv_bfloat16* Wt2  = Bf + OB_WT2;
  __nv_bfloat16* Wd2  = Bf + OB_WD2;
  __nv_bfloat16* WFX2 = Bf + OB_WFX2;
  __nv_bfloat16* Xg2  = Bf + OB_XG2;
  __nv_bfloat16* st2b = Bf + OB_ST2;

  __half* wpT1 = Hf + OH_WPT1;
  __half* Wt1  = Hf + OH_WT1;
  __half* WQ1  = Hf + OH_WQ1;
  __half* WK1  = Hf + OH_WK1;
  __half* WV1  = Hf + OH_WV1;
  __half* Xg1  = Hf + OH_XG1;
  __half* PQ1  = Hf + OH_PQ1;
  __half* PK1  = Hf + OH_PK1;
  __half* PVt1 = Hf + OH_PVT1;
  __half* at1  = Hf + OH_AT1;

  cudaFuncSetAttribute(gemm_ca<WeffQP, true, false>,
                       cudaFuncAttributeMaxDynamicSharedMemorySize, SMEMB);
  cudaFuncSetAttribute(gemm_ca<WeffKVP, false, true>,
                       cudaFuncAttributeMaxDynamicSharedMemorySize, SMEMB);
  cudaFuncSetAttribute(gemm_ca<QtwXP, true, false>,
                       cudaFuncAttributeMaxDynamicSharedMemorySize, SMEMB);
  cudaFuncSetAttribute(gemm_ca<PoolQKVP, false, true>,
                       cudaFuncAttributeMaxDynamicSharedMemorySize, SMEMB);
  cudaFuncSetAttribute(gemm_ca<LogitsP, false, true>,
                       cudaFuncAttributeMaxDynamicSharedMemorySize, SMEMB);
  cudaFuncSetAttribute(gemm_ca<AVP, false, true>,
                       cudaFuncAttributeMaxDynamicSharedMemorySize, SMEMB);
  cudaFuncSetAttribute(gemm_ca<FinalP, true, false>,
                       cudaFuncAttributeMaxDynamicSharedMemorySize, SMEMB);

  // converters
  k_wpT<<<(int)((3u * 512 * 512 * 4 + 255) / 256), 256>>>(wpq, wpk, wpv, wpT2,
                                                          wpT1);
  k_wt<<<(int)((3u * 8 * 512 * 512 + 255) / 256), 256>>>(Wq, Wk, Wv, Wt2, Wt1);
  k_wxe2<<<(512 * 2048 + 255) / 256, 256>>>(wpx, WFX2);
  k_wd2<<<(512 * 4096 + 255) / 256, 256>>>(Wd, Wd2);
  k_bpool<<<(3 * 4096 + 255) / 256, 256>>>(wpq, wpk, wpv, bq, bk, bv, bpool);
  k_gather2<<<(int)((3136u * 2048 + 255) / 256), 256>>>(x, Xg2, Xg1);
  k_padpv<<<(16 * 512 * 31 + 255) / 256, 256>>>(PVt1);
  k_emb<<<(int)((SZ_EMB + 255) / 256), 256>>>(emb);

  {
    WeffQP p;
    p.M = 512; p.N = 512; p.nch = 16; p.Kh = 512; p.sA = 1024; p.sB = 1024;
    p.wpT2 = (const uint16_t*)wpT2; p.Wt2 = (const uint16_t*)Wt2;
    p.WQF = WQF; p.WQ1 = WQ1;
    gemm_ca<WeffQP, true, false><<<dim3(4, 4, 32), 128, SMEMB>>>(p);
  }
  {
    WeffKVP p;
    p.M = 512; p.N = 512; p.nch = 16; p.Kh = 0; p.sA = 512; p.sB = 512;
    p.wpT1 = (const uint16_t*)wpT1; p.Wt1 = (const uint16_t*)Wt1;
    p.WK1 = WK1; p.WV1 = WV1;
    gemm_ca<WeffKVP, false, true><<<dim3(4, 4, 64), 128, SMEMB>>>(p);
  }

  k_F<<<(int)((384u * 2048 + 255) / 256), 256>>>(WQF, emb, WFX2);

  {
    QtwXP p;
    p.M = 3136; p.N = 896; p.nch = 64; p.Kh = 2048; p.sA = 4096; p.sB = 4096;
    p.Xg2 = (const uint16_t*)Xg2; p.WFX2 = (const uint16_t*)WFX2;
    p.qtw = qtw; p.PX = PX;
    gemm_ca<QtwXP, true, false><<<dim3(7, 25, 1), 128, SMEMB>>>(p);
  }
  {
    PoolQKVP p;
    p.M = 3136; p.N = 12288; p.nch = 64; p.Kh = 0; p.sA = 2048; p.sB = 2048;
    p.Xg1 = (const uint16_t*)Xg1; p.W1 = (const uint16_t*)WQ1;
    p.bias = bpool; p.PQ = PQ; p.PQ1 = PQ1; p.PK1 = PK1; p.PVt1 = PVt1;
    gemm_ca<PoolQKVP, false, true><<<dim3(96, 25, 1), 128, SMEMB>>>(p);
  }

  k_cls<<<(2 * 12288 + 2 * 512 + 255) / 256, 256>>>(x, Wq, bq, Wk, bk, Wv, bv,
                                                    PQ, PX, PQ1, PK1, PVt1);

  {
    LogitsP p;
    p.M = LP_; p.N = LP_; p.nch = 16; p.Kh = 0; p.sA = 512; p.sB = 512;
    p.PQ1 = (const uint16_t*)PQ1; p.PK1 = (const uint16_t*)PK1; p.lg = lg;
    gemm_ca<LogitsP, false, true><<<dim3(13, 13, 16), 128, SMEMB>>>(p);
  }

  k_softmax<<<dim3(LP_, 16), 256>>>(lg, qtw, at1);

  {
    AVP p;
    p.M = LP_; p.N = 512; p.nch = 50; p.Kh = 0; p.sA = 1600; p.sB = 1600;
    p.at1 = (const uint16_t*)at1; p.PVt1 = (const uint16_t*)PVt1;
    p.PQ = PQ; p.st2b = st2b;
    gemm_ca<AVP, false, true><<<dim3(4, 13, 16), 128, SMEMB>>>(p);
  }

  {
    FinalP p;
    p.M = B_ * LP_; p.N = 512; p.nch = 64; p.Kh = 4096; p.sA = 8192;
    p.sB = 8192;
    p.st2b = (const uint16_t*)st2b; p.Wd2 = (const uint16_t*)Wd2; p.yp = yp;
    gemm_ca<FinalP, true, false><<<dim3(4, 25, 2), 128, SMEMB>>>(p);
  }

  k_ln<<<B_ * LP_, 256>>>(yp, bd, PX, gamma, beta, y);
}

// round 17
// speedup vs baseline: 1.8991x; 1.0385x over previous
#include <cuda_runtime.h>
#include <cuda_bf16.h>
#include <cuda_fp16.h>
#include <math.h>
#include <stdint.h>
#include <stddef.h>

// ---------------------------------------------------------------------------
// MultiHeadPooledAttention — mixed-precision HMMA GEMMs.
//   bf16 hi/lo 3-pass (2-stage pipe): Weff-Q, QtwX (split-K=2), Final (split-K=4)
//   fp16 single-pass (4-stage pipe): Weff-KV, PoolQKV (merged, M-fast grid),
//                                    Logits, attn·V
// qr factored to weights (exact chain), added in fused softmax.
// ---------------------------------------------------------------------------

namespace {
constexpr int B_  = 2;
constexpr int L_  = 6273;   // 1 + 8*28*28
constexpr int NH_ = 8;
constexpr int LP_ = 1569;   // 1 + 8*14*14
constexpr int LPP_ = 1600;
constexpr int NB_ = 1568;
constexpr int LGLD_ = 1600;
constexpr float SCALE_ = 0.04419417382415922f;  // 512^-0.5

// fp32 scratch
constexpr size_t PXH_  = (size_t)B_ * LP_ * 512;   // PX partial stride
constexpr size_t QTWH_ = (size_t)16 * LP_ * 36;    // qtw partial stride
constexpr size_t YPH_  = (size_t)B_ * LP_ * 512;   // yp partial stride

constexpr size_t SZ_PQ  = (size_t)16 * LP_ * 512;
constexpr size_t SZ_PX  = 2 * PXH_;
constexpr size_t SZ_EMB = (size_t)NB_ * 512;
constexpr size_t SZ_BP  = (size_t)3 * 4096;
constexpr size_t SZ_LG  = (size_t)16 * LP_ * LGLD_;
constexpr size_t SZ_YP  = 4 * YPH_;
constexpr size_t SZ_QTW = 2 * QTWH_;
constexpr size_t SZ_WQF = (size_t)4096 * 2048;

constexpr size_t OF_PQ  = 0;
constexpr size_t OF_PX  = OF_PQ + SZ_PQ;
constexpr size_t OF_EMB = OF_PX + SZ_PX;
constexpr size_t OF_BP  = OF_EMB + SZ_EMB;
constexpr size_t OF_LG  = OF_BP + SZ_BP;
constexpr size_t OF_YP  = OF_LG + SZ_LG;
constexpr size_t OF_QTW = OF_YP + SZ_YP;
constexpr size_t OF_WQF = OF_QTW + SZ_QTW;
constexpr size_t SZ_F32 = OF_WQF + SZ_WQF;

// bf16 hi/lo buffers (planar: hi at [0,Kh), lo at [Kh,2Kh), row stride 2Kh)
constexpr size_t SZB_WPT2 = (size_t)4 * 512 * 1024;
constexpr size_t SZB_WT2  = (size_t)8 * 512 * 1024;
constexpr size_t SZB_WD2  = (size_t)512 * 8192;
constexpr size_t SZB_WFX2 = (size_t)896 * 4096;   // F (384 rows) + WXe (512)
constexpr size_t SZB_XG2  = (size_t)3136 * 4096;
constexpr size_t SZB_ST2  = (size_t)B_ * LP_ * 8192;

constexpr size_t OB_WPT2 = 0;
constexpr size_t OB_WT2  = OB_WPT2 + SZB_WPT2;
constexpr size_t OB_WD2  = OB_WT2 + SZB_WT2;
constexpr size_t OB_WFX2 = OB_WD2 + SZB_WD2;
constexpr size_t OB_XG2  = OB_WFX2 + SZB_WFX2;
constexpr size_t OB_ST2  = OB_XG2 + SZB_XG2;
constexpr size_t SZ_BF   = OB_ST2 + SZB_ST2;

// fp16 single-plane buffers (WQ1/WK1/WV1 contiguous => merged PoolQKV B)
constexpr size_t SZH_WPT1 = (size_t)8 * 512 * 512;
constexpr size_t SZH_WT1  = (size_t)16 * 512 * 512;
constexpr size_t SZH_WQ1  = (size_t)4096 * 2048;
constexpr size_t SZH_WK1  = (size_t)4096 * 2048;
constexpr size_t SZH_WV1  = (size_t)4096 * 2048;
constexpr size_t SZH_XG1  = (size_t)3136 * 2048;
constexpr size_t SZH_PQ1  = (size_t)16 * LP_ * 512;
constexpr size_t SZH_PK1  = (size_t)16 * LP_ * 512;
constexpr size_t SZH_PVT1 = (size_t)16 * 512 * 1600;
constexpr size_t SZH_AT1  = (size_t)16 * LP_ * 1600;

constexpr size_t OH_WPT1 = 0;
constexpr size_t OH_WT1  = OH_WPT1 + SZH_WPT1;
constexpr size_t OH_WQ1  = OH_WT1 + SZH_WT1;
constexpr size_t OH_WK1  = OH_WQ1 + SZH_WQ1;
constexpr size_t OH_WV1  = OH_WK1 + SZH_WK1;
constexpr size_t OH_XG1  = OH_WV1 + SZH_WV1;
constexpr size_t OH_PQ1  = OH_XG1 + SZH_XG1;
constexpr size_t OH_PK1  = OH_PQ1 + SZH_PQ1;
constexpr size_t OH_PVT1 = OH_PK1 + SZH_PK1;
constexpr size_t OH_AT1  = OH_PVT1 + SZH_PVT1;
constexpr size_t SZ_HF   = OH_AT1 + SZH_AT1;
}  // namespace

__device__ float g_scratch[SZ_F32];
__device__ __align__(16) __nv_bfloat16 g_bf[SZ_BF];
__device__ __align__(16) __half g_hf[SZ_HF];

// ------------------------------- PTX helpers -------------------------------

__device__ __forceinline__ uint32_t smem_u32(const void* p) {
  uint32_t a;
  asm("{ .reg .u64 t; cvta.to.shared.u64 t, %1; cvt.u32.u64 %0, t; }"
      : "=r"(a) : "l"(p));
  return a;
}

__device__ __forceinline__ void ldm4(uint32_t* d, uint32_t addr) {
  asm volatile("ldmatrix.sync.aligned.m8n8.x4.shared.b16 {%0,%1,%2,%3}, [%4];"
               : "=r"(d[0]), "=r"(d[1]), "=r"(d[2]), "=r"(d[3]) : "r"(addr));
}

__device__ __forceinline__ void mma_bf(float* c, const uint32_t* a,
                                       const uint32_t* b) {
  asm volatile(
      "mma.sync.aligned.m16n8k16.row.col.f32.bf16.bf16.f32 "
      "{%0,%1,%2,%3}, {%4,%5,%6,%7}, {%8,%9}, {%0,%1,%2,%3};"
      : "+f"(c[0]), "+f"(c[1]), "+f"(c[2]), "+f"(c[3])
      : "r"(a[0]), "r"(a[1]), "r"(a[2]), "r"(a[3]), "r"(b[0]), "r"(b[1]));
}
__device__ __forceinline__ void mma_fp(float* c, const uint32_t* a,
                                       const uint32_t* b) {
  asm volatile(
      "mma.sync.aligned.m16n8k16.row.col.f32.f16.f16.f32 "
      "{%0,%1,%2,%3}, {%4,%5,%6,%7}, {%8,%9}, {%0,%1,%2,%3};"
      : "+f"(c[0]), "+f"(c[1]), "+f"(c[2]), "+f"(c[3])
      : "r"(a[0]), "r"(a[1]), "r"(a[2]), "r"(a[3]), "r"(b[0]), "r"(b[1]));
}

__device__ __forceinline__ void cpa16(uint32_t dst, const void* src, bool ok) {
  int sz = ok ? 16 : 0;
  asm volatile("cp.async.cg.shared.global [%0], [%1], 16, %2;"
               :: "r"(dst), "l"(src), "r"(sz) : "memory");
}
__device__ __forceinline__ void cpa_commit() {
  asm volatile("cp.async.commit_group;" ::: "memory");
}
template <int N>
__device__ __forceinline__ void cpa_wait() {
  asm volatile("cp.async.wait_group %0;" :: "n"(N) : "memory");
}

__device__ __forceinline__ void st2(__nv_bfloat16* p, size_t i, size_t kh,
                                    float v) {
  __nv_bfloat16 h = __float2bfloat16(v);
  p[i] = h;
  p[i + kh] = __float2bfloat16(v - __bfloat162float(h));
}

// --------------------------- cp.async GEMM kernel ----------------------------
// FP16: 4-stage pipeline, 2 planes/stage. SPLIT(bf16-3): 2-stage, 4 planes.

constexpr int ROWB = 80;
constexpr int TILEB = 128 * ROWB;
constexpr int SMEMB = 8 * TILEB;  // 81920 both configs

__device__ __forceinline__ void issue4(const uint16_t* S, int stride, int rmax,
                                       int r0, int kofs, uint32_t dstB,
                                       int tid) {
#pragma unroll
  for (int i = 0; i < 4; i++) {
    int idx = tid + 128 * i;
    int row = idx >> 2, q = idx & 3;
    int gr = r0 + row;
    bool ok = gr < rmax;
    const uint16_t* src = S + (size_t)(ok ? gr : 0) * stride + kofs + q * 8;
    cpa16(dstB + (uint32_t)(row * ROWB + q * 16), src, ok);
  }
}

template <typename P, bool SPLIT, bool FP16, bool SWAP = false>
__global__ __launch_bounds__(128) void gemm_ca(P p) {
  extern __shared__ __align__(16) char sm[];
  uint32_t base = smem_u32(sm);

  constexpr int NST = FP16 ? 4 : 2;
  constexpr int STB = FP16 ? 2 * TILEB : 4 * TILEB;

  const int tid = threadIdx.x;
  const int wid = tid >> 5, lane = tid & 31;
  const int wm = wid >> 1, wn = wid & 1;
  const int lj = lane >> 3, lr = lane & 7;

  const int z = blockIdx.z;
  const uint16_t* A = p.Aptr(z);
  const uint16_t* Bm = p.Bptr(z);
  const int M = p.M, N = p.N;
  const int bxx = SWAP ? blockIdx.y : blockIdx.x;  // N tile
  const int byy = SWAP ? blockIdx.x : blockIdx.y;  // M tile
  const int m0 = byy * 128, n0 = bxx * 128;
  const int nch = p.nch, Kh = p.Kh, sA = p.sA, sB = p.sB;
  const int kb = p.kbase(z);

  float acc[4][8][4];
#pragma unroll
  for (int a = 0; a < 4; a++)
#pragma unroll
    for (int b = 0; b < 8; b++)
#pragma unroll
      for (int c = 0; c < 4; c++) acc[a][b][c] = 0.f;

  const uint32_t aRow = (uint32_t)(wm * 64 + (lj & 1) * 8 + lr);
  const uint32_t aCol = (uint32_t)((lj >> 1) * 16);
  const uint32_t bRow = (uint32_t)(wn * 64 + (lj >> 1) * 8 + lr);
  const uint32_t bCol = (uint32_t)((lj & 1) * 16);

  // prologue: issue chunks 0..NST-2
#pragma unroll
  for (int pc = 0; pc < NST - 1; pc++) {
    if (pc < nch) {
      int k0 = kb + pc * 32;
      uint32_t st = base + (uint32_t)(pc * STB);
      issue4(A, sA, M, m0, k0, st, tid);
      if (SPLIT) issue4(A, sA, M, m0, Kh + k0, st + TILEB, tid);
      issue4(Bm, sB, N, n0, k0, st + (SPLIT ? 2 : 1) * TILEB, tid);
      if (SPLIT) issue4(Bm, sB, N, n0, Kh + k0, st + 3 * TILEB, tid);
    }
    cpa_commit();
  }

  for (int ch = 0; ch < nch; ++ch) {
    cpa_wait<NST - 2>();
    __syncthreads();

    int nc = ch + NST - 1;
    if (nc < nch) {
      int k0 = kb + nc * 32;
      uint32_t st = base + (uint32_t)((nc % NST) * STB);
      issue4(A, sA, M, m0, k0, st, tid);
      if (SPLIT) issue4(A, sA, M, m0, Kh + k0, st + TILEB, tid);
      issue4(Bm, sB, N, n0, k0, st + (SPLIT ? 2 : 1) * TILEB, tid);
      if (SPLIT) issue4(Bm, sB, N, n0, Kh + k0, st + 3 * TILEB, tid);
    }
    cpa_commit();

    uint32_t stg = base + (uint32_t)((ch % NST) * STB);
    const int npass = SPLIT ? 3 : 1;
#pragma unroll 1
    for (int ps = 0; ps < npass; ps++) {
      uint32_t aT = stg + ((ps == 1) ? TILEB : 0);
      uint32_t bT = stg + (SPLIT ? 2 : 1) * TILEB + ((ps == 2) ? TILEB : 0);
#pragma unroll
      for (int ks = 0; ks < 2; ks++) {
        uint32_t afr[4][4];
#pragma unroll
        for (int mi = 0; mi < 4; mi++)
          ldm4(afr[mi], aT + (aRow + mi * 16) * ROWB + ks * 32 + aCol);
        uint32_t bfr[8][2];
#pragma unroll
        for (int nb = 0; nb < 4; nb++) {
          uint32_t t[4];
          ldm4(t, bT + (bRow + nb * 16) * ROWB + ks * 32 + bCol);
          bfr[2 * nb][0] = t[0];
          bfr[2 * nb][1] = t[1];
          bfr[2 * nb + 1][0] = t[2];
          bfr[2 * nb + 1][1] = t[3];
        }
#pragma unroll
        for (int mi = 0; mi < 4; mi++)
#pragma unroll
          for (int ni = 0; ni < 8; ni++) {
            if (FP16) mma_fp(acc[mi][ni], afr[mi], bfr[ni]);
            else      mma_bf(acc[mi][ni], afr[mi], bfr[ni]);
          }
      }
    }
    __syncthreads();
  }

  const int rr = lane >> 2, cc = (lane & 3) * 2;
#pragma unroll
  for (int mi = 0; mi < 4; mi++) {
#pragma unroll
    for (int ni = 0; ni < 8; ni++) {
      int rb = m0 + wm * 64 + mi * 16 + rr;
      int cb = n0 + wn * 64 + ni * 8 + cc;
      if (rb < M) {
        if (cb < N)     p.store(z, rb, cb,     acc[mi][ni][0]);
        if (cb + 1 < N) p.store(z, rb, cb + 1, acc[mi][ni][1]);
      }
      if (rb + 8 < M) {
        if (cb < N)     p.store(z, rb + 8, cb,     acc[mi][ni][2]);
        if (cb + 1 < N) p.store(z, rb + 8, cb + 1, acc[mi][ni][3]);
      }
    }
  }
}

// ----------------------------- GEMM problem defs ----------------------------

struct WeffQP {  // bf16 3-pass, z = n*4+t (32 blocks); outputs fp32 + fp16
  int M, N, nch, Kh, sA, sB;
  const uint16_t *wpT2, *Wt2;
  float* WQF;
  __half* WQ1;
  __device__ int kbase(int) const { return 0; }
  __device__ const uint16_t* Aptr(int z) const {
    return wpT2 + (size_t)(z & 3) * 512 * 1024;
  }
  __device__ const uint16_t* Bptr(int z) const {
    return Wt2 + (size_t)(z >> 2) * 512 * 1024;
  }
  __device__ void store(int z, int r, int c, float v) const {
    int n = z >> 2, t = z & 3;
    size_t idx = ((size_t)n * 512 + r) * 2048 + t * 512 + c;
    WQF[idx] = v;
    WQ1[idx] = __float2half(v);
  }
};

struct WeffKVP {  // fp16 1-pass, z = tv*32 + n*4 + t (64 blocks)
  int M, N, nch, Kh, sA, sB;
  const uint16_t *wpT1, *Wt1;
  __half *WK1, *WV1;
  __device__ int kbase(int) const { return 0; }
  __device__ const uint16_t* Aptr(int z) const {
    int tv = z >> 5, t = z & 3;
    return wpT1 + (size_t)(tv * 4 + t) * 512 * 512;
  }
  __device__ const uint16_t* Bptr(int z) const {
    int tv = z >> 5, n = (z & 31) >> 2;
    return Wt1 + (size_t)(tv * 8 + n) * 512 * 512;
  }
  __device__ void store(int z, int r, int c, float v) const {
    int tv = z >> 5, n = (z & 31) >> 2, t = z & 3;
    __half* dst = tv ? WV1 : WK1;
    dst[((size_t)n * 512 + r) * 2048 + t * 512 + c] = __float2half(v);
  }
};

struct QtwXP {  // bf16 3-pass, split-K=2: N=896 (F rows 0..383, WXe 384..895)
  int M, N, nch, Kh, sA, sB;
  const uint16_t *Xg2, *WFX2;
  float* qtw;   // 2 partials of QTWH_
  float* PX;    // 2 partials of PXH_
  __device__ int kbase(int z) const { return z * 1024; }
  __device__ const uint16_t* Aptr(int) const { return Xg2; }
  __device__ const uint16_t* Bptr(int) const { return WFX2; }
  __device__ void store(int z, int r, int c, float v) const {
    int b = r / NB_, o = r % NB_;
    if (c < 288) {
      int n = c / 36, j = c - n * 36;
      qtw[(size_t)z * QTWH_ + ((size_t)(b * 8 + n) * LP_ + 1 + o) * 36 + j] = v;
    } else if (c >= 384) {
      PX[(size_t)z * PXH_ + ((size_t)b * LP_ + 1 + o) * 512 + (c - 384)] = v;
    }
  }
};

struct PoolQKVP {  // fp16 1-pass, merged N=12288 (WQ1|WK1|WV1 contiguous)
  int M, N, nch, Kh, sA, sB;
  const uint16_t *Xg1, *W1;
  const float* bias;  // bpool, [3][4096] matching q,k,v column order
  float* PQ;
  __half* PQ1;
  __half* PK1;
  __half* PVt1;
  __device__ int kbase(int) const { return 0; }
  __device__ const uint16_t* Aptr(int) const { return Xg1; }
  __device__ const uint16_t* Bptr(int) const { return W1; }
  __device__ void store(int, int r, int c, float v) const {
    int b = r / NB_, o = r % NB_;
    v += bias[c];
    int ti = c >> 12;
    int h = c & 4095;
    int n = h >> 9, d = h & 511;
    int zz = b * 8 + n;
    if (ti == 0) {
      size_t idx = ((size_t)zz * LP_ + 1 + o) * 512 + d;
      PQ[idx] = v;
      PQ1[idx] = __float2half(v);
    } else if (ti == 1) {
      PK1[((size_t)zz * LP_ + 1 + o) * 512 + d] = __float2half(v);
    } else {
      PVt1[((size_t)zz * 512 + d) * 1600 + 1 + o] = __float2half(v);
    }
  }
};

struct LogitsP {  // fp16 1-pass, raw PQ·PK^T (scale + qr applied in softmax)
  int M, N, nch, Kh, sA, sB;
  const uint16_t *PQ1, *PK1;
  float* lg;
  __device__ int kbase(int) const { return 0; }
  __device__ const uint16_t* Aptr(int z) const {
    return PQ1 + (size_t)z * LP_ * 512;
  }
  __device__ const uint16_t* Bptr(int z) const {
    return PK1 + (size_t)z * LP_ * 512;
  }
  __device__ void store(int z, int r, int c, float v) const {
    lg[(size_t)z * LP_ * LGLD_ + (size_t)r * LGLD_ + c] = v;
  }
};

struct AVP {  // fp16 1-pass
  int M, N, nch, Kh, sA, sB;
  const uint16_t *at1, *PVt1;
  const float* PQ;
  __nv_bfloat16* st2b;
  __device__ int kbase(int) const { return 0; }
  __device__ const uint16_t* Aptr(int z) const {
    return at1 + (size_t)z * LP_ * 1600;
  }
  __device__ const uint16_t* Bptr(int z) const {
    return PVt1 + (size_t)z * 512 * 1600;
  }
  __device__ void store(int z, int r, int c, float v) const {
    float pq = PQ[(size_t)z * LP_ * 512 + (size_t)r * 512 + c];
    v += (r > 0 ? 2.f : 1.f) * pq;
    int b = z >> 3, n = z & 7;
    st2(st2b, ((size_t)b * LP_ + r) * 8192 + n * 512 + c, 4096, v);
  }
};

struct FinalP {  // bf16 3-pass, split-K=4
  int M, N, nch, Kh, sA, sB;
  const uint16_t *st2b, *Wd2;
  float* yp;
  __device__ int kbase(int z) const { return z * 1024; }
  __device__ const uint16_t* Aptr(int) const { return st2b; }
  __device__ const uint16_t* Bptr(int) const { return Wd2; }
  __device__ void store(int z, int r, int c, float v) const {
    yp[(size_t)z * YPH_ + (size_t)r * 512 + c] = v;
  }
};

// ------------------------------ helper kernels ------------------------------

__global__ void k_wpT(const float* wpq, const float* wpk, const float* wpv,
                      __nv_bfloat16* wpT2, __half* wpT1) {
  size_t idx = (size_t)blockIdx.x * blockDim.x + threadIdx.x;
  if (idx >= (size_t)3 * 512 * 512 * 4) return;
  int ti = (int)(idx / (512 * 512 * 4));
  int r = (int)(idx % (512 * 512 * 4));
  int c = r / 2048;
  int d = (r % 2048) >> 2;
  int t = r & 3;
  const float* wp = (ti == 0) ? wpq : ((ti == 1) ? wpk : wpv);
  float v = wp[r];
  if (ti == 0)
    st2(wpT2, ((size_t)t * 512 + c) * 1024 + d, 512, v);
  else
    wpT1[((size_t)((ti - 1) * 4 + t) * 512 + c) * 512 + d] = __float2half(v);
}

// Tiled transpose: coalesced reads of W and coalesced writes of Wt.
__global__ void k_wtT(const float* Wq, const float* Wk, const float* Wv,
                      __nv_bfloat16* Wt2, __half* Wt1) {
  __shared__ float s[32][33];
  int h = blockIdx.z;             // ti*8+n
  int ti = h >> 3, n = h & 7;
  const float* W = (ti == 0) ? Wq : ((ti == 1) ? Wk : Wv);
  int m0 = blockIdx.x * 32, d0 = blockIdx.y * 32;
  int tx = threadIdx.x, ty = threadIdx.y;
#pragma unroll
  for (int k = 0; k < 4; k++) {
    int d = d0 + ty + k * 8;
    s[ty + k * 8][tx] = W[((size_t)(n * 512 + d)) * 512 + m0 + tx];
  }
  __syncthreads();
#pragma unroll
  for (int k = 0; k < 4; k++) {
    int m = m0 + ty + k * 8;
    int d = d0 + tx;
    float v = s[tx][ty + k * 8];
    if (ti == 0)
      st2(Wt2, ((size_t)(n * 512 + m)) * 1024 + d, 512, v);
    else
      Wt1[(((size_t)((ti - 1) * 8 + n) * 512 + m)) * 512 + d] = __float2half(v);
  }
}

__global__ void k_wxe2(const float* wpx, __nv_bfloat16* WFX2) {
  size_t idx = (size_t)blockIdx.x * blockDim.x + threadIdx.x;
  if (idx >= (size_t)512 * 2048) return;
  int c = (int)(idx >> 11);
  int col = (int)(idx & 2047);
  int t = col >> 9, m = col & 511;
  float v = wpx[(size_t)c * 2048 + m * 4 + t];
  st2(WFX2, (size_t)(384 + c) * 4096 + col, 2048, v);
}

__global__ void k_F(const float* WQF, const float* emb, __nv_bfloat16* WFX2) {
  size_t idx = (size_t)blockIdx.x * blockDim.x + threadIdx.x;
  if (idx >= (size_t)384 * 2048) return;
  int k = (int)(idx & 2047);
  int nj = (int)(idx >> 11);
  float s = 0.f;
  if (nj < 288) {
    int n = nj / 36, j = nj - n * 36;
    int d0, dn, kk;
    if (j < 8)       { d0 = 0;   dn = 170; kk = j * 196; }
    else if (j < 22) { d0 = 170; dn = 170; kk = (j - 8) * 14; }
    else             { d0 = 340; dn = 172; kk = j - 22; }
    const float* e = emb + (size_t)kk * 512 + d0;
    const float* w = WQF + (size_t)(n * 512 + d0) * 2048 + k;
    for (int d = 0; d < dn; d++) s += w[(size_t)d * 2048] * e[d];
  }
  st2(WFX2, (size_t)nj * 4096 + k, 2048, s);
}

__global__ void k_wd2(const float* Wd, __nv_bfloat16* Wd2) {
  size_t idx = (size_t)blockIdx.x * blockDim.x + threadIdx.x;
  if (idx >= (size_t)512 * 4096) return;
  int c = (int)(idx >> 12), k = (int)(idx & 4095);
  st2(Wd2, (size_t)c * 8192 + k, 4096, Wd[idx]);
}

__global__ void k_bpool(const float* wpq, const float* wpk, const float* wpv,
                        const float* bq, const float* bk, const float* bv,
                        float* bpool) {
  int j = blockIdx.x * blockDim.x + threadIdx.x;
  if (j >= 3 * 4096) return;
  int ti = j / 4096, h = j % 4096, n = h >> 9, c = h & 511;
  const float* wp = (ti == 0) ? wpq : ((ti == 1) ? wpk : wpv);
  const float* b = (ti == 0) ? bq : ((ti == 1) ? bk : bv);
  float s = 0.f;
  for (int d = 0; d < 512; d++) {
    float bb = b[n * 512 + d];
    const float* w = wp + (size_t)c * 2048 + d * 4;
    s += (w[0] + w[1] + w[2] + w[3]) * bb;
  }
  bpool[j] = s;
}

__global__ void k_gather2(const float* x, __nv_bfloat16* Xg2, __half* Xg1) {
  size_t idx = (size_t)blockIdx.x * blockDim.x + threadIdx.x;
  if (idx >= (size_t)3136 * 2048) return;
  int r = (int)(idx >> 11);
  int col = (int)(idx & 2047);
  int t = col >> 9, m = col & 511;
  int b = r / NB_, o = r % NB_;
  int t2 = o / 196, hh = (o / 14) % 14, ww = o % 14;
  int kh = t >> 1, kw = t & 1;
  int row = 1 + (t2 * 28 + 2 * hh + kh) * 28 + 2 * ww + kw;
  float v = x[((size_t)b * L_ + row) * 512 + m];
  st2(Xg2, (size_t)r * 4096 + col, 2048, v);
  Xg1[(size_t)r * 2048 + col] = __float2half(v);
}

__global__ void k_padpv(__half* PVt1) {
  int idx = blockIdx.x * blockDim.x + threadIdx.x;
  if (idx >= 16 * 512 * 31) return;
  int j = idx % 31;
  int rc = idx / 31;
  PVt1[(size_t)rc * 1600 + LP_ + j] = __float2half(0.f);
}

__global__ void k_cls(const float* x, const float* Wq, const float* bq,
                      const float* Wk, const float* bk, const float* Wv,
                      const float* bv, float* PQ, float* PX, __half* PQ1,
                      __half* PK1, __half* PVt1) {
  int idx = blockIdx.x * blockDim.x + threadIdx.x;
  if (idx < 2 * 12288) {
    int b = idx / 12288, j = idx % 12288, ti = j / 4096, jj = j & 4095;
    const float* W = (ti == 0) ? Wq : ((ti == 1) ? Wk : Wv);
    const float* bias = (ti == 0) ? bq : ((ti == 1) ? bk : bv);
    const float* xr = x + (size_t)b * L_ * 512;
    const float* wr = W + (size_t)jj * 512;
    float s = bias[jj];
    for (int m = 0; m < 512; m++) s += xr[m] * wr[m];
    int n = jj >> 9, c = jj & 511;
    int zz = b * 8 + n;
    if (ti == 0) {
      PQ[(size_t)zz * LP_ * 512 + c] = s;
      PQ1[(size_t)zz * LP_ * 512 + c] = __float2half(s);
    } else if (ti == 1) {
      PK1[(size_t)zz * LP_ * 512 + c] = __float2half(s);
    } else {
      PVt1[((size_t)zz * 512 + c) * 1600 + 0] = __float2half(s);
    }
  } else if (idx < 2 * 12288 + 2 * 512) {
    int k = idx - 2 * 12288;
    int b = k >> 9, c = k & 511;
    PX[(size_t)b * LP_ * 512 + c] = x[(size_t)b * L_ * 512 + c];
    PX[PXH_ + (size_t)b * LP_ * 512 + c] = 0.f;  // zero second partial, row 0
  }
}

__device__ __forceinline__ float sincos_val(int pos, int c, int dim) {
  int half = dim / 2;
  bool is_cos = c >= half;
  int i = is_cos ? c - half : c;
  float omega = powf(10000.f, -((float)i) / (float)half);
  float ang = (float)pos * omega;
  return is_cos ? cosf(ang) : sinf(ang);
}

__global__ void k_emb(float* emb) {
  size_t idx = (size_t)blockIdx.x * blockDim.x + threadIdx.x;
  if (idx >= SZ_EMB) return;
  int k = (int)(idx >> 9);
  int c = (int)(idx & 511);
  int t2 = k / 196, h2 = (k / 14) % 14, w2 = k % 14;
  float v;
  if (c < 170) v = sincos_val(t2, c, 170);
  else if (c < 340) v = sincos_val(h2, c - 170, 170);
  else v = sincos_val(w2, c - 340, 172);
  emb[idx] = v;
}

__global__ void k_softmax(const float* lg, const float* qtw, __half* at1) {
  int z = blockIdx.y, q = blockIdx.x;
  const float* row = lg + ((size_t)z * LP_ + q) * LGLD_;
  __half* arow = at1 + ((size_t)z * LP_ + q) * 1600;
  int tid = threadIdx.x;
  __shared__ float sr[LPP_];
  __shared__ float red[256];
  __shared__ float qv[36];
  if (tid < 36) {
    size_t qi = ((size_t)z * LP_ + q) * 36 + tid;
    qv[tid] = (q > 0) ? (qtw[qi] + qtw[QTWH_ + qi]) : 0.f;
  }
  __syncthreads();
  float mx = -1e30f;
  for (int i = tid; i < LP_; i += 256) {
    float l = SCALE_ * row[i];
    if (q > 0 && i > 0) {
      int k = i - 1;
      int t2 = k / 196;
      int rm = k - t2 * 196;
      int h2 = rm / 14;
      int w2 = rm - h2 * 14;
      l += qv[t2] + qv[8 + h2] + qv[22 + w2];
    }
    sr[i] = l;
    mx = fmaxf(mx, l);
  }
  red[tid] = mx;
  __syncthreads();
  for (int s = 128; s > 0; s >>= 1) {
    if (tid < s) red[tid] = fmaxf(red[tid], red[tid + s]);
    __syncthreads();
  }
  mx = red[0];
  __syncthreads();
  float sum = 0.f;
  for (int i = tid; i < LP_; i += 256) {
    float e = expf(sr[i] - mx);
    sr[i] = e;
    sum += e;
  }
  red[tid] = sum;
  __syncthreads();
  for (int s = 128; s > 0; s >>= 1) {
    if (tid < s) red[tid] += red[tid + s];
    __syncthreads();
  }
  float inv = 1.f / red[0];
  for (int i = tid; i < LPP_; i += 256) {
    float v = (i < LP_) ? sr[i] * inv : 0.f;
    arow[i] = __float2half(v);
  }
}

__global__ void k_ln(const float* yp, const float* bd, const float* PX,
                     const float* gamma, const float* beta, float* y) {
  int row = blockIdx.x;
  size_t r0 = (size_t)row * 512;
  const float* px0 = PX + r0;
  const float* px1 = PX + PXH_ + r0;
  float* yr = y + r0;
  int tid = threadIdx.x;
  float v0 = bd[tid] + px0[tid] + px1[tid];
  float v1 = bd[tid + 256] + px0[tid + 256] + px1[tid + 256];
#pragma unroll
  for (int zz = 0; zz < 4; zz++) {
    const float* ypz = yp + (size_t)zz * YPH_ + r0;
    v0 += ypz[tid];
    v1 += ypz[tid + 256];
  }
  __shared__ float red[256];
  red[tid] = v0 + v1;
  __syncthreads();
  for (int s = 128; s > 0; s >>= 1) {
    if (tid < s) red[tid] += red[tid + s];
    __syncthreads();
  }
  float mu = red[0] * (1.f / 512.f);
  __syncthreads();
  float d0 = v0 - mu, d1 = v1 - mu;
  red[tid] = d0 * d0 + d1 * d1;
  __syncthreads();
  for (int s = 128; s > 0; s >>= 1) {
    if (tid < s) red[tid] += red[tid + s];
    __syncthreads();
  }
  float inv = rsqrtf(red[0] * (1.f / 512.f) + 1e-5f);
  yr[tid] = d0 * inv * gamma[tid] + beta[tid];
  yr[tid + 256] = d1 * inv * gamma[tid + 256] + beta[tid + 256];
}

// --------------------------------- launcher ---------------------------------

extern "C" void kernel_launch(void* const* d_in, const int* in_sizes, int n_in,
                              void* d_out, int out_size) {
  (void)in_sizes; (void)n_in; (void)out_size;
  const float* x   = (const float*)d_in[0];
  const float* Wq  = (const float*)d_in[1];
  const float* bq  = (const float*)d_in[2];
  const float* Wk  = (const float*)d_in[3];
  const float* bk  = (const float*)d_in[4];
  const float* Wv  = (const float*)d_in[5];
  const float* bv  = (const float*)d_in[6];
  const float* wpq = (const float*)d_in[7];
  const float* wpk = (const float*)d_in[8];
  const float* wpv = (const float*)d_in[9];
  const float* wpx = (const float*)d_in[10];
  const float* Wd  = (const float*)d_in[11];
  const float* bd  = (const float*)d_in[12];
  const float* gamma = (const float*)d_in[13];
  const float* beta  = (const float*)d_in[14];
  float* y = (float*)d_out;

  float* S = nullptr;
  cudaGetSymbolAddress((void**)&S, g_scratch);
  __nv_bfloat16* Bf = nullptr;
  cudaGetSymbolAddress((void**)&Bf, g_bf);
  __half* Hf = nullptr;
  cudaGetSymbolAddress((void**)&Hf, g_hf);

  float* PQ    = S + OF_PQ;
  float* PX    = S + OF_PX;
  float* emb   = S + OF_EMB;
  float* bpool = S + OF_BP;
  float* lg    = S + OF_LG;
  float* yp    = S + OF_YP;
  float* qtw   = S + OF_QTW;
  float* WQF   = S + OF_WQF;

  __nv_bfloat16* wpT2 = Bf + OB_WPT2;
  __nv_bfloat16* Wt2  = Bf + OB_WT2;
  __nv_bfloat16* Wd2  = Bf + OB_WD2;
  __nv_bfloat16* WFX2 = Bf + OB_WFX2;
  __nv_bfloat16* Xg2  = Bf + OB_XG2;
  __nv_bfloat16* st2b = Bf + OB_ST2;

  __half* wpT1 = Hf + OH_WPT1;
  __half* Wt1  = Hf + OH_WT1;
  __half* WQ1  = Hf + OH_WQ1;
  __half* Xg1  = Hf + OH_XG1;
  __half* PQ1  = Hf + OH_PQ1;
  __half* PK1  = Hf + OH_PK1;
  __half* PVt1 = Hf + OH_PVT1;
  __half* at1  = Hf + OH_AT1;
  __half* WK1  = Hf + OH_WK1;
  __half* WV1  = Hf + OH_WV1;

  cudaFuncSetAttribute(gemm_ca<WeffQP, true, false>,
                       cudaFuncAttributeMaxDynamicSharedMemorySize, SMEMB);
  cudaFuncSetAttribute(gemm_ca<WeffKVP, false, true>,
                       cudaFuncAttributeMaxDynamicSharedMemorySize, SMEMB);
  cudaFuncSetAttribute(gemm_ca<QtwXP, true, false>,
                       cudaFuncAttributeMaxDynamicSharedMemorySize, SMEMB);
  cudaFuncSetAttribute(gemm_ca<PoolQKVP, false, true, true>,
                       cudaFuncAttributeMaxDynamicSharedMemorySize, SMEMB);
  cudaFuncSetAttribute(gemm_ca<LogitsP, false, true>,
                       cudaFuncAttributeMaxDynamicSharedMemorySize, SMEMB);
  cudaFuncSetAttribute(gemm_ca<AVP, false, true>,
                       cudaFuncAttributeMaxDynamicSharedMemorySize, SMEMB);
  cudaFuncSetAttribute(gemm_ca<FinalP, true, false>,
                       cudaFuncAttributeMaxDynamicSharedMemorySize, SMEMB);

  // converters
  k_wpT<<<(int)((3u * 512 * 512 * 4 + 255) / 256), 256>>>(wpq, wpk, wpv, wpT2,
                                                          wpT1);
  k_wtT<<<dim3(16, 16, 24), dim3(32, 8)>>>(Wq, Wk, Wv, Wt2, Wt1);
  k_wxe2<<<(512 * 2048 + 255) / 256, 256>>>(wpx, WFX2);
  k_wd2<<<(512 * 4096 + 255) / 256, 256>>>(Wd, Wd2);
  k_bpool<<<(3 * 4096 + 255) / 256, 256>>>(wpq, wpk, wpv, bq, bk, bv, bpool);
  k_gather2<<<(int)((3136u * 2048 + 255) / 256), 256>>>(x, Xg2, Xg1);
  k_padpv<<<(16 * 512 * 31 + 255) / 256, 256>>>(PVt1);
  k_emb<<<(int)((SZ_EMB + 255) / 256), 256>>>(emb);

  {
    WeffQP p;
    p.M = 512; p.N = 512; p.nch = 16; p.Kh = 512; p.sA = 1024; p.sB = 1024;
    p.wpT2 = (const uint16_t*)wpT2; p.Wt2 = (const uint16_t*)Wt2;
    p.WQF = WQF; p.WQ1 = WQ1;
    gemm_ca<WeffQP, true, false><<<dim3(4, 4, 32), 128, SMEMB>>>(p);
  }
  {
    WeffKVP p;
    p.M = 512; p.N = 512; p.nch = 16; p.Kh = 0; p.sA = 512; p.sB = 512;
    p.wpT1 = (const uint16_t*)wpT1; p.Wt1 = (const uint16_t*)Wt1;
    p.WK1 = WK1; p.WV1 = WV1;
    gemm_ca<WeffKVP, false, true><<<dim3(4, 4, 64), 128, SMEMB>>>(p);
  }

  k_F<<<(int)((384u * 2048 + 255) / 256), 256>>>(WQF, emb, WFX2);

  {
    QtwXP p;
    p.M = 3136; p.N = 896; p.nch = 32; p.Kh = 2048; p.sA = 4096; p.sB = 4096;
    p.Xg2 = (const uint16_t*)Xg2; p.WFX2 = (const uint16_t*)WFX2;
    p.qtw = qtw; p.PX = PX;
    gemm_ca<QtwXP, true, false><<<dim3(7, 25, 2), 128, SMEMB>>>(p);
  }
  {
    PoolQKVP p;
    p.M = 3136; p.N = 12288; p.nch = 64; p.Kh = 0; p.sA = 2048; p.sB = 2048;
    p.Xg1 = (const uint16_t*)Xg1; p.W1 = (const uint16_t*)WQ1;
    p.bias = bpool; p.PQ = PQ; p.PQ1 = PQ1; p.PK1 = PK1; p.PVt1 = PVt1;
    gemm_ca<PoolQKVP, false, true, true><<<dim3(25, 96, 1), 128, SMEMB>>>(p);
  }

  k_cls<<<(2 * 12288 + 2 * 512 + 255) / 256, 256>>>(x, Wq, bq, Wk, bk, Wv, bv,
                                                    PQ, PX, PQ1, PK1, PVt1);

  {
    LogitsP p;
    p.M = LP_; p.N = LP_; p.nch = 16; p.Kh = 0; p.sA = 512; p.sB = 512;
    p.PQ1 = (const uint16_t*)PQ1; p.PK1 = (const uint16_t*)PK1; p.lg = lg;
    gemm_ca<LogitsP, false, true><<<dim3(13, 13, 16), 128, SMEMB>>>(p);
  }

  k_softmax<<<dim3(LP_, 16), 256>>>(lg, qtw, at1);

  {
    AVP p;
    p.M = LP_; p.N = 512; p.nch = 50; p.Kh = 0; p.sA = 1600; p.sB = 1600;
    p.at1 = (const uint16_t*)at1; p.PVt1 = (const uint16_t*)PVt1;
    p.PQ = PQ; p.st2b = st2b;
    gemm_ca<AVP, false, true><<<dim3(4, 13, 16), 128, SMEMB>>>(p);
  }

  {
    FinalP p;
    p.M = B_ * LP_; p.N = 512; p.nch = 32; p.Kh = 4096; p.sA = 8192;
    p.sB = 8192;
    p.st2b = (const uint16_t*)st2b; p.Wd2 = (const uint16_t*)Wd2; p.yp = yp;
    gemm_ca<FinalP, true, false><<<dim3(4, 25, 4), 128, SMEMB>>>(p);
  }

  k_ln<<<B_ * LP_, 256>>>(yp, bd, PX, gamma, beta, y);
}